// round 6
// baseline (speedup 1.0000x reference)
#include <cuda_runtime.h>
#include <cstdlib>
#include <cfloat>

#define BB 8
#define NN 2048
#define KNB 20
#define NEGS 0.2f
#define EPSB 1e-5f

__attribute__((constructor)) static void _eager_load(){ setenv("CUDA_MODULE_LOADING","EAGER",0); }

// ------------------------- scratch (device globals) -------------------------
__device__ float g_xT  [(size_t)BB*NN*256];
__device__ float g_xx  [BB*NN];
__device__ float g_dist[(size_t)BB*NN*NN];
__device__ int   g_idx [(size_t)BB*NN*KNB];
__device__ float g_s   [(size_t)BB*256*NN*KNB];
__device__ float g_kmax[(size_t)BB*256*NN];
__device__ float g_kmin[(size_t)BB*256*NN];
__device__ float g_ksum[(size_t)BB*256*NN];
__device__ float g_ksq [(size_t)BB*256*NN];
__device__ float g_xcat[(size_t)BB*512*NN];
__device__ float g_h5  [(size_t)BB*1024*NN];
__device__ float g_hb1 [(size_t)BB*256*NN];
__device__ float g_hb2 [(size_t)BB*256*NN];
__device__ float g_hb3 [(size_t)BB*128*NN];
__device__ float g_glob[BB*1088];
__device__ float g_b207[BB*256];
__device__ float g_prm [2048];

// ------------------------- generic fp32 GEMM (pipelined, bit-identical math) --
// Single accumulator per output, FMA, k strictly ascending.
// BKIND 0: B row-major JxK            (Bs[kk][nn] = B[gn*ldb+gk])
// BKIND 1: B is KxJ (ldb = row str)   (Bs[kk][nn] = B[gk*ldb+gn])
// BKIND 2: edge features on the fly   (B[gn][gk] = gk<C ? xT[m]-xT[n] : xT[n])
// MODE 0: plain   MODE 1: dist epilogue (symmetric: skip bx<by, mirror store)
// MODE 2: row bias
template<int BKIND, int MODE>
__global__ void __launch_bounds__(256,2) k_gemm(
    int M, int Ncol, int Kd,
    const float* __restrict__ A, int lda, size_t asb,
    const float* __restrict__ Bp, int ldb, size_t bsb,
    float* __restrict__ Cp, size_t csb,
    const float* __restrict__ e0,
    const float* __restrict__ xTp, const int* __restrict__ idxp, int Cc)
{
    const int BM=128, BN=128, BK=16;
    if(MODE==1 && blockIdx.x < blockIdx.y) return;   // symmetric: upper triangle only
    __shared__ float As[2][BK][BM+4];
    __shared__ float Bs[2][BK][BN+4];
    int b  = blockIdx.z;
    int m0 = blockIdx.y*BM, n0 = blockIdx.x*BN;
    A  += (size_t)b*asb;
    Bp += (size_t)b*bsb;
    Cp += (size_t)b*csb;
    if(BKIND==2){ xTp += (size_t)b*NN*Cc; idxp += (size_t)b*NN*KNB; }
    int tid = threadIdx.x;
    int tx = tid%16, ty = tid/16;

    float acc[8][8];
    #pragma unroll
    for(int i=0;i<8;i++)
        #pragma unroll
        for(int j=0;j<8;j++) acc[i][j]=0.f;

    float ra[8], rb[8];

    auto fetchA = [&](int k0){
        #pragma unroll
        for(int i=0;i<8;i++){
            int e = tid + 256*i;
            int kk=e%BK, mm=e/BK;
            int gm=m0+mm, gk=k0+kk;
            ra[i] = (gm<M && gk<Kd) ? A[(size_t)gm*lda+gk] : 0.f;
        }
    };
    auto fetchB = [&](int k0){
        if(BKIND==0){
            #pragma unroll
            for(int i=0;i<8;i++){
                int e = tid + 256*i;
                int kk=e%BK, nn=e/BK;
                int gn=n0+nn, gk=k0+kk;
                rb[i] = (gn<Ncol && gk<Kd) ? Bp[(size_t)gn*ldb+gk] : 0.f;
            }
        } else if(BKIND==1){
            #pragma unroll
            for(int i=0;i<8;i++){
                int e = tid + 256*i;
                int nn=e%BN, kk=e/BN;
                int gn=n0+nn, gk=k0+kk;
                rb[i] = (gn<Ncol && gk<Kd) ? Bp[(size_t)gk*ldb+gn] : 0.f;
            }
        } else {
            #pragma unroll
            for(int i=0;i<8;i++){
                int e = tid + 256*i;
                int kk=e%BK, nn=e/BK;
                int gn=n0+nn, gk=k0+kk;
                float val = 0.f;
                if(gk<Kd){                       // Kd = 2C; gn < Ncol always (J mult of 128)
                    int n  = gn/KNB, kq = gn%KNB;
                    int cc = (gk<Cc)? gk : gk-Cc;
                    float ctr = xTp[(size_t)n*Cc + cc];
                    if(gk<Cc){
                        int m = idxp[(size_t)n*KNB + kq];
                        val = __fsub_rn(xTp[(size_t)m*Cc + cc], ctr);
                    } else val = ctr;
                }
                rb[i] = val;
            }
        }
    };
    auto store = [&](int buf){
        #pragma unroll
        for(int i=0;i<8;i++){
            int e = tid + 256*i;
            As[buf][e%BK][e/BK] = ra[i];
        }
        if(BKIND==1){
            #pragma unroll
            for(int i=0;i<8;i++){
                int e = tid + 256*i;
                Bs[buf][e/BN][e%BN] = rb[i];
            }
        } else {
            #pragma unroll
            for(int i=0;i<8;i++){
                int e = tid + 256*i;
                Bs[buf][e%BK][e/BK] = rb[i];
            }
        }
    };

    int nk = (Kd + BK - 1)/BK;
    fetchA(0); fetchB(0);
    store(0);
    __syncthreads();

    for(int t=0;t<nk;t++){
        int cur = t&1;
        if(t+1<nk){ fetchA((t+1)*BK); fetchB((t+1)*BK); }
        #pragma unroll
        for(int kk=0;kk<BK;kk++){   // ascending k, FMA, single accumulator
            float a8[8], b8[8];
            #pragma unroll
            for(int i=0;i<8;i++) a8[i]=As[cur][kk][ty*8+i];
            #pragma unroll
            for(int j=0;j<8;j++) b8[j]=Bs[cur][kk][tx*8+j];
            #pragma unroll
            for(int i=0;i<8;i++)
                #pragma unroll
                for(int j=0;j<8;j++) acc[i][j] = __fmaf_rn(a8[i], b8[j], acc[i][j]);
        }
        if(t+1<nk){
            __syncthreads();
            store(1-cur);
            __syncthreads();
        }
    }

    #pragma unroll
    for(int i=0;i<8;i++){
        int gm = m0+ty*8+i;
        if(gm>=M) continue;
        #pragma unroll
        for(int j=0;j<8;j++){
            int gn = n0+tx*8+j;
            if(gn>=Ncol) continue;
            float v = acc[i][j];
            if(MODE==1){
                v = __fsub_rn(__fsub_rn(__fmul_rn(2.0f, v), e0[(size_t)b*NN+gm]), e0[(size_t)b*NN+gn]);
                Cp[(size_t)gm*Ncol + gn] = v;
                Cp[(size_t)gn*Ncol + gm] = v;   // mirror (bit-identical by symmetry of the FMA chain)
            } else {
                if(MODE==2) v = __fadd_rn(v, e0[(size_t)b*M+gm]);
                Cp[(size_t)gm*Ncol + gn] = v;
            }
        }
    }
}

// ------------------------- small kernels -------------------------

__global__ void k_tin(const float* __restrict__ x){
    int i = blockIdx.x*blockDim.x + threadIdx.x;
    if(i >= BB*NN*3) return;
    int c = i%3; int n = (i/3)%NN; int b = i/(3*NN);
    g_xT[i] = x[((size_t)b*3 + c)*NN + n];
}

// per-point squared norm: ascending c, mul then add (ref lowering order)
__global__ void k_xx(int C){
    int p = blockIdx.x*blockDim.x + threadIdx.x;
    if(p >= BB*NN) return;
    const float* v = g_xT + (size_t)p*C;
    float s = 0.f;
    for(int c=0;c<C;c++) s = __fadd_rn(s, __fmul_rn(v[c], v[c]));
    g_xx[p] = s;
}

// Two-phase top-K (largest, min-index tiebreak).
// Phase 1: each of 8 warps -> local top-20 of its 256 contiguous elements (shfl only).
// Phase 2: warp 0 merges the 160 candidates -> global top-20 (identical set+ties).
__global__ void __launch_bounds__(256) k_topk(){
    int n = blockIdx.x, b = blockIdx.y;
    const float* row = g_dist + ((size_t)b*NN + n)*NN;
    int tid = threadIdx.x, lane = tid&31, w = tid>>5;
    int base = w*256 + lane*8;
    float v[8];
    {
        const float4* r4 = (const float4*)(row + base);
        float4 q0 = r4[0], q1 = r4[1];
        v[0]=q0.x; v[1]=q0.y; v[2]=q0.z; v[3]=q0.w;
        v[4]=q1.x; v[5]=q1.y; v[6]=q1.z; v[7]=q1.w;
    }
    __shared__ float sv[160];
    __shared__ int   si[160];

    #pragma unroll 1
    for(int j=0;j<KNB;j++){
        float bv = v[0]; int bs = 0;
        #pragma unroll
        for(int t=1;t<8;t++) if(v[t]>bv){ bv=v[t]; bs=t; }
        int gi = base + bs;
        #pragma unroll
        for(int o=16;o;o>>=1){
            float v2 = __shfl_xor_sync(0xffffffffu, bv, o);
            int   i2 = __shfl_xor_sync(0xffffffffu, gi, o);
            if(v2>bv || (v2==bv && i2<gi)){ bv=v2; gi=i2; }
        }
        if(lane==0){ sv[w*KNB+j]=bv; si[w*KNB+j]=gi; }
        int loc = gi - w*256;
        if((loc>>3)==lane) v[loc&7] = -FLT_MAX;
    }
    __syncthreads();
    if(w==0){
        int* out = g_idx + ((size_t)b*NN+n)*KNB;
        #pragma unroll 1
        for(int j=0;j<KNB;j++){
            float bv=-FLT_MAX; int bi=0x7fffffff; int bslot=0;
            #pragma unroll
            for(int q=0;q<5;q++){
                int s = lane + 32*q;
                float vv = sv[s]; int ii = si[s];
                if(vv>bv || (vv==bv && ii<bi)){ bv=vv; bi=ii; bslot=s; }
            }
            #pragma unroll
            for(int o=16;o;o>>=1){
                float v2 = __shfl_xor_sync(0xffffffffu, bv, o);
                int   i2 = __shfl_xor_sync(0xffffffffu, bi, o);
                int   s2 = __shfl_xor_sync(0xffffffffu, bslot, o);
                if(v2>bv || (v2==bv && i2<bi)){ bv=v2; bi=i2; bslot=s2; }
            }
            if(lane==0) out[j] = bi;
            if((bslot&31)==lane) sv[bslot] = -FLT_MAX;
        }
    }
}

// reduce k -> max/min/sum/sumsq; vectorized loads, same ascending-k op order
__global__ void k_kreduce(const float* __restrict__ s, int O){
    size_t p = (size_t)blockIdx.x*blockDim.x + threadIdx.x;
    size_t total = (size_t)BB*O*NN;
    if(p>=total) return;
    const float4* sp = (const float4*)(s + p*KNB);
    float h[KNB];
    #pragma unroll
    for(int q=0;q<5;q++){
        float4 f = sp[q];
        h[q*4+0]=f.x; h[q*4+1]=f.y; h[q*4+2]=f.z; h[q*4+3]=f.w;
    }
    float mx=-FLT_MAX, mn=FLT_MAX, sm=0.f, sq=0.f;
    #pragma unroll
    for(int k=0;k<KNB;k++){
        float hv = h[k];
        mx = fmaxf(mx,hv); mn = fminf(mn,hv);
        sm = __fadd_rn(sm,hv); sq = __fmaf_rn(hv,hv,sq);
    }
    g_kmax[p]=mx; g_kmin[p]=mn; g_ksum[p]=sm; g_ksq[p]=sq;
}

__global__ void k_ec_stats(int O){
    int o = blockIdx.x, tid = threadIdx.x;
    double s=0.0, ss=0.0;
    for(int b=0;b<BB;b++){
        size_t base = ((size_t)b*O + o)*NN;
        for(int n=tid;n<NN;n+=256){ s += g_ksum[base+n]; ss += g_ksq[base+n]; }
    }
    __shared__ double rs[256], rq[256];
    rs[tid]=s; rq[tid]=ss; __syncthreads();
    for(int st=128;st;st>>=1){ if(tid<st){ rs[tid]+=rs[tid+st]; rq[tid]+=rq[tid+st]; } __syncthreads(); }
    if(tid==0){
        double cnt = (double)BB*NN*KNB;
        double mean = rs[0]/cnt;
        double var  = rq[0]/cnt - mean*mean;
        g_prm[2*o]   = (float)mean;
        g_prm[2*o+1] = (float)var;
    }
}

__global__ void k_ec_apply(int O, int c0, float* __restrict__ xTout,
                           const float* __restrict__ gw, const float* __restrict__ bw){
    int o = blockIdx.x, b = blockIdx.y;
    float m = g_prm[2*o], vv = g_prm[2*o+1];
    float gg = gw[o], bb = bw[o];
    float sd = __fsqrt_rn(__fadd_rn(vv, EPSB));
    const float* src = (gg>=0.f ? g_kmax : g_kmin) + ((size_t)b*O + o)*NN;
    float* xc = g_xcat + ((size_t)b*512 + c0 + o)*NN;
    for(int n=threadIdx.x;n<NN;n+=blockDim.x){
        float y = __fadd_rn(__fmul_rn(__fdiv_rn(__fsub_rn(src[n], m), sd), gg), bb);
        y = (y>=0.f) ? y : __fmul_rn(NEGS, y);
        xc[n] = y;
        xTout[((size_t)b*NN + n)*O + o] = y;
    }
}

__global__ void k_conv_stats(const float* __restrict__ h, int O){
    int o = blockIdx.x, tid = threadIdx.x;
    double s=0.0, ss=0.0;
    for(int b=0;b<BB;b++){
        size_t base = ((size_t)b*O + o)*NN;
        for(int n=tid;n<NN;n+=256){ float v=h[base+n]; s += v; ss += (double)v*v; }
    }
    __shared__ double rs[256], rq[256];
    rs[tid]=s; rq[tid]=ss; __syncthreads();
    for(int st=128;st;st>>=1){ if(tid<st){ rs[tid]+=rs[tid+st]; rq[tid]+=rq[tid+st]; } __syncthreads(); }
    if(tid==0){
        double cnt = (double)BB*NN;
        double mean = rs[0]/cnt;
        double var  = rq[0]/cnt - mean*mean;
        g_prm[2*o]   = (float)mean;
        g_prm[2*o+1] = (float)var;
    }
}

__global__ void k_conv_apply(float* __restrict__ h, int O,
                             const float* __restrict__ gw, const float* __restrict__ bw){
    int o = blockIdx.x, b = blockIdx.y;
    float m = g_prm[2*o], vv = g_prm[2*o+1];
    float gg = gw[o], bb = bw[o];
    float sd = __fsqrt_rn(__fadd_rn(vv, EPSB));
    float* p = h + ((size_t)b*O + o)*NN;
    for(int n=threadIdx.x;n<NN;n+=blockDim.x){
        float y = __fadd_rn(__fmul_rn(__fdiv_rn(__fsub_rn(p[n], m), sd), gg), bb);
        p[n] = (y>=0.f) ? y : __fmul_rn(NEGS, y);
    }
}

__global__ void k_gmax(const float* __restrict__ gw, const float* __restrict__ bw){
    int o = blockIdx.x, b = blockIdx.y, tid = threadIdx.x;
    float gg = gw[o];
    const float* p = g_h5 + ((size_t)b*1024 + o)*NN;
    float m = -FLT_MAX, mn = FLT_MAX;
    for(int n=tid;n<NN;n+=256){
        float v = p[n];
        m = fmaxf(m, v); mn = fminf(mn, v);
    }
    __shared__ float r[256], r2[256];
    r[tid]=m; r2[tid]=mn; __syncthreads();
    for(int st=128;st;st>>=1){
        if(tid<st){ r[tid]=fmaxf(r[tid], r[tid+st]); r2[tid]=fminf(r2[tid], r2[tid+st]); }
        __syncthreads();
    }
    if(tid==0){
        float src = (gg>=0.f) ? r[0] : r2[0];
        float mm = g_prm[2*o], vv = g_prm[2*o+1];
        float sd = __fsqrt_rn(__fadd_rn(vv, EPSB));
        float y = __fadd_rn(__fmul_rn(__fdiv_rn(__fsub_rn(src, mm), sd), gg), bw[o]);
        y = (y>=0.f) ? y : __fmul_rn(NEGS, y);
        g_glob[b*1088 + o] = y;
    }
}

__global__ void k_lf(const float* __restrict__ l, const float* __restrict__ W,
                     const float* __restrict__ gw, const float* __restrict__ bw){
    int tid = threadIdx.x;
    int o = tid & 63, b = tid >> 6;
    __shared__ float hs[8][64];
    __shared__ float pm[64], pv[64];
    float s = 0.f;
    #pragma unroll
    for(int c=0;c<16;c++) s = __fmaf_rn(W[o*16 + c], l[b*16 + c], s);
    hs[b][o] = s;
    __syncthreads();
    if(tid < 64){
        float m = 0.f;
        #pragma unroll
        for(int q=0;q<8;q++) m = __fadd_rn(m, hs[q][tid]);
        m = __fdiv_rn(m, 8.f);
        float v = 0.f;
        #pragma unroll
        for(int q=0;q<8;q++){ float d = __fsub_rn(hs[q][tid], m); v = __fmaf_rn(d, d, v); }
        v = __fdiv_rn(v, 8.f);
        pm[tid] = m; pv[tid] = v;
    }
    __syncthreads();
    float sd = __fsqrt_rn(__fadd_rn(pv[o], EPSB));
    float y = __fadd_rn(__fmul_rn(__fdiv_rn(__fsub_rn(hs[b][o], pm[o]), sd), gw[o]), bw[o]);
    y = (y>=0.f) ? y : __fmul_rn(NEGS, y);
    g_glob[b*1088 + 1024 + o] = y;
}

__global__ void k_bias207(const float* __restrict__ W207){
    int b = blockIdx.x;
    __shared__ float gl[1088];
    for(int i=threadIdx.x;i<1088;i+=256) gl[i] = g_glob[b*1088 + i];
    __syncthreads();
    int o = threadIdx.x;
    float s = 0.f;
    for(int c=0;c<1088;c++) s = __fmaf_rn(W207[(size_t)o*1600 + c], gl[c], s);
    g_b207[b*256 + o] = s;
}

// ------------------------- launcher -------------------------
extern "C" void kernel_launch(void* const* d_in, const int* in_sizes, int n_in,
                              void* d_out, int out_size){
    (void)in_sizes; (void)n_in; (void)out_size;
    const float* x    = (const float*)d_in[0];
    const float* l    = (const float*)d_in[1];
    const float* Wec[4] = {(const float*)d_in[2],(const float*)d_in[5],(const float*)d_in[8],(const float*)d_in[11]};
    const float* gec[4] = {(const float*)d_in[3],(const float*)d_in[6],(const float*)d_in[9],(const float*)d_in[12]};
    const float* bec[4] = {(const float*)d_in[4],(const float*)d_in[7],(const float*)d_in[10],(const float*)d_in[13]};
    const float* W5   = (const float*)d_in[14]; const float* g5v  = (const float*)d_in[15]; const float* b5v  = (const float*)d_in[16];
    const float* W206 = (const float*)d_in[17]; const float* g206 = (const float*)d_in[18]; const float* b206 = (const float*)d_in[19];
    const float* W207 = (const float*)d_in[20]; const float* g207 = (const float*)d_in[21]; const float* b207 = (const float*)d_in[22];
    const float* W208 = (const float*)d_in[23]; const float* g208 = (const float*)d_in[24]; const float* b208 = (const float*)d_in[25];
    const float* W209 = (const float*)d_in[26]; const float* g209 = (const float*)d_in[27]; const float* b209 = (const float*)d_in[28];
    const float* W2010= (const float*)d_in[29];

    float *xT,*xxp,*dist,*sbuf,*xcat,*h5,*hb1,*hb2,*hb3,*b207p;
    int *idxp;
    cudaGetSymbolAddress((void**)&xT,   g_xT);
    cudaGetSymbolAddress((void**)&xxp,  g_xx);
    cudaGetSymbolAddress((void**)&dist, g_dist);
    cudaGetSymbolAddress((void**)&idxp, g_idx);
    cudaGetSymbolAddress((void**)&sbuf, g_s);
    cudaGetSymbolAddress((void**)&xcat, g_xcat);
    cudaGetSymbolAddress((void**)&h5,   g_h5);
    cudaGetSymbolAddress((void**)&hb1,  g_hb1);
    cudaGetSymbolAddress((void**)&hb2,  g_hb2);
    cudaGetSymbolAddress((void**)&hb3,  g_hb3);
    cudaGetSymbolAddress((void**)&b207p,g_b207);

    const int Cin[4] = {3,64,64,128};
    const int Oo [4] = {64,64,128,256};
    const int c0 [4] = {0,64,128,256};

    k_tin<<<(BB*NN*3 + 255)/256, 256>>>(x);

    for(int li=0; li<4; li++){
        int C = Cin[li], O = Oo[li];
        k_xx<<<(BB*NN + 255)/256, 256>>>(C);
        // symmetric dist GEMM (upper blocks compute + mirror)
        k_gemm<0,1><<<dim3(NN/128, NN/128, BB), 256>>>(
            NN, NN, C, xT, C, (size_t)NN*C, xT, C, (size_t)NN*C, dist, (size_t)NN*NN,
            xxp, nullptr, nullptr, 0);
        k_topk<<<dim3(NN, BB), 256>>>();
        // fused gather + edge GEMM: h = W @ [nbr-ctr, ctr]
        int C2 = 2*C, J = NN*KNB;
        k_gemm<2,0><<<dim3(J/128, (O+127)/128, BB), 256>>>(
            O, J, C2, Wec[li], C2, 0, nullptr, 0, 0, sbuf, (size_t)O*J,
            nullptr, xT, idxp, C);
        size_t tp = (size_t)BB*O*NN;
        k_kreduce<<<(unsigned)((tp + 255)/256), 256>>>(sbuf, O);
        k_ec_stats<<<O, 256>>>(O);
        k_ec_apply<<<dim3(O, BB), 256>>>(O, c0[li], xT, gec[li], bec[li]);
    }

    k_gemm<1,0><<<dim3(NN/128, 1024/128, BB), 256>>>(
        1024, NN, 512, W5, 512, 0, xcat, NN, (size_t)512*NN, h5, (size_t)1024*NN,
        nullptr, nullptr, nullptr, 0);
    k_conv_stats<<<1024, 256>>>(h5, 1024);
    k_gmax<<<dim3(1024, BB), 256>>>(g5v, b5v);
    k_lf<<<1, 512>>>(l, W206, g206, b206);
    k_bias207<<<BB, 256>>>(W207);
    k_gemm<1,2><<<dim3(NN/128, 2, BB), 256>>>(
        256, NN, 512, W207 + 1088, 1600, 0, xcat, NN, (size_t)512*NN, hb1, (size_t)256*NN,
        b207p, nullptr, nullptr, 0);
    k_conv_stats<<<256, 256>>>(hb1, 256);
    k_conv_apply<<<dim3(256, BB), 256>>>(hb1, 256, g207, b207);
    k_gemm<1,0><<<dim3(NN/128, 2, BB), 256>>>(
        256, NN, 256, W208, 256, 0, hb1, NN, (size_t)256*NN, hb2, (size_t)256*NN,
        nullptr, nullptr, nullptr, 0);
    k_conv_stats<<<256, 256>>>(hb2, 256);
    k_conv_apply<<<dim3(256, BB), 256>>>(hb2, 256, g208, b208);
    k_gemm<1,0><<<dim3(NN/128, 1, BB), 256>>>(
        128, NN, 256, W209, 256, 0, hb2, NN, (size_t)256*NN, hb3, (size_t)128*NN,
        nullptr, nullptr, nullptr, 0);
    k_conv_stats<<<128, 256>>>(hb3, 128);
    k_conv_apply<<<dim3(128, BB), 256>>>(hb3, 128, g209, b209);
    k_gemm<1,0><<<dim3(NN/128, 1, BB), 256>>>(
        50, NN, 128, W2010, 128, 0, hb3, NN, (size_t)128*NN, (float*)d_out, (size_t)50*NN,
        nullptr, nullptr, nullptr, 0);
}

// round 7
// speedup vs baseline: 1.1644x; 1.1644x over previous
#include <cuda_runtime.h>
#include <cstdlib>
#include <cfloat>

#define BB 8
#define NN 2048
#define KNB 20
#define NEGS 0.2f
#define EPSB 1e-5f

__attribute__((constructor)) static void _eager_load(){ setenv("CUDA_MODULE_LOADING","EAGER",0); }

// ------------------------- scratch (device globals) -------------------------
__device__ float g_xT  [(size_t)BB*NN*256];
__device__ float g_xx  [BB*NN];
__device__ float g_dist[(size_t)BB*NN*NN];
__device__ int   g_idx [(size_t)BB*NN*KNB];
__device__ float g_G   [(size_t)BB*NN*KNB*256];
__device__ float g_s   [(size_t)BB*256*NN*KNB];
__device__ float g_kmax[(size_t)BB*256*NN];
__device__ float g_kmin[(size_t)BB*256*NN];
__device__ float g_ksum[(size_t)BB*256*NN];
__device__ float g_ksq [(size_t)BB*256*NN];
__device__ float g_xcat[(size_t)BB*512*NN];
__device__ float g_h5  [(size_t)BB*1024*NN];
__device__ float g_hb1 [(size_t)BB*256*NN];
__device__ float g_hb2 [(size_t)BB*256*NN];
__device__ float g_hb3 [(size_t)BB*128*NN];
__device__ float g_glob[BB*1088];
__device__ float g_b207[BB*256];
__device__ float g_prm [2048];

// ------------------------- generic fp32 GEMM (pipelined, bit-identical math) --
// Single accumulator per output, FMA, k strictly ascending.
// MODE 0: plain   MODE 1: dist epilogue   MODE 2: row bias
template<bool BT, int MODE>
__global__ void __launch_bounds__(256,2) k_gemm(
    int M, int Ncol, int Kd,
    const float* __restrict__ A, int lda, size_t asb,
    const float* __restrict__ Bp, int ldb, size_t bsb,
    float* __restrict__ Cp, size_t csb,
    const float* __restrict__ e0)
{
    const int BM=128, BN=128, BK=16;
    __shared__ float As[2][BK][BM+4];
    __shared__ float Bs[2][BK][BN+4];
    int b  = blockIdx.z;
    int m0 = blockIdx.y*BM, n0 = blockIdx.x*BN;
    A  += (size_t)b*asb;
    Bp += (size_t)b*bsb;
    Cp += (size_t)b*csb;
    int tid = threadIdx.x;
    int tx = tid%16, ty = tid/16;

    float acc[8][8];
    #pragma unroll
    for(int i=0;i<8;i++)
        #pragma unroll
        for(int j=0;j<8;j++) acc[i][j]=0.f;

    float ra[8], rb[8];

    auto fetchA = [&](int k0){
        #pragma unroll
        for(int i=0;i<8;i++){
            int e = tid + 256*i;
            int kk=e%BK, mm=e/BK;
            int gm=m0+mm, gk=k0+kk;
            ra[i] = (gm<M && gk<Kd) ? A[(size_t)gm*lda+gk] : 0.f;
        }
    };
    auto fetchB = [&](int k0){
        if(!BT){
            #pragma unroll
            for(int i=0;i<8;i++){
                int e = tid + 256*i;
                int kk=e%BK, nn=e/BK;
                int gn=n0+nn, gk=k0+kk;
                rb[i] = (gn<Ncol && gk<Kd) ? Bp[(size_t)gn*ldb+gk] : 0.f;
            }
        } else {
            #pragma unroll
            for(int i=0;i<8;i++){
                int e = tid + 256*i;
                int nn=e%BN, kk=e/BN;
                int gn=n0+nn, gk=k0+kk;
                rb[i] = (gn<Ncol && gk<Kd) ? Bp[(size_t)gk*ldb+gn] : 0.f;
            }
        }
    };
    auto store = [&](int buf){
        #pragma unroll
        for(int i=0;i<8;i++){
            int e = tid + 256*i;
            As[buf][e%BK][e/BK] = ra[i];
        }
        if(!BT){
            #pragma unroll
            for(int i=0;i<8;i++){
                int e = tid + 256*i;
                Bs[buf][e%BK][e/BK] = rb[i];
            }
        } else {
            #pragma unroll
            for(int i=0;i<8;i++){
                int e = tid + 256*i;
                Bs[buf][e/BN][e%BN] = rb[i];
            }
        }
    };

    int nk = (Kd + BK - 1)/BK;
    fetchA(0); fetchB(0);
    store(0);
    __syncthreads();

    for(int t=0;t<nk;t++){
        int cur = t&1;
        if(t+1<nk){ fetchA((t+1)*BK); fetchB((t+1)*BK); }
        #pragma unroll
        for(int kk=0;kk<BK;kk++){   // ascending k, FMA, single accumulator
            float a8[8], b8[8];
            #pragma unroll
            for(int i=0;i<8;i++) a8[i]=As[cur][kk][ty*8+i];
            #pragma unroll
            for(int j=0;j<8;j++) b8[j]=Bs[cur][kk][tx*8+j];
            #pragma unroll
            for(int i=0;i<8;i++)
                #pragma unroll
                for(int j=0;j<8;j++) acc[i][j] = __fmaf_rn(a8[i], b8[j], acc[i][j]);
        }
        if(t+1<nk){
            __syncthreads();
            store(1-cur);
            __syncthreads();
        }
    }

    #pragma unroll
    for(int i=0;i<8;i++){
        int gm = m0+ty*8+i;
        if(gm>=M) continue;
        #pragma unroll
        for(int j=0;j<8;j++){
            int gn = n0+tx*8+j;
            if(gn>=Ncol) continue;
            float v = acc[i][j];
            if(MODE==1)
                v = __fsub_rn(__fsub_rn(__fmul_rn(2.0f, v), e0[(size_t)b*NN+gm]), e0[(size_t)b*NN+gn]);
            else if(MODE==2)
                v = __fadd_rn(v, e0[(size_t)b*M+gm]);
            Cp[(size_t)gm*Ncol + gn] = v;
        }
    }
}

// ------------------------- small kernels -------------------------

__global__ void k_tin(const float* __restrict__ x){
    int i = blockIdx.x*blockDim.x + threadIdx.x;
    if(i >= BB*NN*3) return;
    int c = i%3; int n = (i/3)%NN; int b = i/(3*NN);
    g_xT[i] = x[((size_t)b*3 + c)*NN + n];
}

// per-point squared norm: ascending c, mul then add (ref lowering order)
__global__ void k_xx(int C){
    int p = blockIdx.x*blockDim.x + threadIdx.x;
    if(p >= BB*NN) return;
    const float* v = g_xT + (size_t)p*C;
    float s = 0.f;
    for(int c=0;c<C;c++) s = __fadd_rn(s, __fmul_rn(v[c], v[c]));
    g_xx[p] = s;
}

// Bucket-select + bitonic top-K (largest, min-index tiebreak; exact).
// 1) block min/max  2) 256-bin monotone histogram  3) pick bin B with suffix>=K
// 4) candidates (bucket>=B) packed as (monofloat<<32 | ~idx), ascending bitonic,
//    read top 20 from the high end -> descending value, ascending index on ties.
__global__ void __launch_bounds__(256) k_topk(){
    int n = blockIdx.x, bq = blockIdx.y;
    const float* row = g_dist + ((size_t)bq*NN + n)*NN;
    int tid = threadIdx.x, lane = tid&31, w = tid>>5;
    int base = tid*8;
    float v[8];
    {
        const float4* r4 = (const float4*)(row + base);
        float4 q0 = r4[0], q1 = r4[1];
        v[0]=q0.x; v[1]=q0.y; v[2]=q0.z; v[3]=q0.w;
        v[4]=q1.x; v[5]=q1.y; v[6]=q1.z; v[7]=q1.w;
    }
    __shared__ float swmx[8], swmn[8];
    __shared__ int hist[256];
    __shared__ unsigned long long cand[256];
    __shared__ int s_cnt, s_B;
    __shared__ float s_lo, s_hi;

    float mx=v[0], mn=v[0];
    #pragma unroll
    for(int t=1;t<8;t++){ mx=fmaxf(mx,v[t]); mn=fminf(mn,v[t]); }
    #pragma unroll
    for(int o=16;o;o>>=1){
        mx=fmaxf(mx,__shfl_xor_sync(0xffffffffu,mx,o));
        mn=fminf(mn,__shfl_xor_sync(0xffffffffu,mn,o));
    }
    if(lane==0){ swmx[w]=mx; swmn[w]=mn; }
    hist[tid]=0;
    __syncthreads();
    if(tid==0){
        float hx=swmx[0], hn=swmn[0];
        #pragma unroll
        for(int q=1;q<8;q++){ hx=fmaxf(hx,swmx[q]); hn=fminf(hn,swmn[q]); }
        s_lo=hn; s_hi=hx; s_cnt=0;
    }
    __syncthreads();
    float lo=s_lo, hi=s_hi;
    float scale = (hi>lo) ? 255.0f/(hi-lo) : 0.0f;
    int bk[8];
    #pragma unroll
    for(int t=0;t<8;t++){
        int bb = (int)((v[t]-lo)*scale);
        bb = max(0, min(255, bb));
        bk[t]=bb;
        atomicAdd(&hist[bb],1);
    }
    __syncthreads();
    if(w==0){
        int cs = 0;
        #pragma unroll
        for(int t=0;t<8;t++) cs += hist[lane*8+t];
        int rs = cs;                               // inclusive suffix over chunks
        #pragma unroll
        for(int o=1;o<32;o<<=1){
            int t2 = __shfl_down_sync(0xffffffffu, rs, o);
            if(lane+o<32) rs += t2;
        }
        int sufx = rs - cs;                        // exclusive suffix
        if(rs >= KNB && sufx < KNB){               // exactly one lane
            int run = sufx, Bv = lane*8;
            for(int j=7;j>=0;j--){
                run += hist[lane*8+j];
                if(run >= KNB){ Bv = lane*8+j; break; }
            }
            s_B = Bv;
        }
    }
    __syncthreads();
    int B = s_B;
    #pragma unroll
    for(int t=0;t<8;t++){
        if(bk[t] >= B){
            int pos = atomicAdd(&s_cnt,1);
            if(pos<256){
                unsigned int u = __float_as_uint(v[t]);
                u = (u & 0x80000000u) ? ~u : (u | 0x80000000u);   // monotone map
                cand[pos] = ((unsigned long long)u<<32) | (unsigned int)(~(base+t));
            }
        }
    }
    __syncthreads();
    int cnt = s_cnt;
    if(cnt<=256){
        if(tid>=cnt) cand[tid]=0ull;
        __syncthreads();
        // classic bitonic ascending over 256 u64 keys
        for(int k=2;k<=256;k<<=1){
            for(int j=k>>1;j>0;j>>=1){
                int ixj = tid ^ j;
                if(ixj > tid){
                    bool up = ((tid & k) == 0);
                    unsigned long long a=cand[tid], c=cand[ixj];
                    if( (a > c) == up ){ cand[tid]=c; cand[ixj]=a; }
                }
                __syncthreads();
            }
        }
        if(tid<KNB)
            g_idx[((size_t)bq*NN+n)*KNB + tid] = (int)(~(unsigned int)cand[255-tid]);
    } else {
        // deterministic serial fallback (degenerate rows only; dist is scratch)
        if(tid==0){
            float* rw = g_dist + ((size_t)bq*NN + n)*NN;
            for(int j=0;j<KNB;j++){
                float bvv=-FLT_MAX; int bii=0;
                for(int i=0;i<NN;i++){ float vv=rw[i]; if(vv>bvv){bvv=vv;bii=i;} }
                g_idx[((size_t)bq*NN+n)*KNB + j]=bii;
                rw[bii]=-FLT_MAX;
            }
        }
    }
}

// G[b, n*K+k, :] = [ xT[idx] - xT[n] (C), xT[n] (C) ]
__global__ void k_gather(int C){
    int C2 = 2*C;
    size_t e = (size_t)blockIdx.x*blockDim.x + threadIdx.x;
    size_t total = (size_t)BB*NN*KNB*C2;
    if(e>=total) return;
    int c = (int)(e % C2);
    size_t r = e / C2;
    int k = (int)(r % KNB);
    int n = (int)((r/KNB) % NN);
    int b = (int)(r/((size_t)KNB*NN));
    int cc = (c < C) ? c : (c - C);
    float ctr = g_xT[((size_t)b*NN + n)*C + cc];
    float val;
    if(c < C){
        int m = g_idx[((size_t)b*NN+n)*KNB + k];
        val = __fsub_rn(g_xT[((size_t)b*NN + m)*C + cc], ctr);
    } else {
        val = ctr;
    }
    g_G[e] = val;
}

// reduce k -> max/min/sum/sumsq; vectorized loads, ascending-k op order
__global__ void k_kreduce(const float* __restrict__ s, int O){
    size_t p = (size_t)blockIdx.x*blockDim.x + threadIdx.x;
    size_t total = (size_t)BB*O*NN;
    if(p>=total) return;
    const float4* sp = (const float4*)(s + p*KNB);
    float h[KNB];
    #pragma unroll
    for(int q=0;q<5;q++){
        float4 f = sp[q];
        h[q*4+0]=f.x; h[q*4+1]=f.y; h[q*4+2]=f.z; h[q*4+3]=f.w;
    }
    float mx=-FLT_MAX, mn=FLT_MAX, sm=0.f, sq=0.f;
    #pragma unroll
    for(int k=0;k<KNB;k++){
        float hv = h[k];
        mx = fmaxf(mx,hv); mn = fminf(mn,hv);
        sm = __fadd_rn(sm,hv); sq = __fmaf_rn(hv,hv,sq);
    }
    g_kmax[p]=mx; g_kmin[p]=mn; g_ksum[p]=sm; g_ksq[p]=sq;
}

__global__ void k_ec_stats(int O){
    int o = blockIdx.x, tid = threadIdx.x;
    double s=0.0, ss=0.0;
    for(int b=0;b<BB;b++){
        size_t base = ((size_t)b*O + o)*NN;
        for(int n=tid;n<NN;n+=256){ s += g_ksum[base+n]; ss += g_ksq[base+n]; }
    }
    __shared__ double rs[256], rq[256];
    rs[tid]=s; rq[tid]=ss; __syncthreads();
    for(int st=128;st;st>>=1){ if(tid<st){ rs[tid]+=rs[tid+st]; rq[tid]+=rq[tid+st]; } __syncthreads(); }
    if(tid==0){
        double cnt = (double)BB*NN*KNB;
        double mean = rs[0]/cnt;
        double var  = rq[0]/cnt - mean*mean;
        g_prm[2*o]   = (float)mean;
        g_prm[2*o+1] = (float)var;
    }
}

__global__ void k_ec_apply(int O, int c0, float* __restrict__ xTout,
                           const float* __restrict__ gw, const float* __restrict__ bw){
    int o = blockIdx.x, b = blockIdx.y;
    float m = g_prm[2*o], vv = g_prm[2*o+1];
    float gg = gw[o], bb = bw[o];
    float sd = __fsqrt_rn(__fadd_rn(vv, EPSB));
    const float* src = (gg>=0.f ? g_kmax : g_kmin) + ((size_t)b*O + o)*NN;
    float* xc = g_xcat + ((size_t)b*512 + c0 + o)*NN;
    for(int n=threadIdx.x;n<NN;n+=blockDim.x){
        float y = __fadd_rn(__fmul_rn(__fdiv_rn(__fsub_rn(src[n], m), sd), gg), bb);
        y = (y>=0.f) ? y : __fmul_rn(NEGS, y);
        xc[n] = y;
        xTout[((size_t)b*NN + n)*O + o] = y;
    }
}

__global__ void k_conv_stats(const float* __restrict__ h, int O){
    int o = blockIdx.x, tid = threadIdx.x;
    double s=0.0, ss=0.0;
    for(int b=0;b<BB;b++){
        size_t base = ((size_t)b*O + o)*NN;
        for(int n=tid;n<NN;n+=256){ float v=h[base+n]; s += v; ss += (double)v*v; }
    }
    __shared__ double rs[256], rq[256];
    rs[tid]=s; rq[tid]=ss; __syncthreads();
    for(int st=128;st;st>>=1){ if(tid<st){ rs[tid]+=rs[tid+st]; rq[tid]+=rq[tid+st]; } __syncthreads(); }
    if(tid==0){
        double cnt = (double)BB*NN;
        double mean = rs[0]/cnt;
        double var  = rq[0]/cnt - mean*mean;
        g_prm[2*o]   = (float)mean;
        g_prm[2*o+1] = (float)var;
    }
}

__global__ void k_conv_apply(float* __restrict__ h, int O,
                             const float* __restrict__ gw, const float* __restrict__ bw){
    int o = blockIdx.x, b = blockIdx.y;
    float m = g_prm[2*o], vv = g_prm[2*o+1];
    float gg = gw[o], bb = bw[o];
    float sd = __fsqrt_rn(__fadd_rn(vv, EPSB));
    float* p = h + ((size_t)b*O + o)*NN;
    for(int n=threadIdx.x;n<NN;n+=blockDim.x){
        float y = __fadd_rn(__fmul_rn(__fdiv_rn(__fsub_rn(p[n], m), sd), gg), bb);
        p[n] = (y>=0.f) ? y : __fmul_rn(NEGS, y);
    }
}

__global__ void k_gmax(const float* __restrict__ gw, const float* __restrict__ bw){
    int o = blockIdx.x, b = blockIdx.y, tid = threadIdx.x;
    float gg = gw[o];
    const float* p = g_h5 + ((size_t)b*1024 + o)*NN;
    float m = -FLT_MAX, mn = FLT_MAX;
    for(int n=tid;n<NN;n+=256){
        float v = p[n];
        m = fmaxf(m, v); mn = fminf(mn, v);
    }
    __shared__ float r[256], r2[256];
    r[tid]=m; r2[tid]=mn; __syncthreads();
    for(int st=128;st;st>>=1){
        if(tid<st){ r[tid]=fmaxf(r[tid], r[tid+st]); r2[tid]=fminf(r2[tid], r2[tid+st]); }
        __syncthreads();
    }
    if(tid==0){
        float src = (gg>=0.f) ? r[0] : r2[0];
        float mm = g_prm[2*o], vv = g_prm[2*o+1];
        float sd = __fsqrt_rn(__fadd_rn(vv, EPSB));
        float y = __fadd_rn(__fmul_rn(__fdiv_rn(__fsub_rn(src, mm), sd), gg), bw[o]);
        y = (y>=0.f) ? y : __fmul_rn(NEGS, y);
        g_glob[b*1088 + o] = y;
    }
}

__global__ void k_lf(const float* __restrict__ l, const float* __restrict__ W,
                     const float* __restrict__ gw, const float* __restrict__ bw){
    int tid = threadIdx.x;
    int o = tid & 63, b = tid >> 6;
    __shared__ float hs[8][64];
    __shared__ float pm[64], pv[64];
    float s = 0.f;
    #pragma unroll
    for(int c=0;c<16;c++) s = __fmaf_rn(W[o*16 + c], l[b*16 + c], s);
    hs[b][o] = s;
    __syncthreads();
    if(tid < 64){
        float m = 0.f;
        #pragma unroll
        for(int q=0;q<8;q++) m = __fadd_rn(m, hs[q][tid]);
        m = __fdiv_rn(m, 8.f);
        float v = 0.f;
        #pragma unroll
        for(int q=0;q<8;q++){ float d = __fsub_rn(hs[q][tid], m); v = __fmaf_rn(d, d, v); }
        v = __fdiv_rn(v, 8.f);
        pm[tid] = m; pv[tid] = v;
    }
    __syncthreads();
    float sd = __fsqrt_rn(__fadd_rn(pv[o], EPSB));
    float y = __fadd_rn(__fmul_rn(__fdiv_rn(__fsub_rn(hs[b][o], pm[o]), sd), gw[o]), bw[o]);
    y = (y>=0.f) ? y : __fmul_rn(NEGS, y);
    g_glob[b*1088 + 1024 + o] = y;
}

__global__ void k_bias207(const float* __restrict__ W207){
    int b = blockIdx.x;
    __shared__ float gl[1088];
    for(int i=threadIdx.x;i<1088;i+=256) gl[i] = g_glob[b*1088 + i];
    __syncthreads();
    int o = threadIdx.x;
    float s = 0.f;
    for(int c=0;c<1088;c++) s = __fmaf_rn(W207[(size_t)o*1600 + c], gl[c], s);
    g_b207[b*256 + o] = s;
}

// ------------------------- launcher -------------------------
extern "C" void kernel_launch(void* const* d_in, const int* in_sizes, int n_in,
                              void* d_out, int out_size){
    (void)in_sizes; (void)n_in; (void)out_size;
    const float* x    = (const float*)d_in[0];
    const float* l    = (const float*)d_in[1];
    const float* Wec[4] = {(const float*)d_in[2],(const float*)d_in[5],(const float*)d_in[8],(const float*)d_in[11]};
    const float* gec[4] = {(const float*)d_in[3],(const float*)d_in[6],(const float*)d_in[9],(const float*)d_in[12]};
    const float* bec[4] = {(const float*)d_in[4],(const float*)d_in[7],(const float*)d_in[10],(const float*)d_in[13]};
    const float* W5   = (const float*)d_in[14]; const float* g5v  = (const float*)d_in[15]; const float* b5v  = (const float*)d_in[16];
    const float* W206 = (const float*)d_in[17]; const float* g206 = (const float*)d_in[18]; const float* b206 = (const float*)d_in[19];
    const float* W207 = (const float*)d_in[20]; const float* g207 = (const float*)d_in[21]; const float* b207 = (const float*)d_in[22];
    const float* W208 = (const float*)d_in[23]; const float* g208 = (const float*)d_in[24]; const float* b208 = (const float*)d_in[25];
    const float* W209 = (const float*)d_in[26]; const float* g209 = (const float*)d_in[27]; const float* b209 = (const float*)d_in[28];
    const float* W2010= (const float*)d_in[29];

    float *xT,*xxp,*dist,*G,*sbuf,*xcat,*h5,*hb1,*hb2,*hb3,*b207p;
    cudaGetSymbolAddress((void**)&xT,   g_xT);
    cudaGetSymbolAddress((void**)&xxp,  g_xx);
    cudaGetSymbolAddress((void**)&dist, g_dist);
    cudaGetSymbolAddress((void**)&G,    g_G);
    cudaGetSymbolAddress((void**)&sbuf, g_s);
    cudaGetSymbolAddress((void**)&xcat, g_xcat);
    cudaGetSymbolAddress((void**)&h5,   g_h5);
    cudaGetSymbolAddress((void**)&hb1,  g_hb1);
    cudaGetSymbolAddress((void**)&hb2,  g_hb2);
    cudaGetSymbolAddress((void**)&hb3,  g_hb3);
    cudaGetSymbolAddress((void**)&b207p,g_b207);

    const int Cin[4] = {3,64,64,128};
    const int Oo [4] = {64,64,128,256};
    const int c0 [4] = {0,64,128,256};

    k_tin<<<(BB*NN*3 + 255)/256, 256>>>(x);

    for(int li=0; li<4; li++){
        int C = Cin[li], O = Oo[li];
        k_xx<<<(BB*NN + 255)/256, 256>>>(C);
        k_gemm<false,1><<<dim3(NN/128, NN/128, BB), 256>>>(
            NN, NN, C, xT, C, (size_t)NN*C, xT, C, (size_t)NN*C, dist, (size_t)NN*NN, xxp);
        k_topk<<<dim3(NN, BB), 256>>>();
        int C2 = 2*C;
        size_t tot = (size_t)BB*NN*KNB*C2;
        k_gather<<<(unsigned)((tot + 255)/256), 256>>>(C);
        int J = NN*KNB;
        k_gemm<false,0><<<dim3(J/128, (O+127)/128, BB), 256>>>(
            O, J, C2, Wec[li], C2, 0, G, C2, (size_t)J*C2, sbuf, (size_t)O*J, nullptr);
        size_t tp = (size_t)BB*O*NN;
        k_kreduce<<<(unsigned)((tp + 255)/256), 256>>>(sbuf, O);
        k_ec_stats<<<O, 256>>>(O);
        k_ec_apply<<<dim3(O, BB), 256>>>(O, c0[li], xT, gec[li], bec[li]);
    }

    k_gemm<true,0><<<dim3(NN/128, 1024/128, BB), 256>>>(
        1024, NN, 512, W5, 512, 0, xcat, NN, (size_t)512*NN, h5, (size_t)1024*NN, nullptr);
    k_conv_stats<<<1024, 256>>>(h5, 1024);
    k_gmax<<<dim3(1024, BB), 256>>>(g5v, b5v);
    k_lf<<<1, 512>>>(l, W206, g206, b206);
    k_bias207<<<BB, 256>>>(W207);
    k_gemm<true,2><<<dim3(NN/128, 2, BB), 256>>>(
        256, NN, 512, W207 + 1088, 1600, 0, xcat, NN, (size_t)512*NN, hb1, (size_t)256*NN, b207p);
    k_conv_stats<<<256, 256>>>(hb1, 256);
    k_conv_apply<<<dim3(256, BB), 256>>>(hb1, 256, g207, b207);
    k_gemm<true,0><<<dim3(NN/128, 2, BB), 256>>>(
        256, NN, 256, W208, 256, 0, hb1, NN, (size_t)256*NN, hb2, (size_t)256*NN, nullptr);
    k_conv_stats<<<256, 256>>>(hb2, 256);
    k_conv_apply<<<dim3(256, BB), 256>>>(hb2, 256, g208, b208);
    k_gemm<true,0><<<dim3(NN/128, 1, BB), 256>>>(
        128, NN, 256, W209, 256, 0, hb2, NN, (size_t)256*NN, hb3, (size_t)128*NN, nullptr);
    k_conv_stats<<<128, 256>>>(hb3, 128);
    k_conv_apply<<<dim3(128, BB), 256>>>(hb3, 128, g209, b209);
    k_gemm<true,0><<<dim3(NN/128, 1, BB), 256>>>(
        50, NN, 128, W2010, 128, 0, hb3, NN, (size_t)128*NN, (float*)d_out, (size_t)50*NN, nullptr);
}

// round 8
// speedup vs baseline: 1.2258x; 1.0527x over previous
#include <cuda_runtime.h>
#include <cstdlib>
#include <cfloat>

#define BB 8
#define NN 2048
#define KNB 20
#define NEGS 0.2f
#define EPSB 1e-5f

__attribute__((constructor)) static void _eager_load(){ setenv("CUDA_MODULE_LOADING","EAGER",0); }

// ------------------------- scratch (device globals) -------------------------
__device__ float g_xT  [(size_t)BB*NN*256];
__device__ float g_xx  [BB*NN];
__device__ float g_dist[(size_t)BB*NN*NN];
__device__ int   g_idx [(size_t)BB*NN*KNB];
__device__ float g_kmax[(size_t)BB*256*NN];
__device__ float g_kmin[(size_t)BB*256*NN];
__device__ float g_ksum[(size_t)BB*256*NN];
__device__ float g_ksq [(size_t)BB*256*NN];
__device__ float g_xcat[(size_t)BB*512*NN];
__device__ float g_h5  [(size_t)BB*1024*NN];
__device__ float g_hb1 [(size_t)BB*256*NN];
__device__ float g_hb2 [(size_t)BB*256*NN];
__device__ float g_hb3 [(size_t)BB*128*NN];
__device__ float g_glob[BB*1088];
__device__ float g_b207[BB*256];
__device__ float g_prm [2048];

// ------------------------- generic fp32 GEMM (pipelined, bit-identical math) --
// Single accumulator per output, FMA, k strictly ascending.
// MODE 0: plain   MODE 1: dist epilogue   MODE 2: row bias
template<bool BT, int MODE>
__global__ void __launch_bounds__(256,2) k_gemm(
    int M, int Ncol, int Kd,
    const float* __restrict__ A, int lda, size_t asb,
    const float* __restrict__ Bp, int ldb, size_t bsb,
    float* __restrict__ Cp, size_t csb,
    const float* __restrict__ e0)
{
    const int BM=128, BN=128, BK=16;
    __shared__ float As[2][BK][BM+4];
    __shared__ float Bs[2][BK][BN+4];
    int b  = blockIdx.z;
    int m0 = blockIdx.y*BM, n0 = blockIdx.x*BN;
    A  += (size_t)b*asb;
    Bp += (size_t)b*bsb;
    Cp += (size_t)b*csb;
    int tid = threadIdx.x;
    int tx = tid%16, ty = tid/16;

    float acc[8][8];
    #pragma unroll
    for(int i=0;i<8;i++)
        #pragma unroll
        for(int j=0;j<8;j++) acc[i][j]=0.f;

    float ra[8], rb[8];

    auto fetchA = [&](int k0){
        #pragma unroll
        for(int i=0;i<8;i++){
            int e = tid + 256*i;
            int kk=e%BK, mm=e/BK;
            int gm=m0+mm, gk=k0+kk;
            ra[i] = (gm<M && gk<Kd) ? A[(size_t)gm*lda+gk] : 0.f;
        }
    };
    auto fetchB = [&](int k0){
        if(!BT){
            #pragma unroll
            for(int i=0;i<8;i++){
                int e = tid + 256*i;
                int kk=e%BK, nn=e/BK;
                int gn=n0+nn, gk=k0+kk;
                rb[i] = (gn<Ncol && gk<Kd) ? Bp[(size_t)gn*ldb+gk] : 0.f;
            }
        } else {
            #pragma unroll
            for(int i=0;i<8;i++){
                int e = tid + 256*i;
                int nn=e%BN, kk=e/BN;
                int gn=n0+nn, gk=k0+kk;
                rb[i] = (gn<Ncol && gk<Kd) ? Bp[(size_t)gk*ldb+gn] : 0.f;
            }
        }
    };
    auto store = [&](int buf){
        #pragma unroll
        for(int i=0;i<8;i++){
            int e = tid + 256*i;
            As[buf][e%BK][e/BK] = ra[i];
        }
        if(!BT){
            #pragma unroll
            for(int i=0;i<8;i++){
                int e = tid + 256*i;
                Bs[buf][e%BK][e/BK] = rb[i];
            }
        } else {
            #pragma unroll
            for(int i=0;i<8;i++){
                int e = tid + 256*i;
                Bs[buf][e/BN][e%BN] = rb[i];
            }
        }
    };

    int nk = (Kd + BK - 1)/BK;
    fetchA(0); fetchB(0);
    store(0);
    __syncthreads();

    for(int t=0;t<nk;t++){
        int cur = t&1;
        if(t+1<nk){ fetchA((t+1)*BK); fetchB((t+1)*BK); }
        #pragma unroll
        for(int kk=0;kk<BK;kk++){   // ascending k, FMA, single accumulator
            float a8[8], b8[8];
            #pragma unroll
            for(int i=0;i<8;i++) a8[i]=As[cur][kk][ty*8+i];
            #pragma unroll
            for(int j=0;j<8;j++) b8[j]=Bs[cur][kk][tx*8+j];
            #pragma unroll
            for(int i=0;i<8;i++)
                #pragma unroll
                for(int j=0;j<8;j++) acc[i][j] = __fmaf_rn(a8[i], b8[j], acc[i][j]);
        }
        if(t+1<nk){
            __syncthreads();
            store(1-cur);
            __syncthreads();
        }
    }

    #pragma unroll
    for(int i=0;i<8;i++){
        int gm = m0+ty*8+i;
        if(gm>=M) continue;
        #pragma unroll
        for(int j=0;j<8;j++){
            int gn = n0+tx*8+j;
            if(gn>=Ncol) continue;
            float v = acc[i][j];
            if(MODE==1)
                v = __fsub_rn(__fsub_rn(__fmul_rn(2.0f, v), e0[(size_t)b*NN+gm]), e0[(size_t)b*NN+gn]);
            else if(MODE==2)
                v = __fadd_rn(v, e0[(size_t)b*M+gm]);
            Cp[(size_t)gm*Ncol + gn] = v;
        }
    }
}

// ------------- fused edge-conv GEMM + k-reduce (BN = 160 = 8 points x 20) ----
// h[o, n*20+k] = sum_c W[o,c] * f[n,k,c],  f = [xT[idx]-xT[n], xT[n]]
// Epilogue reduces over k (strict ascending order, bit-identical to the old
// separate kreduce) and writes kmax/kmin/ksum/ksq at [(b*O+o)*NN + n].
__global__ void __launch_bounds__(256,2) k_egemm(
    int M, int Kd,                       // M = O, Kd = 2C
    const float* __restrict__ A,         // W  [O, 2C]
    const float* __restrict__ xTp,       // [B, N, C]
    const int*   __restrict__ idxp,      // [B, N, K]
    int Cc)
{
    const int BM=128, BN=160, BK=16;
    __shared__ float As[2][BK][BM+4];
    __shared__ float Bs[2][BK][BN+4];
    __shared__ int   s_m [BN];           // neighbor point id per column
    __shared__ int   s_pt[BN];           // local point (0..7) per column
    int b  = blockIdx.z;
    int m0 = blockIdx.y*BM;
    int p0 = blockIdx.x*8;               // first point of this tile
    xTp  += (size_t)b*NN*Cc;
    idxp += (size_t)b*NN*KNB;
    int tid = threadIdx.x;
    int tx = tid%16, ty = tid/16;

    if(tid < BN){
        int pt = tid/KNB;
        int kq = tid - pt*KNB;
        s_pt[tid] = pt;
        s_m [tid] = idxp[(size_t)(p0+pt)*KNB + kq];
    }
    __syncthreads();

    float acc[8][10];
    #pragma unroll
    for(int i=0;i<8;i++)
        #pragma unroll
        for(int j=0;j<10;j++) acc[i][j]=0.f;

    float ra[8], rb[10];

    auto fetchA = [&](int k0){
        #pragma unroll
        for(int i=0;i<8;i++){
            int e = tid + 256*i;
            int kk=e&15, mm=e>>4;
            int gm=m0+mm, gk=k0+kk;
            ra[i] = (gm<M && gk<Kd) ? A[(size_t)gm*Kd+gk] : 0.f;
        }
    };
    auto fetchB = [&](int k0){
        #pragma unroll
        for(int i=0;i<10;i++){
            int e = tid + 256*i;
            int kk=e&15, nn=e>>4;
            int gk=k0+kk;
            float val = 0.f;
            if(gk<Kd){
                int cc = (gk<Cc) ? gk : gk-Cc;
                float ctr = xTp[(size_t)(p0+s_pt[nn])*Cc + cc];
                if(gk<Cc){
                    float nb = xTp[(size_t)s_m[nn]*Cc + cc];
                    val = __fsub_rn(nb, ctr);
                } else val = ctr;
            }
            rb[i] = val;
        }
    };
    auto store = [&](int buf){
        #pragma unroll
        for(int i=0;i<8;i++){
            int e = tid + 256*i;
            As[buf][e&15][e>>4] = ra[i];
        }
        #pragma unroll
        for(int i=0;i<10;i++){
            int e = tid + 256*i;
            Bs[buf][e&15][e>>4] = rb[i];
        }
    };

    int nk = (Kd + BK - 1)/BK;
    fetchA(0); fetchB(0);
    store(0);
    __syncthreads();

    for(int t=0;t<nk;t++){
        int cur = t&1;
        if(t+1<nk){ fetchA((t+1)*BK); fetchB((t+1)*BK); }
        #pragma unroll
        for(int kk=0;kk<BK;kk++){
            float a8[8], b10[10];
            #pragma unroll
            for(int i=0;i<8;i++) a8[i]=As[cur][kk][ty*8+i];
            #pragma unroll
            for(int j=0;j<10;j++) b10[j]=Bs[cur][kk][tx*10+j];
            #pragma unroll
            for(int i=0;i<8;i++)
                #pragma unroll
                for(int j=0;j<10;j++) acc[i][j] = __fmaf_rn(a8[i], b10[j], acc[i][j]);
        }
        if(t+1<nk){
            __syncthreads();
            store(1-cur);
            __syncthreads();
        }
    }

    // Epilogue: strict ascending-k reduction. Even-tx thread holds k0..9 of
    // point p0 + tx/2; partner (tx|1) holds k10..19. Fold own 10 in order,
    // then partner's 10 in order via shfl — identical op sequence to the old
    // kreduce (init: -FLT_MAX/FLT_MAX/0/0, fmaxf/fminf/__fadd_rn/__fmaf_rn).
    int O = M;
    #pragma unroll
    for(int i=0;i<8;i++){
        float mx=-FLT_MAX, mn=FLT_MAX, sm=0.f, sq=0.f;
        #pragma unroll
        for(int j=0;j<10;j++){
            float h = acc[i][j];
            mx = fmaxf(mx,h); mn = fminf(mn,h);
            sm = __fadd_rn(sm,h); sq = __fmaf_rn(h,h,sq);
        }
        #pragma unroll
        for(int j=0;j<10;j++){
            float h = __shfl_xor_sync(0xffffffffu, acc[i][j], 1);
            mx = fmaxf(mx,h); mn = fminf(mn,h);
            sm = __fadd_rn(sm,h); sq = __fmaf_rn(h,h,sq);
        }
        int gm = m0 + ty*8 + i;
        if(((tx&1)==0) && gm<M){
            int point = p0 + (tx>>1);
            size_t base = ((size_t)b*O + gm)*NN + point;
            g_kmax[base]=mx; g_kmin[base]=mn; g_ksum[base]=sm; g_ksq[base]=sq;
        }
    }
}

// ------------------------- small kernels -------------------------

__global__ void k_tin(const float* __restrict__ x){
    int i = blockIdx.x*blockDim.x + threadIdx.x;
    if(i >= BB*NN*3) return;
    int c = i%3; int n = (i/3)%NN; int b = i/(3*NN);
    g_xT[i] = x[((size_t)b*3 + c)*NN + n];
}

// per-point squared norm: ascending c, mul then add (ref lowering order)
__global__ void k_xx(int C){
    int p = blockIdx.x*blockDim.x + threadIdx.x;
    if(p >= BB*NN) return;
    const float* v = g_xT + (size_t)p*C;
    float s = 0.f;
    for(int c=0;c<C;c++) s = __fadd_rn(s, __fmul_rn(v[c], v[c]));
    g_xx[p] = s;
}

// Bucket-select + bitonic top-K (largest, min-index tiebreak; exact).
__global__ void __launch_bounds__(256) k_topk(){
    int n = blockIdx.x, bq = blockIdx.y;
    const float* row = g_dist + ((size_t)bq*NN + n)*NN;
    int tid = threadIdx.x, lane = tid&31, w = tid>>5;
    int base = tid*8;
    float v[8];
    {
        const float4* r4 = (const float4*)(row + base);
        float4 q0 = r4[0], q1 = r4[1];
        v[0]=q0.x; v[1]=q0.y; v[2]=q0.z; v[3]=q0.w;
        v[4]=q1.x; v[5]=q1.y; v[6]=q1.z; v[7]=q1.w;
    }
    __shared__ float swmx[8], swmn[8];
    __shared__ int hist[256];
    __shared__ unsigned long long cand[256];
    __shared__ int s_cnt, s_B;
    __shared__ float s_lo, s_hi;

    float mx=v[0], mn=v[0];
    #pragma unroll
    for(int t=1;t<8;t++){ mx=fmaxf(mx,v[t]); mn=fminf(mn,v[t]); }
    #pragma unroll
    for(int o=16;o;o>>=1){
        mx=fmaxf(mx,__shfl_xor_sync(0xffffffffu,mx,o));
        mn=fminf(mn,__shfl_xor_sync(0xffffffffu,mn,o));
    }
    if(lane==0){ swmx[w]=mx; swmn[w]=mn; }
    hist[tid]=0;
    __syncthreads();
    if(tid==0){
        float hx=swmx[0], hn=swmn[0];
        #pragma unroll
        for(int q=1;q<8;q++){ hx=fmaxf(hx,swmx[q]); hn=fminf(hn,swmn[q]); }
        s_lo=hn; s_hi=hx; s_cnt=0;
    }
    __syncthreads();
    float lo=s_lo, hi=s_hi;
    float scale = (hi>lo) ? 255.0f/(hi-lo) : 0.0f;
    int bk[8];
    #pragma unroll
    for(int t=0;t<8;t++){
        int bb = (int)((v[t]-lo)*scale);
        bb = max(0, min(255, bb));
        bk[t]=bb;
        atomicAdd(&hist[bb],1);
    }
    __syncthreads();
    if(w==0){
        int cs = 0;
        #pragma unroll
        for(int t=0;t<8;t++) cs += hist[lane*8+t];
        int rs = cs;
        #pragma unroll
        for(int o=1;o<32;o<<=1){
            int t2 = __shfl_down_sync(0xffffffffu, rs, o);
            if(lane+o<32) rs += t2;
        }
        int sufx = rs - cs;
        if(rs >= KNB && sufx < KNB){
            int run = sufx, Bv = lane*8;
            for(int j=7;j>=0;j--){
                run += hist[lane*8+j];
                if(run >= KNB){ Bv = lane*8+j; break; }
            }
            s_B = Bv;
        }
    }
    __syncthreads();
    int B = s_B;
    #pragma unroll
    for(int t=0;t<8;t++){
        if(bk[t] >= B){
            int pos = atomicAdd(&s_cnt,1);
            if(pos<256){
                unsigned int u = __float_as_uint(v[t]);
                u = (u & 0x80000000u) ? ~u : (u | 0x80000000u);
                cand[pos] = ((unsigned long long)u<<32) | (unsigned int)(~(base+t));
            }
        }
    }
    __syncthreads();
    int cnt = s_cnt;
    if(cnt<=256){
        if(tid>=cnt) cand[tid]=0ull;
        __syncthreads();
        for(int k=2;k<=256;k<<=1){
            for(int j=k>>1;j>0;j>>=1){
                int ixj = tid ^ j;
                if(ixj > tid){
                    bool up = ((tid & k) == 0);
                    unsigned long long a=cand[tid], c=cand[ixj];
                    if( (a > c) == up ){ cand[tid]=c; cand[ixj]=a; }
                }
                __syncthreads();
            }
        }
        if(tid<KNB)
            g_idx[((size_t)bq*NN+n)*KNB + tid] = (int)(~(unsigned int)cand[255-tid]);
    } else {
        if(tid==0){
            float* rw = g_dist + ((size_t)bq*NN + n)*NN;
            for(int j=0;j<KNB;j++){
                float bvv=-FLT_MAX; int bii=0;
                for(int i=0;i<NN;i++){ float vv=rw[i]; if(vv>bvv){bvv=vv;bii=i;} }
                g_idx[((size_t)bq*NN+n)*KNB + j]=bii;
                rw[bii]=-FLT_MAX;
            }
        }
    }
}

__global__ void k_ec_stats(int O){
    int o = blockIdx.x, tid = threadIdx.x;
    double s=0.0, ss=0.0;
    for(int b=0;b<BB;b++){
        size_t base = ((size_t)b*O + o)*NN;
        for(int n=tid;n<NN;n+=256){ s += g_ksum[base+n]; ss += g_ksq[base+n]; }
    }
    __shared__ double rs[256], rq[256];
    rs[tid]=s; rq[tid]=ss; __syncthreads();
    for(int st=128;st;st>>=1){ if(tid<st){ rs[tid]+=rs[tid+st]; rq[tid]+=rq[tid+st]; } __syncthreads(); }
    if(tid==0){
        double cnt = (double)BB*NN*KNB;
        double mean = rs[0]/cnt;
        double var  = rq[0]/cnt - mean*mean;
        g_prm[2*o]   = (float)mean;
        g_prm[2*o+1] = (float)var;
    }
}

__global__ void k_ec_apply(int O, int c0, float* __restrict__ xTout,
                           const float* __restrict__ gw, const float* __restrict__ bw){
    int o = blockIdx.x, b = blockIdx.y;
    float m = g_prm[2*o], vv = g_prm[2*o+1];
    float gg = gw[o], bb = bw[o];
    float sd = __fsqrt_rn(__fadd_rn(vv, EPSB));
    const float* src = (gg>=0.f ? g_kmax : g_kmin) + ((size_t)b*O + o)*NN;
    float* xc = g_xcat + ((size_t)b*512 + c0 + o)*NN;
    for(int n=threadIdx.x;n<NN;n+=blockDim.x){
        float y = __fadd_rn(__fmul_rn(__fdiv_rn(__fsub_rn(src[n], m), sd), gg), bb);
        y = (y>=0.f) ? y : __fmul_rn(NEGS, y);
        xc[n] = y;
        xTout[((size_t)b*NN + n)*O + o] = y;
    }
}

__global__ void k_conv_stats(const float* __restrict__ h, int O){
    int o = blockIdx.x, tid = threadIdx.x;
    double s=0.0, ss=0.0;
    for(int b=0;b<BB;b++){
        size_t base = ((size_t)b*O + o)*NN;
        for(int n=tid;n<NN;n+=256){ float v=h[base+n]; s += v; ss += (double)v*v; }
    }
    __shared__ double rs[256], rq[256];
    rs[tid]=s; rq[tid]=ss; __syncthreads();
    for(int st=128;st;st>>=1){ if(tid<st){ rs[tid]+=rs[tid+st]; rq[tid]+=rq[tid+st]; } __syncthreads(); }
    if(tid==0){
        double cnt = (double)BB*NN;
        double mean = rs[0]/cnt;
        double var  = rq[0]/cnt - mean*mean;
        g_prm[2*o]   = (float)mean;
        g_prm[2*o+1] = (float)var;
    }
}

__global__ void k_conv_apply(float* __restrict__ h, int O,
                             const float* __restrict__ gw, const float* __restrict__ bw){
    int o = blockIdx.x, b = blockIdx.y;
    float m = g_prm[2*o], vv = g_prm[2*o+1];
    float gg = gw[o], bb = bw[o];
    float sd = __fsqrt_rn(__fadd_rn(vv, EPSB));
    float* p = h + ((size_t)b*O + o)*NN;
    for(int n=threadIdx.x;n<NN;n+=blockDim.x){
        float y = __fadd_rn(__fmul_rn(__fdiv_rn(__fsub_rn(p[n], m), sd), gg), bb);
        p[n] = (y>=0.f) ? y : __fmul_rn(NEGS, y);
    }
}

__global__ void k_gmax(const float* __restrict__ gw, const float* __restrict__ bw){
    int o = blockIdx.x, b = blockIdx.y, tid = threadIdx.x;
    float gg = gw[o];
    const float* p = g_h5 + ((size_t)b*1024 + o)*NN;
    float m = -FLT_MAX, mn = FLT_MAX;
    for(int n=tid;n<NN;n+=256){
        float v = p[n];
        m = fmaxf(m, v); mn = fminf(mn, v);
    }
    __shared__ float r[256], r2[256];
    r[tid]=m; r2[tid]=mn; __syncthreads();
    for(int st=128;st;st>>=1){
        if(tid<st){ r[tid]=fmaxf(r[tid], r[tid+st]); r2[tid]=fminf(r2[tid], r2[tid+st]); }
        __syncthreads();
    }
    if(tid==0){
        float src = (gg>=0.f) ? r[0] : r2[0];
        float mm = g_prm[2*o], vv = g_prm[2*o+1];
        float sd = __fsqrt_rn(__fadd_rn(vv, EPSB));
        float y = __fadd_rn(__fmul_rn(__fdiv_rn(__fsub_rn(src, mm), sd), gg), bw[o]);
        y = (y>=0.f) ? y : __fmul_rn(NEGS, y);
        g_glob[b*1088 + o] = y;
    }
}

__global__ void k_lf(const float* __restrict__ l, const float* __restrict__ W,
                     const float* __restrict__ gw, const float* __restrict__ bw){
    int tid = threadIdx.x;
    int o = tid & 63, b = tid >> 6;
    __shared__ float hs[8][64];
    __shared__ float pm[64], pv[64];
    float s = 0.f;
    #pragma unroll
    for(int c=0;c<16;c++) s = __fmaf_rn(W[o*16 + c], l[b*16 + c], s);
    hs[b][o] = s;
    __syncthreads();
    if(tid < 64){
        float m = 0.f;
        #pragma unroll
        for(int q=0;q<8;q++) m = __fadd_rn(m, hs[q][tid]);
        m = __fdiv_rn(m, 8.f);
        float v = 0.f;
        #pragma unroll
        for(int q=0;q<8;q++){ float d = __fsub_rn(hs[q][tid], m); v = __fmaf_rn(d, d, v); }
        v = __fdiv_rn(v, 8.f);
        pm[tid] = m; pv[tid] = v;
    }
    __syncthreads();
    float sd = __fsqrt_rn(__fadd_rn(pv[o], EPSB));
    float y = __fadd_rn(__fmul_rn(__fdiv_rn(__fsub_rn(hs[b][o], pm[o]), sd), gw[o]), bw[o]);
    y = (y>=0.f) ? y : __fmul_rn(NEGS, y);
    g_glob[b*1088 + 1024 + o] = y;
}

__global__ void k_bias207(const float* __restrict__ W207){
    int b = blockIdx.x;
    __shared__ float gl[1088];
    for(int i=threadIdx.x;i<1088;i+=256) gl[i] = g_glob[b*1088 + i];
    __syncthreads();
    int o = threadIdx.x;
    float s = 0.f;
    for(int c=0;c<1088;c++) s = __fmaf_rn(W207[(size_t)o*1600 + c], gl[c], s);
    g_b207[b*256 + o] = s;
}

// ------------------------- launcher -------------------------
extern "C" void kernel_launch(void* const* d_in, const int* in_sizes, int n_in,
                              void* d_out, int out_size){
    (void)in_sizes; (void)n_in; (void)out_size;
    const float* x    = (const float*)d_in[0];
    const float* l    = (const float*)d_in[1];
    const float* Wec[4] = {(const float*)d_in[2],(const float*)d_in[5],(const float*)d_in[8],(const float*)d_in[11]};
    const float* gec[4] = {(const float*)d_in[3],(const float*)d_in[6],(const float*)d_in[9],(const float*)d_in[12]};
    const float* bec[4] = {(const float*)d_in[4],(const float*)d_in[7],(const float*)d_in[10],(const float*)d_in[13]};
    const float* W5   = (const float*)d_in[14]; const float* g5v  = (const float*)d_in[15]; const float* b5v  = (const float*)d_in[16];
    const float* W206 = (const float*)d_in[17]; const float* g206 = (const float*)d_in[18]; const float* b206 = (const float*)d_in[19];
    const float* W207 = (const float*)d_in[20]; const float* g207 = (const float*)d_in[21]; const float* b207 = (const float*)d_in[22];
    const float* W208 = (const float*)d_in[23]; const float* g208 = (const float*)d_in[24]; const float* b208 = (const float*)d_in[25];
    const float* W209 = (const float*)d_in[26]; const float* g209 = (const float*)d_in[27]; const float* b209 = (const float*)d_in[28];
    const float* W2010= (const float*)d_in[29];

    float *xT,*xxp,*dist,*xcat,*h5,*hb1,*hb2,*hb3,*b207p;
    int *idxp;
    cudaGetSymbolAddress((void**)&xT,   g_xT);
    cudaGetSymbolAddress((void**)&xxp,  g_xx);
    cudaGetSymbolAddress((void**)&dist, g_dist);
    cudaGetSymbolAddress((void**)&idxp, g_idx);
    cudaGetSymbolAddress((void**)&xcat, g_xcat);
    cudaGetSymbolAddress((void**)&h5,   g_h5);
    cudaGetSymbolAddress((void**)&hb1,  g_hb1);
    cudaGetSymbolAddress((void**)&hb2,  g_hb2);
    cudaGetSymbolAddress((void**)&hb3,  g_hb3);
    cudaGetSymbolAddress((void**)&b207p,g_b207);

    const int Cin[4] = {3,64,64,128};
    const int Oo [4] = {64,64,128,256};
    const int c0 [4] = {0,64,128,256};

    k_tin<<<(BB*NN*3 + 255)/256, 256>>>(x);

    for(int li=0; li<4; li++){
        int C = Cin[li], O = Oo[li];
        k_xx<<<(BB*NN + 255)/256, 256>>>(C);
        k_gemm<false,1><<<dim3(NN/128, NN/128, BB), 256>>>(
            NN, NN, C, xT, C, (size_t)NN*C, xT, C, (size_t)NN*C, dist, (size_t)NN*NN, xxp);
        k_topk<<<dim3(NN, BB), 256>>>();
        // fused edge GEMM + k-reduce (160-wide tiles = 8 points)
        int C2 = 2*C;
        k_egemm<<<dim3(NN/8, (O+127)/128, BB), 256>>>(O, C2, Wec[li], xT, idxp, C);
        k_ec_stats<<<O, 256>>>(O);
        k_ec_apply<<<dim3(O, BB), 256>>>(O, c0[li], xT, gec[li], bec[li]);
    }

    k_gemm<true,0><<<dim3(NN/128, 1024/128, BB), 256>>>(
        1024, NN, 512, W5, 512, 0, xcat, NN, (size_t)512*NN, h5, (size_t)1024*NN, nullptr);
    k_conv_stats<<<1024, 256>>>(h5, 1024);
    k_gmax<<<dim3(1024, BB), 256>>>(g5v, b5v);
    k_lf<<<1, 512>>>(l, W206, g206, b206);
    k_bias207<<<BB, 256>>>(W207);
    k_gemm<true,2><<<dim3(NN/128, 2, BB), 256>>>(
        256, NN, 512, W207 + 1088, 1600, 0, xcat, NN, (size_t)512*NN, hb1, (size_t)256*NN, b207p);
    k_conv_stats<<<256, 256>>>(hb1, 256);
    k_conv_apply<<<dim3(256, BB), 256>>>(hb1, 256, g207, b207);
    k_gemm<true,0><<<dim3(NN/128, 2, BB), 256>>>(
        256, NN, 256, W208, 256, 0, hb1, NN, (size_t)256*NN, hb2, (size_t)256*NN, nullptr);
    k_conv_stats<<<256, 256>>>(hb2, 256);
    k_conv_apply<<<dim3(256, BB), 256>>>(hb2, 256, g208, b208);
    k_gemm<true,0><<<dim3(NN/128, 1, BB), 256>>>(
        128, NN, 256, W209, 256, 0, hb2, NN, (size_t)256*NN, hb3, (size_t)128*NN, nullptr);
    k_conv_stats<<<128, 256>>>(hb3, 128);
    k_conv_apply<<<dim3(128, BB), 256>>>(hb3, 128, g209, b209);
    k_gemm<true,0><<<dim3(NN/128, 1, BB), 256>>>(
        50, NN, 128, W2010, 128, 0, hb3, NN, (size_t)128*NN, (float*)d_out, (size_t)50*NN, nullptr);
}

// round 9
// speedup vs baseline: 1.2896x; 1.0521x over previous
#include <cuda_runtime.h>
#include <cstdlib>
#include <cfloat>

#define BB 8
#define NN 2048
#define KNB 20
#define NEGS 0.2f
#define EPSB 1e-5f

__attribute__((constructor)) static void _eager_load(){ setenv("CUDA_MODULE_LOADING","EAGER",0); }

// ------------------------- scratch (device globals) -------------------------
__device__ float g_xT  [(size_t)BB*NN*256];
__device__ float g_xx  [BB*NN];
__device__ float g_dist[(size_t)BB*NN*NN];
__device__ int   g_idx [(size_t)BB*NN*KNB];
__device__ float g_kmax[(size_t)BB*256*NN];
__device__ float g_kmin[(size_t)BB*256*NN];
__device__ float g_ksum[(size_t)BB*256*NN];
__device__ float g_ksq [(size_t)BB*256*NN];
__device__ float g_xcat[(size_t)BB*512*NN];
__device__ float g_h5  [(size_t)BB*1024*NN];
__device__ float g_hb1 [(size_t)BB*256*NN];
__device__ float g_hb2 [(size_t)BB*256*NN];
__device__ float g_hb3 [(size_t)BB*128*NN];
__device__ float g_glob[BB*1088];
__device__ float g_b207[BB*256];
__device__ float g_prm [2048];

// ------------------------- generic fp32 GEMM (pipelined, bit-identical math) --
// Single accumulator per output, FMA, k strictly ascending.
// MODE 0: plain   MODE 2: row bias
template<bool BT, int MODE>
__global__ void __launch_bounds__(256,2) k_gemm(
    int M, int Ncol, int Kd,
    const float* __restrict__ A, int lda, size_t asb,
    const float* __restrict__ Bp, int ldb, size_t bsb,
    float* __restrict__ Cp, size_t csb,
    const float* __restrict__ e0)
{
    const int BM=128, BN=128, BK=16;
    __shared__ float As[2][BK][BM+4];
    __shared__ float Bs[2][BK][BN+4];
    int b  = blockIdx.z;
    int m0 = blockIdx.y*BM, n0 = blockIdx.x*BN;
    A  += (size_t)b*asb;
    Bp += (size_t)b*bsb;
    Cp += (size_t)b*csb;
    int tid = threadIdx.x;
    int tx = tid%16, ty = tid/16;

    float acc[8][8];
    #pragma unroll
    for(int i=0;i<8;i++)
        #pragma unroll
        for(int j=0;j<8;j++) acc[i][j]=0.f;

    float ra[8], rb[8];

    auto fetchA = [&](int k0){
        #pragma unroll
        for(int i=0;i<8;i++){
            int e = tid + 256*i;
            int kk=e%BK, mm=e/BK;
            int gm=m0+mm, gk=k0+kk;
            ra[i] = (gm<M && gk<Kd) ? A[(size_t)gm*lda+gk] : 0.f;
        }
    };
    auto fetchB = [&](int k0){
        if(!BT){
            #pragma unroll
            for(int i=0;i<8;i++){
                int e = tid + 256*i;
                int kk=e%BK, nn=e/BK;
                int gn=n0+nn, gk=k0+kk;
                rb[i] = (gn<Ncol && gk<Kd) ? Bp[(size_t)gn*ldb+gk] : 0.f;
            }
        } else {
            #pragma unroll
            for(int i=0;i<8;i++){
                int e = tid + 256*i;
                int nn=e%BN, kk=e/BN;
                int gn=n0+nn, gk=k0+kk;
                rb[i] = (gn<Ncol && gk<Kd) ? Bp[(size_t)gk*ldb+gn] : 0.f;
            }
        }
    };
    auto store = [&](int buf){
        #pragma unroll
        for(int i=0;i<8;i++){
            int e = tid + 256*i;
            As[buf][e%BK][e/BK] = ra[i];
        }
        if(!BT){
            #pragma unroll
            for(int i=0;i<8;i++){
                int e = tid + 256*i;
                Bs[buf][e%BK][e/BK] = rb[i];
            }
        } else {
            #pragma unroll
            for(int i=0;i<8;i++){
                int e = tid + 256*i;
                Bs[buf][e/BN][e%BN] = rb[i];
            }
        }
    };

    int nk = (Kd + BK - 1)/BK;
    fetchA(0); fetchB(0);
    store(0);
    __syncthreads();

    for(int t=0;t<nk;t++){
        int cur = t&1;
        if(t+1<nk){ fetchA((t+1)*BK); fetchB((t+1)*BK); }
        #pragma unroll
        for(int kk=0;kk<BK;kk++){
            float a8[8], b8[8];
            #pragma unroll
            for(int i=0;i<8;i++) a8[i]=As[cur][kk][ty*8+i];
            #pragma unroll
            for(int j=0;j<8;j++) b8[j]=Bs[cur][kk][tx*8+j];
            #pragma unroll
            for(int i=0;i<8;i++)
                #pragma unroll
                for(int j=0;j<8;j++) acc[i][j] = __fmaf_rn(a8[i], b8[j], acc[i][j]);
        }
        if(t+1<nk){
            __syncthreads();
            store(1-cur);
            __syncthreads();
        }
    }

    #pragma unroll
    for(int i=0;i<8;i++){
        int gm = m0+ty*8+i;
        if(gm>=M) continue;
        #pragma unroll
        for(int j=0;j<8;j++){
            int gn = n0+tx*8+j;
            if(gn>=Ncol) continue;
            float v = acc[i][j];
            if(MODE==2) v = __fadd_rn(v, e0[(size_t)b*M+gm]);
            Cp[(size_t)gm*Ncol + gn] = v;
        }
    }
}

// -------- symmetric dist GEMM: upper-triangle blocks compute, mirror store ---
// dist[m][n] = 2*(x_m . x_n) - xx[m] - xx[n].  Mirrors are bit-identical
// (fma operand commutativity + same ascending-k order); diagonal tiles cover
// both orders directly so they skip the mirror.
__global__ void __launch_bounds__(256,2) k_dgemm(
    int Kd, const float* __restrict__ Xp, const float* __restrict__ e0)
{
    const int BK=16;
    if(blockIdx.x < blockIdx.y) return;
    __shared__ float pool[8448];   // As[2][16][132] | Bs[2][16][132]; reused as ts[32][132]
    #define ASM(buf,kk,mm) pool[(buf)*2112 + (kk)*132 + (mm)]
    #define BSM(buf,kk,nn) pool[4224 + (buf)*2112 + (kk)*132 + (nn)]
    int b  = blockIdx.z;
    int m0 = blockIdx.y*128, n0 = blockIdx.x*128;
    const float* A = Xp + (size_t)b*NN*Kd;
    float* Cp = g_dist + (size_t)b*NN*NN;
    const float* xxr = e0 + (size_t)b*NN;
    int tid = threadIdx.x;
    int tx = tid%16, ty = tid/16;

    float acc[8][8];
    #pragma unroll
    for(int i=0;i<8;i++)
        #pragma unroll
        for(int j=0;j<8;j++) acc[i][j]=0.f;

    float ra[8], rb[8];
    auto fetchA = [&](int k0){
        #pragma unroll
        for(int i=0;i<8;i++){
            int e = tid + 256*i;
            int kk=e&15, mm=e>>4;
            int gk=k0+kk;
            ra[i] = (gk<Kd) ? A[(size_t)(m0+mm)*Kd+gk] : 0.f;
        }
    };
    auto fetchB = [&](int k0){
        #pragma unroll
        for(int i=0;i<8;i++){
            int e = tid + 256*i;
            int kk=e&15, nn=e>>4;
            int gk=k0+kk;
            rb[i] = (gk<Kd) ? A[(size_t)(n0+nn)*Kd+gk] : 0.f;
        }
    };
    auto store = [&](int buf){
        #pragma unroll
        for(int i=0;i<8;i++){
            int e = tid + 256*i;
            ASM(buf, e&15, e>>4) = ra[i];
        }
        #pragma unroll
        for(int i=0;i<8;i++){
            int e = tid + 256*i;
            BSM(buf, e&15, e>>4) = rb[i];
        }
    };

    int nk = (Kd + BK - 1)/BK;
    fetchA(0); fetchB(0);
    store(0);
    __syncthreads();
    for(int t=0;t<nk;t++){
        int cur = t&1;
        if(t+1<nk){ fetchA((t+1)*BK); fetchB((t+1)*BK); }
        #pragma unroll
        for(int kk=0;kk<BK;kk++){
            float a8[8], b8[8];
            #pragma unroll
            for(int i=0;i<8;i++) a8[i]=ASM(cur,kk,ty*8+i);
            #pragma unroll
            for(int j=0;j<8;j++) b8[j]=BSM(cur,kk,tx*8+j);
            #pragma unroll
            for(int i=0;i<8;i++)
                #pragma unroll
                for(int j=0;j<8;j++) acc[i][j] = __fmaf_rn(a8[i], b8[j], acc[i][j]);
        }
        if(t+1<nk){
            __syncthreads();
            store(1-cur);
            __syncthreads();
        }
    }

    // epilogue: direct (coalesced) store; keep v in acc for the mirror
    #pragma unroll
    for(int i=0;i<8;i++){
        int gm = m0+ty*8+i;
        float xm = xxr[gm];
        #pragma unroll
        for(int j=0;j<8;j++){
            int gn = n0+tx*8+j;
            float v = __fsub_rn(__fsub_rn(__fmul_rn(2.0f, acc[i][j]), xm), xxr[gn]);
            acc[i][j] = v;
            Cp[(size_t)gm*NN + gn] = v;
        }
    }
    if(blockIdx.x > blockIdx.y){
        // mirror via smem transpose, 32-row chunks, coalesced stores
        for(int c=0;c<4;c++){
            __syncthreads();
            if((tx>>2)==c){
                int tl = tx&3;
                #pragma unroll
                for(int i=0;i<8;i++)
                    #pragma unroll
                    for(int j=0;j<8;j++)
                        pool[(tl*8+j)*132 + ty*8+i] = acc[i][j];
            }
            __syncthreads();
            #pragma unroll
            for(int q=0;q<16;q++){
                int e = tid + 256*q;
                int rr=e>>7, cc=e&127;
                Cp[(size_t)(n0+c*32+rr)*NN + m0+cc] = pool[rr*132+cc];
            }
        }
    }
    #undef ASM
    #undef BSM
}

// ------------- fused edge-conv GEMM + k-reduce (BN = 160 = 8 points x 20) ----
__global__ void __launch_bounds__(256,2) k_egemm(
    int M, int Kd,                       // M = O, Kd = 2C
    const float* __restrict__ A,         // W  [O, 2C]
    const float* __restrict__ xTp,       // [B, N, C]
    const int*   __restrict__ idxp,      // [B, N, K]
    int Cc)
{
    const int BM=128, BN=160, BK=16;
    __shared__ float As[2][BK][BM+4];
    __shared__ float Bs[2][BK][BN+4];
    __shared__ int   s_m [BN];
    __shared__ int   s_pt[BN];
    int b  = blockIdx.z;
    int m0 = blockIdx.y*BM;
    int p0 = blockIdx.x*8;
    xTp  += (size_t)b*NN*Cc;
    idxp += (size_t)b*NN*KNB;
    int tid = threadIdx.x;
    int tx = tid%16, ty = tid/16;

    if(tid < BN){
        int pt = tid/KNB;
        int kq = tid - pt*KNB;
        s_pt[tid] = pt;
        s_m [tid] = idxp[(size_t)(p0+pt)*KNB + kq];
    }
    __syncthreads();

    float acc[8][10];
    #pragma unroll
    for(int i=0;i<8;i++)
        #pragma unroll
        for(int j=0;j<10;j++) acc[i][j]=0.f;

    float ra[8], rb[10];

    auto fetchA = [&](int k0){
        #pragma unroll
        for(int i=0;i<8;i++){
            int e = tid + 256*i;
            int kk=e&15, mm=e>>4;
            int gm=m0+mm, gk=k0+kk;
            ra[i] = (gm<M && gk<Kd) ? A[(size_t)gm*Kd+gk] : 0.f;
        }
    };
    auto fetchB = [&](int k0){
        #pragma unroll
        for(int i=0;i<10;i++){
            int e = tid + 256*i;
            int kk=e&15, nn=e>>4;
            int gk=k0+kk;
            float val = 0.f;
            if(gk<Kd){
                int cc = (gk<Cc) ? gk : gk-Cc;
                float ctr = xTp[(size_t)(p0+s_pt[nn])*Cc + cc];
                if(gk<Cc){
                    float nb = xTp[(size_t)s_m[nn]*Cc + cc];
                    val = __fsub_rn(nb, ctr);
                } else val = ctr;
            }
            rb[i] = val;
        }
    };
    auto store = [&](int buf){
        #pragma unroll
        for(int i=0;i<8;i++){
            int e = tid + 256*i;
            As[buf][e&15][e>>4] = ra[i];
        }
        #pragma unroll
        for(int i=0;i<10;i++){
            int e = tid + 256*i;
            Bs[buf][e&15][e>>4] = rb[i];
        }
    };

    int nk = (Kd + BK - 1)/BK;
    fetchA(0); fetchB(0);
    store(0);
    __syncthreads();

    for(int t=0;t<nk;t++){
        int cur = t&1;
        if(t+1<nk){ fetchA((t+1)*BK); fetchB((t+1)*BK); }
        #pragma unroll
        for(int kk=0;kk<BK;kk++){
            float a8[8], b10[10];
            #pragma unroll
            for(int i=0;i<8;i++) a8[i]=As[cur][kk][ty*8+i];
            #pragma unroll
            for(int j=0;j<10;j++) b10[j]=Bs[cur][kk][tx*10+j];
            #pragma unroll
            for(int i=0;i<8;i++)
                #pragma unroll
                for(int j=0;j<10;j++) acc[i][j] = __fmaf_rn(a8[i], b10[j], acc[i][j]);
        }
        if(t+1<nk){
            __syncthreads();
            store(1-cur);
            __syncthreads();
        }
    }

    // Epilogue: strict ascending-k reduction (bit-identical to separate kreduce)
    int O = M;
    #pragma unroll
    for(int i=0;i<8;i++){
        float mx=-FLT_MAX, mn=FLT_MAX, sm=0.f, sq=0.f;
        #pragma unroll
        for(int j=0;j<10;j++){
            float h = acc[i][j];
            mx = fmaxf(mx,h); mn = fminf(mn,h);
            sm = __fadd_rn(sm,h); sq = __fmaf_rn(h,h,sq);
        }
        #pragma unroll
        for(int j=0;j<10;j++){
            float h = __shfl_xor_sync(0xffffffffu, acc[i][j], 1);
            mx = fmaxf(mx,h); mn = fminf(mn,h);
            sm = __fadd_rn(sm,h); sq = __fmaf_rn(h,h,sq);
        }
        int gm = m0 + ty*8 + i;
        if(((tx&1)==0) && gm<M){
            int point = p0 + (tx>>1);
            size_t base = ((size_t)b*O + gm)*NN + point;
            g_kmax[base]=mx; g_kmin[base]=mn; g_ksum[base]=sm; g_ksq[base]=sq;
        }
    }
}

// ------------------------- small kernels -------------------------

__global__ void k_tin(const float* __restrict__ x){
    int i = blockIdx.x*blockDim.x + threadIdx.x;
    if(i >= BB*NN*3) return;
    int c = i%3; int n = (i/3)%NN; int b = i/(3*NN);
    g_xT[i] = x[((size_t)b*3 + c)*NN + n];
}

__global__ void k_xx(int C){
    int p = blockIdx.x*blockDim.x + threadIdx.x;
    if(p >= BB*NN) return;
    const float* v = g_xT + (size_t)p*C;
    float s = 0.f;
    for(int c=0;c<C;c++) s = __fadd_rn(s, __fmul_rn(v[c], v[c]));
    g_xx[p] = s;
}

// Bucket-select + adaptive bitonic top-K (largest, min-index tiebreak; exact).
__global__ void __launch_bounds__(256) k_topk(){
    int n = blockIdx.x, bq = blockIdx.y;
    const float* row = g_dist + ((size_t)bq*NN + n)*NN;
    int tid = threadIdx.x, lane = tid&31, w = tid>>5;
    int base = tid*8;
    float v[8];
    {
        const float4* r4 = (const float4*)(row + base);
        float4 q0 = r4[0], q1 = r4[1];
        v[0]=q0.x; v[1]=q0.y; v[2]=q0.z; v[3]=q0.w;
        v[4]=q1.x; v[5]=q1.y; v[6]=q1.z; v[7]=q1.w;
    }
    __shared__ float swmx[8], swmn[8];
    __shared__ int hist8[8][256];
    __shared__ int hist[256];
    __shared__ unsigned long long cand[256];
    __shared__ int s_cnt, s_B, s_size;
    __shared__ float s_lo, s_hi;

    float mx=v[0], mn=v[0];
    #pragma unroll
    for(int t=1;t<8;t++){ mx=fmaxf(mx,v[t]); mn=fminf(mn,v[t]); }
    #pragma unroll
    for(int o=16;o;o>>=1){
        mx=fmaxf(mx,__shfl_xor_sync(0xffffffffu,mx,o));
        mn=fminf(mn,__shfl_xor_sync(0xffffffffu,mn,o));
    }
    if(lane==0){ swmx[w]=mx; swmn[w]=mn; }
    #pragma unroll
    for(int q=0;q<8;q++) hist8[q][tid]=0;
    __syncthreads();
    if(tid==0){
        float hx=swmx[0], hn=swmn[0];
        #pragma unroll
        for(int q=1;q<8;q++){ hx=fmaxf(hx,swmx[q]); hn=fminf(hn,swmn[q]); }
        s_lo=hn; s_hi=hx; s_cnt=0;
    }
    __syncthreads();
    float lo=s_lo, hi=s_hi;
    float scale = (hi>lo) ? 255.0f/(hi-lo) : 0.0f;
    int bk[8];
    #pragma unroll
    for(int t=0;t<8;t++){
        int bb = (int)((v[t]-lo)*scale);
        bb = max(0, min(255, bb));
        bk[t]=bb;
        atomicAdd(&hist8[w][bb],1);   // per-warp: 8x less contention
    }
    __syncthreads();
    {
        int hsum = 0;
        #pragma unroll
        for(int q=0;q<8;q++) hsum += hist8[q][tid];
        hist[tid] = hsum;
    }
    __syncthreads();
    if(w==0){
        int cs = 0;
        #pragma unroll
        for(int t=0;t<8;t++) cs += hist[lane*8+t];
        int rs = cs;
        #pragma unroll
        for(int o=1;o<32;o<<=1){
            int t2 = __shfl_down_sync(0xffffffffu, rs, o);
            if(lane+o<32) rs += t2;
        }
        int sufx = rs - cs;
        if(rs >= KNB && sufx < KNB){
            int run = sufx, Bv = lane*8;
            for(int j=7;j>=0;j--){
                run += hist[lane*8+j];
                if(run >= KNB){ Bv = lane*8+j; break; }
            }
            s_B = Bv;
        }
    }
    __syncthreads();
    int B = s_B;
    #pragma unroll
    for(int t=0;t<8;t++){
        if(bk[t] >= B){
            int pos = atomicAdd(&s_cnt,1);
            if(pos<256){
                unsigned int u = __float_as_uint(v[t]);
                u = (u & 0x80000000u) ? ~u : (u | 0x80000000u);
                cand[pos] = ((unsigned long long)u<<32) | (unsigned int)(~(base+t));
            }
        }
    }
    __syncthreads();
    int cnt = s_cnt;
    if(cnt<=256){
        if(tid==0){
            int sz = 32;
            while(sz < cnt) sz <<= 1;
            s_size = sz;
        }
        __syncthreads();
        int sz = s_size;
        if(tid<sz && tid>=cnt) cand[tid]=0ull;   // padding sorts below all real keys
        __syncthreads();
        for(int k=2;k<=sz;k<<=1){
            for(int j=k>>1;j>0;j>>=1){
                int ixj = tid ^ j;
                if(ixj > tid && ixj < sz && tid < sz){
                    bool up = ((tid & k) == 0);
                    unsigned long long a=cand[tid], c=cand[ixj];
                    if( (a > c) == up ){ cand[tid]=c; cand[ixj]=a; }
                }
                __syncthreads();
            }
        }
        if(tid<KNB)
            g_idx[((size_t)bq*NN+n)*KNB + tid] = (int)(~(unsigned int)cand[sz-1-tid]);
    } else {
        if(tid==0){
            float* rw = g_dist + ((size_t)bq*NN + n)*NN;
            for(int j=0;j<KNB;j++){
                float bvv=-FLT_MAX; int bii=0;
                for(int i=0;i<NN;i++){ float vv=rw[i]; if(vv>bvv){bvv=vv;bii=i;} }
                g_idx[((size_t)bq*NN+n)*KNB + j]=bii;
                rw[bii]=-FLT_MAX;
            }
        }
    }
}

__global__ void k_ec_stats(int O){
    int o = blockIdx.x, tid = threadIdx.x;
    double s=0.0, ss=0.0;
    for(int b=0;b<BB;b++){
        size_t base = ((size_t)b*O + o)*NN;
        for(int n=tid;n<NN;n+=256){ s += g_ksum[base+n]; ss += g_ksq[base+n]; }
    }
    __shared__ double rs[256], rq[256];
    rs[tid]=s; rq[tid]=ss; __syncthreads();
    for(int st=128;st;st>>=1){ if(tid<st){ rs[tid]+=rs[tid+st]; rq[tid]+=rq[tid+st]; } __syncthreads(); }
    if(tid==0){
        double cnt = (double)BB*NN*KNB;
        double mean = rs[0]/cnt;
        double var  = rq[0]/cnt - mean*mean;
        g_prm[2*o]   = (float)mean;
        g_prm[2*o+1] = (float)var;
    }
}

__global__ void k_ec_apply(int O, int c0, float* __restrict__ xTout,
                           const float* __restrict__ gw, const float* __restrict__ bw){
    int o = blockIdx.x, b = blockIdx.y;
    float m = g_prm[2*o], vv = g_prm[2*o+1];
    float gg = gw[o], bb = bw[o];
    float sd = __fsqrt_rn(__fadd_rn(vv, EPSB));
    const float* src = (gg>=0.f ? g_kmax : g_kmin) + ((size_t)b*O + o)*NN;
    float* xc = g_xcat + ((size_t)b*512 + c0 + o)*NN;
    for(int n=threadIdx.x;n<NN;n+=blockDim.x){
        float y = __fadd_rn(__fmul_rn(__fdiv_rn(__fsub_rn(src[n], m), sd), gg), bb);
        y = (y>=0.f) ? y : __fmul_rn(NEGS, y);
        xc[n] = y;
        xTout[((size_t)b*NN + n)*O + o] = y;
    }
}

__global__ void k_conv_stats(const float* __restrict__ h, int O){
    int o = blockIdx.x, tid = threadIdx.x;
    double s=0.0, ss=0.0;
    for(int b=0;b<BB;b++){
        size_t base = ((size_t)b*O + o)*NN;
        for(int n=tid;n<NN;n+=256){ float v=h[base+n]; s += v; ss += (double)v*v; }
    }
    __shared__ double rs[256], rq[256];
    rs[tid]=s; rq[tid]=ss; __syncthreads();
    for(int st=128;st;st>>=1){ if(tid<st){ rs[tid]+=rs[tid+st]; rq[tid]+=rq[tid+st]; } __syncthreads(); }
    if(tid==0){
        double cnt = (double)BB*NN;
        double mean = rs[0]/cnt;
        double var  = rq[0]/cnt - mean*mean;
        g_prm[2*o]   = (float)mean;
        g_prm[2*o+1] = (float)var;
    }
}

__global__ void k_conv_apply(float* __restrict__ h, int O,
                             const float* __restrict__ gw, const float* __restrict__ bw){
    int o = blockIdx.x, b = blockIdx.y;
    float m = g_prm[2*o], vv = g_prm[2*o+1];
    float gg = gw[o], bb = bw[o];
    float sd = __fsqrt_rn(__fadd_rn(vv, EPSB));
    float* p = h + ((size_t)b*O + o)*NN;
    for(int n=threadIdx.x;n<NN;n+=blockDim.x){
        float y = __fadd_rn(__fmul_rn(__fdiv_rn(__fsub_rn(p[n], m), sd), gg), bb);
        p[n] = (y>=0.f) ? y : __fmul_rn(NEGS, y);
    }
}

__global__ void k_gmax(const float* __restrict__ gw, const float* __restrict__ bw){
    int o = blockIdx.x, b = blockIdx.y, tid = threadIdx.x;
    float gg = gw[o];
    const float* p = g_h5 + ((size_t)b*1024 + o)*NN;
    float m = -FLT_MAX, mn = FLT_MAX;
    for(int n=tid;n<NN;n+=256){
        float v = p[n];
        m = fmaxf(m, v); mn = fminf(mn, v);
    }
    __shared__ float r[256], r2[256];
    r[tid]=m; r2[tid]=mn; __syncthreads();
    for(int st=128;st;st>>=1){
        if(tid<st){ r[tid]=fmaxf(r[tid], r[tid+st]); r2[tid]=fminf(r2[tid], r2[tid+st]); }
        __syncthreads();
    }
    if(tid==0){
        float src = (gg>=0.f) ? r[0] : r2[0];
        float mm = g_prm[2*o], vv = g_prm[2*o+1];
        float sd = __fsqrt_rn(__fadd_rn(vv, EPSB));
        float y = __fadd_rn(__fmul_rn(__fdiv_rn(__fsub_rn(src, mm), sd), gg), bw[o]);
        y = (y>=0.f) ? y : __fmul_rn(NEGS, y);
        g_glob[b*1088 + o] = y;
    }
}

__global__ void k_lf(const float* __restrict__ l, const float* __restrict__ W,
                     const float* __restrict__ gw, const float* __restrict__ bw){
    int tid = threadIdx.x;
    int o = tid & 63, b = tid >> 6;
    __shared__ float hs[8][64];
    __shared__ float pm[64], pv[64];
    float s = 0.f;
    #pragma unroll
    for(int c=0;c<16;c++) s = __fmaf_rn(W[o*16 + c], l[b*16 + c], s);
    hs[b][o] = s;
    __syncthreads();
    if(tid < 64){
        float m = 0.f;
        #pragma unroll
        for(int q=0;q<8;q++) m = __fadd_rn(m, hs[q][tid]);
        m = __fdiv_rn(m, 8.f);
        float v = 0.f;
        #pragma unroll
        for(int q=0;q<8;q++){ float d = __fsub_rn(hs[q][tid], m); v = __fmaf_rn(d, d, v); }
        v = __fdiv_rn(v, 8.f);
        pm[tid] = m; pv[tid] = v;
    }
    __syncthreads();
    float sd = __fsqrt_rn(__fadd_rn(pv[o], EPSB));
    float y = __fadd_rn(__fmul_rn(__fdiv_rn(__fsub_rn(hs[b][o], pm[o]), sd), gw[o]), bw[o]);
    y = (y>=0.f) ? y : __fmul_rn(NEGS, y);
    g_glob[b*1088 + 1024 + o] = y;
}

__global__ void k_bias207(const float* __restrict__ W207){
    int b = blockIdx.x;
    __shared__ float gl[1088];
    for(int i=threadIdx.x;i<1088;i+=256) gl[i] = g_glob[b*1088 + i];
    __syncthreads();
    int o = threadIdx.x;
    float s = 0.f;
    for(int c=0;c<1088;c++) s = __fmaf_rn(W207[(size_t)o*1600 + c], gl[c], s);
    g_b207[b*256 + o] = s;
}

// ------------------------- launcher -------------------------
extern "C" void kernel_launch(void* const* d_in, const int* in_sizes, int n_in,
                              void* d_out, int out_size){
    (void)in_sizes; (void)n_in; (void)out_size;
    const float* x    = (const float*)d_in[0];
    const float* l    = (const float*)d_in[1];
    const float* Wec[4] = {(const float*)d_in[2],(const float*)d_in[5],(const float*)d_in[8],(const float*)d_in[11]};
    const float* gec[4] = {(const float*)d_in[3],(const float*)d_in[6],(const float*)d_in[9],(const float*)d_in[12]};
    const float* bec[4] = {(const float*)d_in[4],(const float*)d_in[7],(const float*)d_in[10],(const float*)d_in[13]};
    const float* W5   = (const float*)d_in[14]; const float* g5v  = (const float*)d_in[15]; const float* b5v  = (const float*)d_in[16];
    const float* W206 = (const float*)d_in[17]; const float* g206 = (const float*)d_in[18]; const float* b206 = (const float*)d_in[19];
    const float* W207 = (const float*)d_in[20]; const float* g207 = (const float*)d_in[21]; const float* b207 = (const float*)d_in[22];
    const float* W208 = (const float*)d_in[23]; const float* g208 = (const float*)d_in[24]; const float* b208 = (const float*)d_in[25];
    const float* W209 = (const float*)d_in[26]; const float* g209 = (const float*)d_in[27]; const float* b209 = (const float*)d_in[28];
    const float* W2010= (const float*)d_in[29];

    float *xT,*xxp,*xcat,*h5,*hb1,*hb2,*hb3,*b207p;
    int *idxp;
    cudaGetSymbolAddress((void**)&xT,   g_xT);
    cudaGetSymbolAddress((void**)&xxp,  g_xx);
    cudaGetSymbolAddress((void**)&idxp, g_idx);
    cudaGetSymbolAddress((void**)&xcat, g_xcat);
    cudaGetSymbolAddress((void**)&h5,   g_h5);
    cudaGetSymbolAddress((void**)&hb1,  g_hb1);
    cudaGetSymbolAddress((void**)&hb2,  g_hb2);
    cudaGetSymbolAddress((void**)&hb3,  g_hb3);
    cudaGetSymbolAddress((void**)&b207p,g_b207);

    const int Cin[4] = {3,64,64,128};
    const int Oo [4] = {64,64,128,256};
    const int c0 [4] = {0,64,128,256};

    k_tin<<<(BB*NN*3 + 255)/256, 256>>>(x);

    for(int li=0; li<4; li++){
        int C = Cin[li], O = Oo[li];
        k_xx<<<(BB*NN + 255)/256, 256>>>(C);
        k_dgemm<<<dim3(NN/128, NN/128, BB), 256>>>(C, xT, xxp);
        k_topk<<<dim3(NN, BB), 256>>>();
        int C2 = 2*C;
        k_egemm<<<dim3(NN/8, (O+127)/128, BB), 256>>>(O, C2, Wec[li], xT, idxp, C);
        k_ec_stats<<<O, 256>>>(O);
        k_ec_apply<<<dim3(O, BB), 256>>>(O, c0[li], xT, gec[li], bec[li]);
    }

    k_gemm<true,0><<<dim3(NN/128, 1024/128, BB), 256>>>(
        1024, NN, 512, W5, 512, 0, xcat, NN, (size_t)512*NN, h5, (size_t)1024*NN, nullptr);
    k_conv_stats<<<1024, 256>>>(h5, 1024);
    k_gmax<<<dim3(1024, BB), 256>>>(g5v, b5v);
    k_lf<<<1, 512>>>(l, W206, g206, b206);
    k_bias207<<<BB, 256>>>(W207);
    k_gemm<true,2><<<dim3(NN/128, 2, BB), 256>>>(
        256, NN, 512, W207 + 1088, 1600, 0, xcat, NN, (size_t)512*NN, hb1, (size_t)256*NN, b207p);
    k_conv_stats<<<256, 256>>>(hb1, 256);
    k_conv_apply<<<dim3(256, BB), 256>>>(hb1, 256, g207, b207);
    k_gemm<true,0><<<dim3(NN/128, 2, BB), 256>>>(
        256, NN, 256, W208, 256, 0, hb1, NN, (size_t)256*NN, hb2, (size_t)256*NN, nullptr);
    k_conv_stats<<<256, 256>>>(hb2, 256);
    k_conv_apply<<<dim3(256, BB), 256>>>(hb2, 256, g208, b208);
    k_gemm<true,0><<<dim3(NN/128, 1, BB), 256>>>(
        128, NN, 256, W209, 256, 0, hb2, NN, (size_t)256*NN, hb3, (size_t)128*NN, nullptr);
    k_conv_stats<<<128, 256>>>(hb3, 128);
    k_conv_apply<<<dim3(128, BB), 256>>>(hb3, 128, g209, b209);
    k_gemm<true,0><<<dim3(NN/128, 1, BB), 256>>>(
        50, NN, 128, W2010, 128, 0, hb3, NN, (size_t)128*NN, (float*)d_out, (size_t)50*NN, nullptr);
}

// round 10
// speedup vs baseline: 1.3131x; 1.0182x over previous
#include <cuda_runtime.h>
#include <cstdlib>
#include <cfloat>

#define BB 8
#define NN 2048
#define KNB 20
#define NEGS 0.2f
#define EPSB 1e-5f

__attribute__((constructor)) static void _eager_load(){ setenv("CUDA_MODULE_LOADING","EAGER",0); }

// ------------------------- scratch (device globals) -------------------------
__device__ float g_xT  [(size_t)BB*NN*256];
__device__ float g_xx  [BB*NN];
__device__ float g_dist[(size_t)BB*NN*NN];
__device__ int   g_idx [(size_t)BB*NN*KNB];
__device__ float g_kmax[(size_t)BB*256*NN];
__device__ float g_kmin[(size_t)BB*256*NN];
__device__ float g_ksum[(size_t)BB*256*NN];
__device__ float g_ksq [(size_t)BB*256*NN];
__device__ float g_xcat[(size_t)BB*512*NN];
__device__ float g_h5  [(size_t)BB*1024*NN];
__device__ float g_hb1 [(size_t)BB*256*NN];
__device__ float g_hb2 [(size_t)BB*256*NN];
__device__ float g_hb3 [(size_t)BB*128*NN];
__device__ float g_glob[BB*1088];
__device__ float g_b207[BB*256];
__device__ float g_prm [2048];

// ------------------------- generic fp32 GEMM (pipelined, bit-identical math) --
template<bool BT, int MODE>
__global__ void __launch_bounds__(256,2) k_gemm(
    int M, int Ncol, int Kd,
    const float* __restrict__ A, int lda, size_t asb,
    const float* __restrict__ Bp, int ldb, size_t bsb,
    float* __restrict__ Cp, size_t csb,
    const float* __restrict__ e0)
{
    const int BM=128, BN=128, BK=16;
    __shared__ float As[2][BK][BM+4];
    __shared__ float Bs[2][BK][BN+4];
    int b  = blockIdx.z;
    int m0 = blockIdx.y*BM, n0 = blockIdx.x*BN;
    A  += (size_t)b*asb;
    Bp += (size_t)b*bsb;
    Cp += (size_t)b*csb;
    int tid = threadIdx.x;
    int tx = tid%16, ty = tid/16;

    float acc[8][8];
    #pragma unroll
    for(int i=0;i<8;i++)
        #pragma unroll
        for(int j=0;j<8;j++) acc[i][j]=0.f;

    float ra[8], rb[8];

    auto fetchA = [&](int k0){
        #pragma unroll
        for(int i=0;i<8;i++){
            int e = tid + 256*i;
            int kk=e%BK, mm=e/BK;
            int gm=m0+mm, gk=k0+kk;
            ra[i] = (gm<M && gk<Kd) ? A[(size_t)gm*lda+gk] : 0.f;
        }
    };
    auto fetchB = [&](int k0){
        if(!BT){
            #pragma unroll
            for(int i=0;i<8;i++){
                int e = tid + 256*i;
                int kk=e%BK, nn=e/BK;
                int gn=n0+nn, gk=k0+kk;
                rb[i] = (gn<Ncol && gk<Kd) ? Bp[(size_t)gn*ldb+gk] : 0.f;
            }
        } else {
            #pragma unroll
            for(int i=0;i<8;i++){
                int e = tid + 256*i;
                int nn=e%BN, kk=e/BN;
                int gn=n0+nn, gk=k0+kk;
                rb[i] = (gn<Ncol && gk<Kd) ? Bp[(size_t)gk*ldb+gn] : 0.f;
            }
        }
    };
    auto store = [&](int buf){
        #pragma unroll
        for(int i=0;i<8;i++){
            int e = tid + 256*i;
            As[buf][e%BK][e/BK] = ra[i];
        }
        if(!BT){
            #pragma unroll
            for(int i=0;i<8;i++){
                int e = tid + 256*i;
                Bs[buf][e%BK][e/BK] = rb[i];
            }
        } else {
            #pragma unroll
            for(int i=0;i<8;i++){
                int e = tid + 256*i;
                Bs[buf][e/BN][e%BN] = rb[i];
            }
        }
    };

    int nk = (Kd + BK - 1)/BK;
    fetchA(0); fetchB(0);
    store(0);
    __syncthreads();

    for(int t=0;t<nk;t++){
        int cur = t&1;
        if(t+1<nk){ fetchA((t+1)*BK); fetchB((t+1)*BK); }
        #pragma unroll
        for(int kk=0;kk<BK;kk++){
            float a8[8], b8[8];
            #pragma unroll
            for(int i=0;i<8;i++) a8[i]=As[cur][kk][ty*8+i];
            #pragma unroll
            for(int j=0;j<8;j++) b8[j]=Bs[cur][kk][tx*8+j];
            #pragma unroll
            for(int i=0;i<8;i++)
                #pragma unroll
                for(int j=0;j<8;j++) acc[i][j] = __fmaf_rn(a8[i], b8[j], acc[i][j]);
        }
        if(t+1<nk){
            __syncthreads();
            store(1-cur);
            __syncthreads();
        }
    }

    #pragma unroll
    for(int i=0;i<8;i++){
        int gm = m0+ty*8+i;
        if(gm>=M) continue;
        #pragma unroll
        for(int j=0;j<8;j++){
            int gn = n0+tx*8+j;
            if(gn>=Ncol) continue;
            float v = acc[i][j];
            if(MODE==2) v = __fadd_rn(v, e0[(size_t)b*M+gm]);
            Cp[(size_t)gm*Ncol + gn] = v;
        }
    }
}

// -------- symmetric dist GEMM (layers 2-4) --------------------------------
__global__ void __launch_bounds__(256,2) k_dgemm(
    int Kd, const float* __restrict__ Xp, const float* __restrict__ e0)
{
    const int BK=16;
    if(blockIdx.x < blockIdx.y) return;
    __shared__ float pool[8448];
    #define ASM(buf,kk,mm) pool[(buf)*2112 + (kk)*132 + (mm)]
    #define BSM(buf,kk,nn) pool[4224 + (buf)*2112 + (kk)*132 + (nn)]
    int b  = blockIdx.z;
    int m0 = blockIdx.y*128, n0 = blockIdx.x*128;
    const float* A = Xp + (size_t)b*NN*Kd;
    float* Cp = g_dist + (size_t)b*NN*NN;
    const float* xxr = e0 + (size_t)b*NN;
    int tid = threadIdx.x;
    int tx = tid%16, ty = tid/16;

    float acc[8][8];
    #pragma unroll
    for(int i=0;i<8;i++)
        #pragma unroll
        for(int j=0;j<8;j++) acc[i][j]=0.f;

    float ra[8], rb[8];
    auto fetchA = [&](int k0){
        #pragma unroll
        for(int i=0;i<8;i++){
            int e = tid + 256*i;
            int kk=e&15, mm=e>>4;
            int gk=k0+kk;
            ra[i] = (gk<Kd) ? A[(size_t)(m0+mm)*Kd+gk] : 0.f;
        }
    };
    auto fetchB = [&](int k0){
        #pragma unroll
        for(int i=0;i<8;i++){
            int e = tid + 256*i;
            int kk=e&15, nn=e>>4;
            int gk=k0+kk;
            rb[i] = (gk<Kd) ? A[(size_t)(n0+nn)*Kd+gk] : 0.f;
        }
    };
    auto store = [&](int buf){
        #pragma unroll
        for(int i=0;i<8;i++){
            int e = tid + 256*i;
            ASM(buf, e&15, e>>4) = ra[i];
        }
        #pragma unroll
        for(int i=0;i<8;i++){
            int e = tid + 256*i;
            BSM(buf, e&15, e>>4) = rb[i];
        }
    };

    int nk = (Kd + BK - 1)/BK;
    fetchA(0); fetchB(0);
    store(0);
    __syncthreads();
    for(int t=0;t<nk;t++){
        int cur = t&1;
        if(t+1<nk){ fetchA((t+1)*BK); fetchB((t+1)*BK); }
        #pragma unroll
        for(int kk=0;kk<BK;kk++){
            float a8[8], b8[8];
            #pragma unroll
            for(int i=0;i<8;i++) a8[i]=ASM(cur,kk,ty*8+i);
            #pragma unroll
            for(int j=0;j<8;j++) b8[j]=BSM(cur,kk,tx*8+j);
            #pragma unroll
            for(int i=0;i<8;i++)
                #pragma unroll
                for(int j=0;j<8;j++) acc[i][j] = __fmaf_rn(a8[i], b8[j], acc[i][j]);
        }
        if(t+1<nk){
            __syncthreads();
            store(1-cur);
            __syncthreads();
        }
    }

    #pragma unroll
    for(int i=0;i<8;i++){
        int gm = m0+ty*8+i;
        float xm = xxr[gm];
        #pragma unroll
        for(int j=0;j<8;j++){
            int gn = n0+tx*8+j;
            float v = __fsub_rn(__fsub_rn(__fmul_rn(2.0f, acc[i][j]), xm), xxr[gn]);
            acc[i][j] = v;
            Cp[(size_t)gm*NN + gn] = v;
        }
    }
    if(blockIdx.x > blockIdx.y){
        for(int c=0;c<4;c++){
            __syncthreads();
            if((tx>>2)==c){
                int tl = tx&3;
                #pragma unroll
                for(int i=0;i<8;i++)
                    #pragma unroll
                    for(int j=0;j<8;j++)
                        pool[(tl*8+j)*132 + ty*8+i] = acc[i][j];
            }
            __syncthreads();
            #pragma unroll
            for(int q=0;q<16;q++){
                int e = tid + 256*q;
                int rr=e>>7, cc=e&127;
                Cp[(size_t)(n0+c*32+rr)*NN + m0+cc] = pool[rr*132+cc];
            }
        }
    }
    #undef ASM
    #undef BSM
}

// ------------- fused edge-conv GEMM + k-reduce (BN = 160 = 8 points x 20) ----
__global__ void __launch_bounds__(256,2) k_egemm(
    int M, int Kd,
    const float* __restrict__ A,
    const float* __restrict__ xTp,
    const int*   __restrict__ idxp,
    int Cc)
{
    const int BM=128, BN=160, BK=16;
    __shared__ float As[2][BK][BM+4];
    __shared__ float Bs[2][BK][BN+4];
    __shared__ int   s_m [BN];
    __shared__ int   s_pt[BN];
    int b  = blockIdx.z;
    int m0 = blockIdx.y*BM;
    int p0 = blockIdx.x*8;
    xTp  += (size_t)b*NN*Cc;
    idxp += (size_t)b*NN*KNB;
    int tid = threadIdx.x;
    int tx = tid%16, ty = tid/16;

    if(tid < BN){
        int pt = tid/KNB;
        int kq = tid - pt*KNB;
        s_pt[tid] = pt;
        s_m [tid] = idxp[(size_t)(p0+pt)*KNB + kq];
    }
    __syncthreads();

    float acc[8][10];
    #pragma unroll
    for(int i=0;i<8;i++)
        #pragma unroll
        for(int j=0;j<10;j++) acc[i][j]=0.f;

    float ra[8], rb[10];

    auto fetchA = [&](int k0){
        #pragma unroll
        for(int i=0;i<8;i++){
            int e = tid + 256*i;
            int kk=e&15, mm=e>>4;
            int gm=m0+mm, gk=k0+kk;
            ra[i] = (gm<M && gk<Kd) ? A[(size_t)gm*Kd+gk] : 0.f;
        }
    };
    auto fetchB = [&](int k0){
        #pragma unroll
        for(int i=0;i<10;i++){
            int e = tid + 256*i;
            int kk=e&15, nn=e>>4;
            int gk=k0+kk;
            float val = 0.f;
            if(gk<Kd){
                int cc = (gk<Cc) ? gk : gk-Cc;
                float ctr = xTp[(size_t)(p0+s_pt[nn])*Cc + cc];
                if(gk<Cc){
                    float nb = xTp[(size_t)s_m[nn]*Cc + cc];
                    val = __fsub_rn(nb, ctr);
                } else val = ctr;
            }
            rb[i] = val;
        }
    };
    auto store = [&](int buf){
        #pragma unroll
        for(int i=0;i<8;i++){
            int e = tid + 256*i;
            As[buf][e&15][e>>4] = ra[i];
        }
        #pragma unroll
        for(int i=0;i<10;i++){
            int e = tid + 256*i;
            Bs[buf][e&15][e>>4] = rb[i];
        }
    };

    int nk = (Kd + BK - 1)/BK;
    fetchA(0); fetchB(0);
    store(0);
    __syncthreads();

    for(int t=0;t<nk;t++){
        int cur = t&1;
        if(t+1<nk){ fetchA((t+1)*BK); fetchB((t+1)*BK); }
        #pragma unroll
        for(int kk=0;kk<BK;kk++){
            float a8[8], b10[10];
            #pragma unroll
            for(int i=0;i<8;i++) a8[i]=As[cur][kk][ty*8+i];
            #pragma unroll
            for(int j=0;j<10;j++) b10[j]=Bs[cur][kk][tx*10+j];
            #pragma unroll
            for(int i=0;i<8;i++)
                #pragma unroll
                for(int j=0;j<10;j++) acc[i][j] = __fmaf_rn(a8[i], b10[j], acc[i][j]);
        }
        if(t+1<nk){
            __syncthreads();
            store(1-cur);
            __syncthreads();
        }
    }

    int O = M;
    #pragma unroll
    for(int i=0;i<8;i++){
        float mx=-FLT_MAX, mn=FLT_MAX, sm=0.f, sq=0.f;
        #pragma unroll
        for(int j=0;j<10;j++){
            float h = acc[i][j];
            mx = fmaxf(mx,h); mn = fminf(mn,h);
            sm = __fadd_rn(sm,h); sq = __fmaf_rn(h,h,sq);
        }
        #pragma unroll
        for(int j=0;j<10;j++){
            float h = __shfl_xor_sync(0xffffffffu, acc[i][j], 1);
            mx = fmaxf(mx,h); mn = fminf(mn,h);
            sm = __fadd_rn(sm,h); sq = __fmaf_rn(h,h,sq);
        }
        int gm = m0 + ty*8 + i;
        if(((tx&1)==0) && gm<M){
            int point = p0 + (tx>>1);
            size_t base = ((size_t)b*O + gm)*NN + point;
            g_kmax[base]=mx; g_kmin[base]=mn; g_ksum[base]=sm; g_ksq[base]=sq;
        }
    }
}

// ------------------------- small kernels -------------------------

__global__ void k_tin(const float* __restrict__ x){
    int i = blockIdx.x*blockDim.x + threadIdx.x;
    if(i >= BB*NN*3) return;
    int c = i%3; int n = (i/3)%NN; int b = i/(3*NN);
    g_xT[i] = x[((size_t)b*3 + c)*NN + n];
}

__global__ void k_xx(int C){
    int p = blockIdx.x*blockDim.x + threadIdx.x;
    if(p >= BB*NN) return;
    const float* v = g_xT + (size_t)p*C;
    float s = 0.f;
    for(int c=0;c<C;c++) s = __fadd_rn(s, __fmul_rn(v[c], v[c]));
    g_xx[p] = s;
}

// shared top-k selection body (given v[8] per thread). FUSED3: recompute
// distances in the (never-taken for continuous data) fallback.
template<int FUSED3>
__device__ __forceinline__ void topk_select(
    float* v, int tid, int lane, int w, int n, int bq,
    const float* __restrict__ X3, float xxn, const float* __restrict__ xxr)
{
    __shared__ float swmx[8], swmn[8];
    __shared__ int hist8[8][256];
    __shared__ int hist[256];
    __shared__ unsigned long long cand[256];
    __shared__ int s_cnt, s_B, s_size;
    __shared__ float s_lo, s_hi;
    int base = tid*8;

    float mx=v[0], mn=v[0];
    #pragma unroll
    for(int t=1;t<8;t++){ mx=fmaxf(mx,v[t]); mn=fminf(mn,v[t]); }
    #pragma unroll
    for(int o=16;o;o>>=1){
        mx=fmaxf(mx,__shfl_xor_sync(0xffffffffu,mx,o));
        mn=fminf(mn,__shfl_xor_sync(0xffffffffu,mn,o));
    }
    if(lane==0){ swmx[w]=mx; swmn[w]=mn; }
    #pragma unroll
    for(int q=0;q<8;q++) hist8[q][tid]=0;
    __syncthreads();
    if(tid==0){
        float hx=swmx[0], hn=swmn[0];
        #pragma unroll
        for(int q=1;q<8;q++){ hx=fmaxf(hx,swmx[q]); hn=fminf(hn,swmn[q]); }
        s_lo=hn; s_hi=hx; s_cnt=0;
    }
    __syncthreads();
    float lo=s_lo, hi=s_hi;
    float scale = (hi>lo) ? 255.0f/(hi-lo) : 0.0f;
    int bk[8];
    #pragma unroll
    for(int t=0;t<8;t++){
        int bb = (int)((v[t]-lo)*scale);
        bb = max(0, min(255, bb));
        bk[t]=bb;
        atomicAdd(&hist8[w][bb],1);
    }
    __syncthreads();
    {
        int hsum = 0;
        #pragma unroll
        for(int q=0;q<8;q++) hsum += hist8[q][tid];
        hist[tid] = hsum;
    }
    __syncthreads();
    if(w==0){
        int cs = 0;
        #pragma unroll
        for(int t=0;t<8;t++) cs += hist[lane*8+t];
        int rs = cs;
        #pragma unroll
        for(int o=1;o<32;o<<=1){
            int t2 = __shfl_down_sync(0xffffffffu, rs, o);
            if(lane+o<32) rs += t2;
        }
        int sufx = rs - cs;
        if(rs >= KNB && sufx < KNB){
            int run = sufx, Bv = lane*8;
            for(int j=7;j>=0;j--){
                run += hist[lane*8+j];
                if(run >= KNB){ Bv = lane*8+j; break; }
            }
            s_B = Bv;
        }
    }
    __syncthreads();
    int B = s_B;
    #pragma unroll
    for(int t=0;t<8;t++){
        if(bk[t] >= B){
            int pos = atomicAdd(&s_cnt,1);
            if(pos<256){
                unsigned int u = __float_as_uint(v[t]);
                u = (u & 0x80000000u) ? ~u : (u | 0x80000000u);
                cand[pos] = ((unsigned long long)u<<32) | (unsigned int)(~(base+t));
            }
        }
    }
    __syncthreads();
    int cnt = s_cnt;
    if(cnt<=256){
        if(tid==0){
            int sz = 32;
            while(sz < cnt) sz <<= 1;
            s_size = sz;
        }
        __syncthreads();
        int sz = s_size;
        if(tid<sz && tid>=cnt) cand[tid]=0ull;
        __syncthreads();
        for(int k=2;k<=sz;k<<=1){
            for(int j=k>>1;j>0;j>>=1){
                int ixj = tid ^ j;
                if(ixj > tid && ixj < sz && tid < sz){
                    bool up = ((tid & k) == 0);
                    unsigned long long a=cand[tid], c=cand[ixj];
                    if( (a > c) == up ){ cand[tid]=c; cand[ixj]=a; }
                }
                __syncthreads();
            }
        }
        if(tid<KNB)
            g_idx[((size_t)bq*NN+n)*KNB + tid] = (int)(~(unsigned int)cand[sz-1-tid]);
    } else {
        if(tid==0){
            if(FUSED3){
                int chosen[KNB];
                for(int j=0;j<KNB;j++){
                    float bvv=-FLT_MAX; int bii=0;
                    for(int i=0;i<NN;i++){
                        bool skip=false;
                        for(int q=0;q<j;q++) if(chosen[q]==i){ skip=true; break; }
                        if(skip) continue;
                        float a0=X3[i*3],a1=X3[i*3+1],a2=X3[i*3+2];
                        float ac=__fmaf_rn(X3[n*3],a0,0.f);
                        ac=__fmaf_rn(X3[n*3+1],a1,ac);
                        ac=__fmaf_rn(X3[n*3+2],a2,ac);
                        float vv=__fsub_rn(__fsub_rn(__fmul_rn(2.0f,ac),xxn),xxr[i]);
                        if(vv>bvv){ bvv=vv; bii=i; }
                    }
                    chosen[j]=bii;
                    g_idx[((size_t)bq*NN+n)*KNB + j]=bii;
                }
            } else {
                float* rw = g_dist + ((size_t)bq*NN + n)*NN;
                for(int j=0;j<KNB;j++){
                    float bvv=-FLT_MAX; int bii=0;
                    for(int i=0;i<NN;i++){ float vv=rw[i]; if(vv>bvv){bvv=vv;bii=i;} }
                    g_idx[((size_t)bq*NN+n)*KNB + j]=bii;
                    rw[bii]=-FLT_MAX;
                }
            }
        }
    }
}

// top-k from precomputed dist rows (layers 2-4)
__global__ void __launch_bounds__(256) k_topk(){
    int n = blockIdx.x, bq = blockIdx.y;
    const float* row = g_dist + ((size_t)bq*NN + n)*NN;
    int tid = threadIdx.x, lane = tid&31, w = tid>>5;
    float v[8];
    {
        const float4* r4 = (const float4*)(row + tid*8);
        float4 q0 = r4[0], q1 = r4[1];
        v[0]=q0.x; v[1]=q0.y; v[2]=q0.z; v[3]=q0.w;
        v[4]=q1.x; v[5]=q1.y; v[6]=q1.z; v[7]=q1.w;
    }
    topk_select<0>(v, tid, lane, w, n, bq, nullptr, 0.f, nullptr);
}

// fused dist+topk for layer 1 (C=3): distances computed on the fly, same
// fma chain (ascending c; zero-pad fmas in dgemm were exact no-ops) and
// same epilogue op order as k_dgemm => bit-identical values.
__global__ void __launch_bounds__(256) k_topk3(){
    int n = blockIdx.x, bq = blockIdx.y;
    const float* X3 = g_xT + (size_t)bq*NN*3;
    const float* xxr = g_xx + (size_t)bq*NN;
    int tid = threadIdx.x, lane = tid&31, w = tid>>5;
    float c0 = X3[n*3], c1 = X3[n*3+1], c2 = X3[n*3+2];
    float xxn = xxr[n];
    float f[24];
    {
        const float4* p4 = (const float4*)(X3 + tid*24);
        #pragma unroll
        for(int q=0;q<6;q++){
            float4 t = p4[q];
            f[q*4+0]=t.x; f[q*4+1]=t.y; f[q*4+2]=t.z; f[q*4+3]=t.w;
        }
    }
    float v[8];
    #pragma unroll
    for(int q=0;q<8;q++){
        float ac = __fmaf_rn(c0, f[q*3+0], 0.f);
        ac = __fmaf_rn(c1, f[q*3+1], ac);
        ac = __fmaf_rn(c2, f[q*3+2], ac);
        v[q] = __fsub_rn(__fsub_rn(__fmul_rn(2.0f, ac), xxn), xxr[tid*8+q]);
    }
    topk_select<1>(v, tid, lane, w, n, bq, X3, xxn, xxr);
}

__global__ void k_ec_stats(int O){
    int o = blockIdx.x, tid = threadIdx.x;
    double s=0.0, ss=0.0;
    for(int b=0;b<BB;b++){
        size_t base = ((size_t)b*O + o)*NN;
        for(int n=tid;n<NN;n+=256){ s += g_ksum[base+n]; ss += g_ksq[base+n]; }
    }
    __shared__ double rs[256], rq[256];
    rs[tid]=s; rq[tid]=ss; __syncthreads();
    for(int st=128;st;st>>=1){ if(tid<st){ rs[tid]+=rs[tid+st]; rq[tid]+=rq[tid+st]; } __syncthreads(); }
    if(tid==0){
        double cnt = (double)BB*NN*KNB;
        double mean = rs[0]/cnt;
        double var  = rq[0]/cnt - mean*mean;
        g_prm[2*o]   = (float)mean;
        g_prm[2*o+1] = (float)var;
    }
}

// coalesced BN+lrelu apply: 32o x 64n smem tile; both xcat and xT writes coalesced
__global__ void __launch_bounds__(256) k_ec_apply2(int O, int c0, float* __restrict__ xTout,
                            const float* __restrict__ gw, const float* __restrict__ bw){
    int o0 = blockIdx.x*32;
    int n0base = blockIdx.y*256;
    int b = blockIdx.z;
    __shared__ float pmm[32], psd[32], pg[32], pb[32];
    __shared__ int   puse[32];
    __shared__ float tile[64][33];
    int tid = threadIdx.x;
    if(tid<32){
        int o = o0+tid;
        float m = g_prm[2*o], vv = g_prm[2*o+1];
        pmm[tid]=m; psd[tid]=__fsqrt_rn(__fadd_rn(vv, EPSB));
        pg[tid]=gw[o]; pb[tid]=bw[o];
        puse[tid] = (gw[o]>=0.f) ? 1 : 0;
    }
    __syncthreads();
    for(int s=0;s<4;s++){
        int n0 = n0base + s*64;
        #pragma unroll
        for(int e=tid; e<2048; e+=256){
            int ol=e>>6, nl=e&63;
            const float* src = puse[ol] ? g_kmax : g_kmin;
            float vsrc = src[((size_t)b*O + o0+ol)*NN + n0+nl];
            float y = __fadd_rn(__fmul_rn(__fdiv_rn(__fsub_rn(vsrc, pmm[ol]), psd[ol]), pg[ol]), pb[ol]);
            y = (y>=0.f) ? y : __fmul_rn(NEGS, y);
            g_xcat[((size_t)b*512 + c0 + o0+ol)*NN + n0+nl] = y;
            tile[nl][ol] = y;
        }
        __syncthreads();
        #pragma unroll
        for(int e=tid; e<2048; e+=256){
            int nl=e>>5, ol=e&31;
            xTout[((size_t)b*NN + n0+nl)*O + o0+ol] = tile[nl][ol];
        }
        __syncthreads();
    }
}

__global__ void k_conv_stats(const float* __restrict__ h, int O){
    int o = blockIdx.x, tid = threadIdx.x;
    double s=0.0, ss=0.0;
    for(int b=0;b<BB;b++){
        size_t base = ((size_t)b*O + o)*NN;
        for(int n=tid;n<NN;n+=256){ float v=h[base+n]; s += v; ss += (double)v*v; }
    }
    __shared__ double rs[256], rq[256];
    rs[tid]=s; rq[tid]=ss; __syncthreads();
    for(int st=128;st;st>>=1){ if(tid<st){ rs[tid]+=rs[tid+st]; rq[tid]+=rq[tid+st]; } __syncthreads(); }
    if(tid==0){
        double cnt = (double)BB*NN;
        double mean = rs[0]/cnt;
        double var  = rq[0]/cnt - mean*mean;
        g_prm[2*o]   = (float)mean;
        g_prm[2*o+1] = (float)var;
    }
}

__global__ void k_conv_apply(float* __restrict__ h, int O,
                             const float* __restrict__ gw, const float* __restrict__ bw){
    int o = blockIdx.x, b = blockIdx.y;
    float m = g_prm[2*o], vv = g_prm[2*o+1];
    float gg = gw[o], bb = bw[o];
    float sd = __fsqrt_rn(__fadd_rn(vv, EPSB));
    float* p = h + ((size_t)b*O + o)*NN;
    for(int n=threadIdx.x;n<NN;n+=blockDim.x){
        float y = __fadd_rn(__fmul_rn(__fdiv_rn(__fsub_rn(p[n], m), sd), gg), bb);
        p[n] = (y>=0.f) ? y : __fmul_rn(NEGS, y);
    }
}

// fused h5 BN-stats (identical double accumulation order) + per-(b,o) max/min
// + global-pool epilogue: one pass over h5 instead of two.
__global__ void __launch_bounds__(256) k_h5stats(const float* __restrict__ gw,
                                                 const float* __restrict__ bw){
    int o = blockIdx.x, tid = threadIdx.x, lane = tid&31, w = tid>>5;
    double s=0.0, ss=0.0;
    float bmx[BB], bmn[BB];
    #pragma unroll
    for(int b=0;b<BB;b++){ bmx[b]=-FLT_MAX; bmn[b]=FLT_MAX; }
    for(int b=0;b<BB;b++){
        size_t base = ((size_t)b*1024 + o)*NN;
        for(int n=tid;n<NN;n+=256){
            float v = g_h5[base+n];
            s += v; ss += (double)v*v;
            bmx[b]=fmaxf(bmx[b],v); bmn[b]=fminf(bmn[b],v);
        }
    }
    __shared__ double rs[256], rq[256];
    rs[tid]=s; rq[tid]=ss; __syncthreads();
    for(int st=128;st;st>>=1){ if(tid<st){ rs[tid]+=rs[tid+st]; rq[tid]+=rq[tid+st]; } __syncthreads(); }
    __shared__ float sx[8][BB], sn[8][BB];
    #pragma unroll
    for(int b=0;b<BB;b++){
        float mx=bmx[b], mn=bmn[b];
        #pragma unroll
        for(int off=16;off;off>>=1){
            mx=fmaxf(mx,__shfl_xor_sync(0xffffffffu,mx,off));
            mn=fminf(mn,__shfl_xor_sync(0xffffffffu,mn,off));
        }
        if(lane==0){ sx[w][b]=mx; sn[w][b]=mn; }
    }
    __shared__ float smean, svar;
    __syncthreads();
    if(tid==0){
        double cnt = (double)BB*NN;
        double mean = rs[0]/cnt;
        double var  = rq[0]/cnt - mean*mean;
        smean = (float)mean; svar = (float)var;
    }
    __syncthreads();
    if(tid<BB){
        int b = tid;
        float mx=sx[0][b], mn=sn[0][b];
        #pragma unroll
        for(int q=1;q<8;q++){ mx=fmaxf(mx,sx[q][b]); mn=fminf(mn,sn[q][b]); }
        float gg = gw[o];
        float src = (gg>=0.f) ? mx : mn;
        float sd = __fsqrt_rn(__fadd_rn(svar, EPSB));
        float y = __fadd_rn(__fmul_rn(__fdiv_rn(__fsub_rn(src, smean), sd), gg), bw[o]);
        y = (y>=0.f) ? y : __fmul_rn(NEGS, y);
        g_glob[b*1088 + o] = y;
    }
}

__global__ void k_lf(const float* __restrict__ l, const float* __restrict__ W,
                     const float* __restrict__ gw, const float* __restrict__ bw){
    int tid = threadIdx.x;
    int o = tid & 63, b = tid >> 6;
    __shared__ float hs[8][64];
    __shared__ float pm[64], pv[64];
    float s = 0.f;
    #pragma unroll
    for(int c=0;c<16;c++) s = __fmaf_rn(W[o*16 + c], l[b*16 + c], s);
    hs[b][o] = s;
    __syncthreads();
    if(tid < 64){
        float m = 0.f;
        #pragma unroll
        for(int q=0;q<8;q++) m = __fadd_rn(m, hs[q][tid]);
        m = __fdiv_rn(m, 8.f);
        float v = 0.f;
        #pragma unroll
        for(int q=0;q<8;q++){ float d = __fsub_rn(hs[q][tid], m); v = __fmaf_rn(d, d, v); }
        v = __fdiv_rn(v, 8.f);
        pm[tid] = m; pv[tid] = v;
    }
    __syncthreads();
    float sd = __fsqrt_rn(__fadd_rn(pv[o], EPSB));
    float y = __fadd_rn(__fmul_rn(__fdiv_rn(__fsub_rn(hs[b][o], pm[o]), sd), gw[o]), bw[o]);
    y = (y>=0.f) ? y : __fmul_rn(NEGS, y);
    g_glob[b*1088 + 1024 + o] = y;
}

__global__ void k_bias207(const float* __restrict__ W207){
    int b = blockIdx.x;
    __shared__ float gl[1088];
    for(int i=threadIdx.x;i<1088;i+=256) gl[i] = g_glob[b*1088 + i];
    __syncthreads();
    int o = threadIdx.x;
    float s = 0.f;
    for(int c=0;c<1088;c++) s = __fmaf_rn(W207[(size_t)o*1600 + c], gl[c], s);
    g_b207[b*256 + o] = s;
}

// ------------------------- launcher -------------------------
extern "C" void kernel_launch(void* const* d_in, const int* in_sizes, int n_in,
                              void* d_out, int out_size){
    (void)in_sizes; (void)n_in; (void)out_size;
    const float* x    = (const float*)d_in[0];
    const float* l    = (const float*)d_in[1];
    const float* Wec[4] = {(const float*)d_in[2],(const float*)d_in[5],(const float*)d_in[8],(const float*)d_in[11]};
    const float* gec[4] = {(const float*)d_in[3],(const float*)d_in[6],(const float*)d_in[9],(const float*)d_in[12]};
    const float* bec[4] = {(const float*)d_in[4],(const float*)d_in[7],(const float*)d_in[10],(const float*)d_in[13]};
    const float* W5   = (const float*)d_in[14]; const float* g5v  = (const float*)d_in[15]; const float* b5v  = (const float*)d_in[16];
    const float* W206 = (const float*)d_in[17]; const float* g206 = (const float*)d_in[18]; const float* b206 = (const float*)d_in[19];
    const float* W207 = (const float*)d_in[20]; const float* g207 = (const float*)d_in[21]; const float* b207 = (const float*)d_in[22];
    const float* W208 = (const float*)d_in[23]; const float* g208 = (const float*)d_in[24]; const float* b208 = (const float*)d_in[25];
    const float* W209 = (const float*)d_in[26]; const float* g209 = (const float*)d_in[27]; const float* b209 = (const float*)d_in[28];
    const float* W2010= (const float*)d_in[29];

    float *xT,*xxp,*xcat,*h5,*hb1,*hb2,*hb3,*b207p;
    int *idxp;
    cudaGetSymbolAddress((void**)&xT,   g_xT);
    cudaGetSymbolAddress((void**)&xxp,  g_xx);
    cudaGetSymbolAddress((void**)&idxp, g_idx);
    cudaGetSymbolAddress((void**)&xcat, g_xcat);
    cudaGetSymbolAddress((void**)&h5,   g_h5);
    cudaGetSymbolAddress((void**)&hb1,  g_hb1);
    cudaGetSymbolAddress((void**)&hb2,  g_hb2);
    cudaGetSymbolAddress((void**)&hb3,  g_hb3);
    cudaGetSymbolAddress((void**)&b207p,g_b207);

    const int Cin[4] = {3,64,64,128};
    const int Oo [4] = {64,64,128,256};
    const int c0 [4] = {0,64,128,256};

    k_tin<<<(BB*NN*3 + 255)/256, 256>>>(x);

    for(int li=0; li<4; li++){
        int C = Cin[li], O = Oo[li];
        k_xx<<<(BB*NN + 255)/256, 256>>>(C);
        if(li==0){
            k_topk3<<<dim3(NN, BB), 256>>>();
        } else {
            k_dgemm<<<dim3(NN/128, NN/128, BB), 256>>>(C, xT, xxp);
            k_topk<<<dim3(NN, BB), 256>>>();
        }
        int C2 = 2*C;
        k_egemm<<<dim3(NN/8, (O+127)/128, BB), 256>>>(O, C2, Wec[li], xT, idxp, C);
        k_ec_stats<<<O, 256>>>(O);
        k_ec_apply2<<<dim3(O/32, NN/256, BB), 256>>>(O, c0[li], xT, gec[li], bec[li]);
    }

    k_gemm<true,0><<<dim3(NN/128, 1024/128, BB), 256>>>(
        1024, NN, 512, W5, 512, 0, xcat, NN, (size_t)512*NN, h5, (size_t)1024*NN, nullptr);
    k_h5stats<<<1024, 256>>>(g5v, b5v);
    k_lf<<<1, 512>>>(l, W206, g206, b206);
    k_bias207<<<BB, 256>>>(W207);
    k_gemm<true,2><<<dim3(NN/128, 2, BB), 256>>>(
        256, NN, 512, W207 + 1088, 1600, 0, xcat, NN, (size_t)512*NN, hb1, (size_t)256*NN, b207p);
    k_conv_stats<<<256, 256>>>(hb1, 256);
    k_conv_apply<<<dim3(256, BB), 256>>>(hb1, 256, g207, b207);
    k_gemm<true,0><<<dim3(NN/128, 2, BB), 256>>>(
        256, NN, 256, W208, 256, 0, hb1, NN, (size_t)256*NN, hb2, (size_t)256*NN, nullptr);
    k_conv_stats<<<256, 256>>>(hb2, 256);
    k_conv_apply<<<dim3(256, BB), 256>>>(hb2, 256, g208, b208);
    k_gemm<true,0><<<dim3(NN/128, 1, BB), 256>>>(
        128, NN, 256, W209, 256, 0, hb2, NN, (size_t)256*NN, hb3, (size_t)128*NN, nullptr);
    k_conv_stats<<<128, 256>>>(hb3, 128);
    k_conv_apply<<<dim3(128, BB), 256>>>(hb3, 128, g209, b209);
    k_gemm<true,0><<<dim3(NN/128, 1, BB), 256>>>(
        50, NN, 128, W2010, 128, 0, hb3, NN, (size_t)128*NN, (float*)d_out, (size_t)50*NN, nullptr);
}

// round 12
// speedup vs baseline: 1.5357x; 1.1696x over previous
#include <cuda_runtime.h>
#include <cstdlib>
#include <cfloat>

#define BB 8
#define NN 2048
#define KNB 20
#define NEGS 0.2f
#define EPSB 1e-5f

__attribute__((constructor)) static void _eager_load(){ setenv("CUDA_MODULE_LOADING","EAGER",0); }

// ------------------------- scratch (device globals) -------------------------
__device__ float g_xT  [(size_t)BB*NN*256];
__device__ float g_xx  [BB*NN];
__device__ float g_dist[(size_t)BB*NN*NN];
__device__ int   g_idx [(size_t)BB*NN*KNB];
__device__ float g_kmax[(size_t)BB*256*NN];
__device__ float g_kmin[(size_t)BB*256*NN];
__device__ float g_ksum[(size_t)BB*256*NN];
__device__ float g_ksq [(size_t)BB*256*NN];
__device__ float g_xcat[(size_t)BB*512*NN];
__device__ float g_h5  [(size_t)BB*1024*NN];
__device__ float g_hb1 [(size_t)BB*256*NN];
__device__ float g_hb2 [(size_t)BB*256*NN];
__device__ float g_hb3 [(size_t)BB*128*NN];
__device__ float g_glob[BB*1088];
__device__ float g_b207[BB*256];
__device__ float g_prm [2048];

// ------------------------- generic fp32 GEMM (pipelined, bit-identical math) --
template<bool BT, int MODE>
__global__ void __launch_bounds__(256,2) k_gemm(
    int M, int Ncol, int Kd,
    const float* __restrict__ A, int lda, size_t asb,
    const float* __restrict__ Bp, int ldb, size_t bsb,
    float* __restrict__ Cp, size_t csb,
    const float* __restrict__ e0)
{
    const int BM=128, BN=128, BK=16;
    __shared__ float As[2][BK][BM+4];
    __shared__ float Bs[2][BK][BN+4];
    int b  = blockIdx.z;
    int m0 = blockIdx.y*BM, n0 = blockIdx.x*BN;
    A  += (size_t)b*asb;
    Bp += (size_t)b*bsb;
    Cp += (size_t)b*csb;
    int tid = threadIdx.x;
    int tx = tid%16, ty = tid/16;

    float acc[8][8];
    #pragma unroll
    for(int i=0;i<8;i++)
        #pragma unroll
        for(int j=0;j<8;j++) acc[i][j]=0.f;

    float ra[8], rb[8];

    auto fetchA = [&](int k0){
        #pragma unroll
        for(int i=0;i<8;i++){
            int e = tid + 256*i;
            int kk=e%BK, mm=e/BK;
            int gm=m0+mm, gk=k0+kk;
            ra[i] = (gm<M && gk<Kd) ? A[(size_t)gm*lda+gk] : 0.f;
        }
    };
    auto fetchB = [&](int k0){
        if(!BT){
            #pragma unroll
            for(int i=0;i<8;i++){
                int e = tid + 256*i;
                int kk=e%BK, nn=e/BK;
                int gn=n0+nn, gk=k0+kk;
                rb[i] = (gn<Ncol && gk<Kd) ? Bp[(size_t)gn*ldb+gk] : 0.f;
            }
        } else {
            #pragma unroll
            for(int i=0;i<8;i++){
                int e = tid + 256*i;
                int nn=e%BN, kk=e/BN;
                int gn=n0+nn, gk=k0+kk;
                rb[i] = (gn<Ncol && gk<Kd) ? Bp[(size_t)gk*ldb+gn] : 0.f;
            }
        }
    };
    auto store = [&](int buf){
        #pragma unroll
        for(int i=0;i<8;i++){
            int e = tid + 256*i;
            As[buf][e%BK][e/BK] = ra[i];
        }
        if(!BT){
            #pragma unroll
            for(int i=0;i<8;i++){
                int e = tid + 256*i;
                Bs[buf][e%BK][e/BK] = rb[i];
            }
        } else {
            #pragma unroll
            for(int i=0;i<8;i++){
                int e = tid + 256*i;
                Bs[buf][e/BN][e%BN] = rb[i];
            }
        }
    };

    int nk = (Kd + BK - 1)/BK;
    fetchA(0); fetchB(0);
    store(0);
    __syncthreads();

    for(int t=0;t<nk;t++){
        int cur = t&1;
        if(t+1<nk){ fetchA((t+1)*BK); fetchB((t+1)*BK); }
        #pragma unroll
        for(int kk=0;kk<BK;kk++){
            float a8[8], b8[8];
            #pragma unroll
            for(int i=0;i<8;i++) a8[i]=As[cur][kk][ty*8+i];
            #pragma unroll
            for(int j=0;j<8;j++) b8[j]=Bs[cur][kk][tx*8+j];
            #pragma unroll
            for(int i=0;i<8;i++)
                #pragma unroll
                for(int j=0;j<8;j++) acc[i][j] = __fmaf_rn(a8[i], b8[j], acc[i][j]);
        }
        if(t+1<nk){
            __syncthreads();
            store(1-cur);
            __syncthreads();
        }
    }

    #pragma unroll
    for(int i=0;i<8;i++){
        int gm = m0+ty*8+i;
        if(gm>=M) continue;
        #pragma unroll
        for(int j=0;j<8;j++){
            int gn = n0+tx*8+j;
            if(gn>=Ncol) continue;
            float v = acc[i][j];
            if(MODE==2) v = __fadd_rn(v, e0[(size_t)b*M+gm]);
            Cp[(size_t)gm*Ncol + gn] = v;
        }
    }
}

// -------- symmetric dist GEMM (layers 2-4) --------------------------------
__global__ void __launch_bounds__(256,2) k_dgemm(
    int Kd, const float* __restrict__ Xp, const float* __restrict__ e0)
{
    const int BK=16;
    if(blockIdx.x < blockIdx.y) return;
    __shared__ float pool[8448];
    #define ASM(buf,kk,mm) pool[(buf)*2112 + (kk)*132 + (mm)]
    #define BSM(buf,kk,nn) pool[4224 + (buf)*2112 + (kk)*132 + (nn)]
    int b  = blockIdx.z;
    int m0 = blockIdx.y*128, n0 = blockIdx.x*128;
    const float* A = Xp + (size_t)b*NN*Kd;
    float* Cp = g_dist + (size_t)b*NN*NN;
    const float* xxr = e0 + (size_t)b*NN;
    int tid = threadIdx.x;
    int tx = tid%16, ty = tid/16;

    float acc[8][8];
    #pragma unroll
    for(int i=0;i<8;i++)
        #pragma unroll
        for(int j=0;j<8;j++) acc[i][j]=0.f;

    float ra[8], rb[8];
    auto fetchA = [&](int k0){
        #pragma unroll
        for(int i=0;i<8;i++){
            int e = tid + 256*i;
            int kk=e&15, mm=e>>4;
            int gk=k0+kk;
            ra[i] = (gk<Kd) ? A[(size_t)(m0+mm)*Kd+gk] : 0.f;
        }
    };
    auto fetchB = [&](int k0){
        #pragma unroll
        for(int i=0;i<8;i++){
            int e = tid + 256*i;
            int kk=e&15, nn=e>>4;
            int gk=k0+kk;
            rb[i] = (gk<Kd) ? A[(size_t)(n0+nn)*Kd+gk] : 0.f;
        }
    };
    auto store = [&](int buf){
        #pragma unroll
        for(int i=0;i<8;i++){
            int e = tid + 256*i;
            ASM(buf, e&15, e>>4) = ra[i];
        }
        #pragma unroll
        for(int i=0;i<8;i++){
            int e = tid + 256*i;
            BSM(buf, e&15, e>>4) = rb[i];
        }
    };

    int nk = (Kd + BK - 1)/BK;
    fetchA(0); fetchB(0);
    store(0);
    __syncthreads();
    for(int t=0;t<nk;t++){
        int cur = t&1;
        if(t+1<nk){ fetchA((t+1)*BK); fetchB((t+1)*BK); }
        #pragma unroll
        for(int kk=0;kk<BK;kk++){
            float a8[8], b8[8];
            #pragma unroll
            for(int i=0;i<8;i++) a8[i]=ASM(cur,kk,ty*8+i);
            #pragma unroll
            for(int j=0;j<8;j++) b8[j]=BSM(cur,kk,tx*8+j);
            #pragma unroll
            for(int i=0;i<8;i++)
                #pragma unroll
                for(int j=0;j<8;j++) acc[i][j] = __fmaf_rn(a8[i], b8[j], acc[i][j]);
        }
        if(t+1<nk){
            __syncthreads();
            store(1-cur);
            __syncthreads();
        }
    }

    #pragma unroll
    for(int i=0;i<8;i++){
        int gm = m0+ty*8+i;
        float xm = xxr[gm];
        #pragma unroll
        for(int j=0;j<8;j++){
            int gn = n0+tx*8+j;
            float v = __fsub_rn(__fsub_rn(__fmul_rn(2.0f, acc[i][j]), xm), xxr[gn]);
            acc[i][j] = v;
            Cp[(size_t)gm*NN + gn] = v;
        }
    }
    if(blockIdx.x > blockIdx.y){
        for(int c=0;c<4;c++){
            __syncthreads();
            if((tx>>2)==c){
                int tl = tx&3;
                #pragma unroll
                for(int i=0;i<8;i++)
                    #pragma unroll
                    for(int j=0;j<8;j++)
                        pool[(tl*8+j)*132 + ty*8+i] = acc[i][j];
            }
            __syncthreads();
            #pragma unroll
            for(int q=0;q<16;q++){
                int e = tid + 256*q;
                int rr=e>>7, cc=e&127;
                Cp[(size_t)(n0+c*32+rr)*NN + m0+cc] = pool[rr*132+cc];
            }
        }
    }
    #undef ASM
    #undef BSM
}

// ------- templated fused edge-conv GEMM + k-reduce -------------------------
// C: input channels (compile-time), BM: tile height. BN = 160 = 8 points x 20.
// Per-output FMA chain: ascending k-tiles, ascending kk, single accumulator —
// identical order regardless of BM, so values are bit-identical across configs.
template<int C, int BM, int MAXB>
__global__ void __launch_bounds__(256,MAXB) k_egemm_t(
    int M,                               // = O (for epilogue addressing)
    const float* __restrict__ A,         // W [O, 2C]
    const float* __restrict__ xTp,       // [B, N, C]
    const int*   __restrict__ idxp)      // [B, N, K]
{
    const int BN=160, BK=16;
    const int Kd = 2*C;
    const int NK = (Kd + BK - 1)/BK;
    const int TM = BM/16;                // rows per thread (4 or 8)
    const int NA = BM*BK/256;            // A elems per thread per tile
    __shared__ float As[2][BK][BM+4];
    __shared__ float Bs[2][BK][BN+4];
    __shared__ int   s_moff[BN];         // neighbor row offset (pre-multiplied by C)
    __shared__ int   s_poff[BN];         // center row offset (pre-multiplied by C)
    int b  = blockIdx.z;
    int m0 = blockIdx.y*BM;
    int p0 = blockIdx.x*8;
    xTp  += (size_t)b*NN*C;
    idxp += (size_t)b*NN*KNB;
    int tid = threadIdx.x;
    int tx = tid%16, ty = tid/16;

    if(tid < BN){
        int pt = tid/KNB;
        int kq = tid - pt*KNB;
        s_poff[tid] = (p0+pt)*C;
        s_moff[tid] = idxp[(size_t)(p0+pt)*KNB + kq]*C;
    }
    __syncthreads();

    float acc[TM][10];
    #pragma unroll
    for(int i=0;i<TM;i++)
        #pragma unroll
        for(int j=0;j<10;j++) acc[i][j]=0.f;

    float ra[NA], rb[10];
    int kkme = tid & 15;

    auto fetchA = [&](int k0){
        #pragma unroll
        for(int i=0;i<NA;i++){
            int e = tid + 256*i;
            int kk=e&15, mm=e>>4;
            int gk=k0+kk;
            ra[i] = (gk<Kd) ? A[(size_t)(m0+mm)*Kd+gk] : 0.f;
        }
    };
    auto fetchB = [&](int k0){
        if(k0 + BK <= C){
            // pure neighbor-diff tile
            int cc = k0 + kkme;
            #pragma unroll
            for(int i=0;i<10;i++){
                int nn = (tid>>4) + 16*i;
                rb[i] = __fsub_rn(xTp[s_moff[nn] + cc], xTp[s_poff[nn] + cc]);
            }
        } else if(k0 >= C){
            // pure center tile
            int cc = k0 - C + kkme;
            #pragma unroll
            for(int i=0;i<10;i++){
                int nn = (tid>>4) + 16*i;
                rb[i] = xTp[s_poff[nn] + cc];
            }
        } else {
            // mixed tile (only C=3): per-element predicates
            int gk = k0 + kkme;
            #pragma unroll
            for(int i=0;i<10;i++){
                int nn = (tid>>4) + 16*i;
                float val = 0.f;
                if(gk < Kd){
                    int cc = (gk<C) ? gk : gk-C;
                    float ctr = xTp[s_poff[nn] + cc];
                    if(gk<C) val = __fsub_rn(xTp[s_moff[nn] + cc], ctr);
                    else     val = ctr;
                }
                rb[i] = val;
            }
        }
    };
    auto store = [&](int buf){
        #pragma unroll
        for(int i=0;i<NA;i++){
            int e = tid + 256*i;
            As[buf][e&15][e>>4] = ra[i];
        }
        #pragma unroll
        for(int i=0;i<10;i++){
            int nn = (tid>>4) + 16*i;
            Bs[buf][kkme][nn] = rb[i];
        }
    };

    fetchA(0); fetchB(0);
    store(0);
    __syncthreads();

    #pragma unroll 1
    for(int t=0;t<NK;t++){
        int cur = t&1;
        if(t+1<NK){ fetchA((t+1)*BK); fetchB((t+1)*BK); }
        #pragma unroll
        for(int kk=0;kk<BK;kk++){
            float am[TM], b10[10];
            #pragma unroll
            for(int i=0;i<TM;i++) am[i]=As[cur][kk][ty*TM+i];
            #pragma unroll
            for(int j=0;j<10;j++) b10[j]=Bs[cur][kk][tx*10+j];
            #pragma unroll
            for(int i=0;i<TM;i++)
                #pragma unroll
                for(int j=0;j<10;j++) acc[i][j] = __fmaf_rn(am[i], b10[j], acc[i][j]);
        }
        if(t+1<NK){
            __syncthreads();
            store(1-cur);
            __syncthreads();
        }
    }

    // Epilogue: strict ascending-k reduction (bit-identical to separate kreduce)
    int O = M;
    #pragma unroll
    for(int i=0;i<TM;i++){
        float mx=-FLT_MAX, mn=FLT_MAX, sm=0.f, sq=0.f;
        #pragma unroll
        for(int j=0;j<10;j++){
            float h = acc[i][j];
            mx = fmaxf(mx,h); mn = fminf(mn,h);
            sm = __fadd_rn(sm,h); sq = __fmaf_rn(h,h,sq);
        }
        #pragma unroll
        for(int j=0;j<10;j++){
            float h = __shfl_xor_sync(0xffffffffu, acc[i][j], 1);
            mx = fmaxf(mx,h); mn = fminf(mn,h);
            sm = __fadd_rn(sm,h); sq = __fmaf_rn(h,h,sq);
        }
        int gm = m0 + ty*TM + i;
        if((tx&1)==0){
            int point = p0 + (tx>>1);
            size_t base = ((size_t)b*O + gm)*NN + point;
            g_kmax[base]=mx; g_kmin[base]=mn; g_ksum[base]=sm; g_ksq[base]=sq;
        }
    }
}

// ------------------------- small kernels -------------------------

__global__ void k_tin(const float* __restrict__ x){
    int i = blockIdx.x*blockDim.x + threadIdx.x;
    if(i >= BB*NN*3) return;
    int c = i%3; int n = (i/3)%NN; int b = i/(3*NN);
    g_xT[i] = x[((size_t)b*3 + c)*NN + n];
}

__global__ void k_xx(int C){
    int p = blockIdx.x*blockDim.x + threadIdx.x;
    if(p >= BB*NN) return;
    const float* v = g_xT + (size_t)p*C;
    float s = 0.f;
    for(int c=0;c<C;c++) s = __fadd_rn(s, __fmul_rn(v[c], v[c]));
    g_xx[p] = s;
}

// shared top-k selection body (given v[8] per thread).
template<int FUSED3>
__device__ __forceinline__ void topk_select(
    float* v, int tid, int lane, int w, int n, int bq,
    const float* __restrict__ X3, float xxn, const float* __restrict__ xxr)
{
    __shared__ float swmx[8], swmn[8];
    __shared__ int hist8[8][256];
    __shared__ int hist[256];
    __shared__ unsigned long long cand[256];
    __shared__ int s_cnt, s_B, s_size;
    __shared__ float s_lo, s_hi;
    int base = tid*8;

    float mx=v[0], mn=v[0];
    #pragma unroll
    for(int t=1;t<8;t++){ mx=fmaxf(mx,v[t]); mn=fminf(mn,v[t]); }
    #pragma unroll
    for(int o=16;o;o>>=1){
        mx=fmaxf(mx,__shfl_xor_sync(0xffffffffu,mx,o));
        mn=fminf(mn,__shfl_xor_sync(0xffffffffu,mn,o));
    }
    if(lane==0){ swmx[w]=mx; swmn[w]=mn; }
    #pragma unroll
    for(int q=0;q<8;q++) hist8[q][tid]=0;
    __syncthreads();
    if(tid==0){
        float hx=swmx[0], hn=swmn[0];
        #pragma unroll
        for(int q=1;q<8;q++){ hx=fmaxf(hx,swmx[q]); hn=fminf(hn,swmn[q]); }
        s_lo=hn; s_hi=hx; s_cnt=0;
    }
    __syncthreads();
    float lo=s_lo, hi=s_hi;
    float scale = (hi>lo) ? 255.0f/(hi-lo) : 0.0f;
    int bk[8];
    #pragma unroll
    for(int t=0;t<8;t++){
        int bb = (int)((v[t]-lo)*scale);
        bb = max(0, min(255, bb));
        bk[t]=bb;
        atomicAdd(&hist8[w][bb],1);
    }
    __syncthreads();
    {
        int hsum = 0;
        #pragma unroll
        for(int q=0;q<8;q++) hsum += hist8[q][tid];
        hist[tid] = hsum;
    }
    __syncthreads();
    if(w==0){
        int cs = 0;
        #pragma unroll
        for(int t=0;t<8;t++) cs += hist[lane*8+t];
        int rs = cs;
        #pragma unroll
        for(int o=1;o<32;o<<=1){
            int t2 = __shfl_down_sync(0xffffffffu, rs, o);
            if(lane+o<32) rs += t2;
        }
        int sufx = rs - cs;
        if(rs >= KNB && sufx < KNB){
            int run = sufx, Bv = lane*8;
            for(int j=7;j>=0;j--){
                run += hist[lane*8+j];
                if(run >= KNB){ Bv = lane*8+j; break; }
            }
            s_B = Bv;
        }
    }
    __syncthreads();
    int B = s_B;
    #pragma unroll
    for(int t=0;t<8;t++){
        if(bk[t] >= B){
            int pos = atomicAdd(&s_cnt,1);
            if(pos<256){
                unsigned int u = __float_as_uint(v[t]);
                u = (u & 0x80000000u) ? ~u : (u | 0x80000000u);
                cand[pos] = ((unsigned long long)u<<32) | (unsigned int)(~(base+t));
            }
        }
    }
    __syncthreads();
    int cnt = s_cnt;
    if(cnt<=256){
        if(tid==0){
            int sz = 32;
            while(sz < cnt) sz <<= 1;
            s_size = sz;
        }
        __syncthreads();
        int sz = s_size;
        if(tid<sz && tid>=cnt) cand[tid]=0ull;
        __syncthreads();
        for(int k=2;k<=sz;k<<=1){
            for(int j=k>>1;j>0;j>>=1){
                int ixj = tid ^ j;
                if(ixj > tid && ixj < sz && tid < sz){
                    bool up = ((tid & k) == 0);
                    unsigned long long a=cand[tid], c=cand[ixj];
                    if( (a > c) == up ){ cand[tid]=c; cand[ixj]=a; }
                }
                __syncthreads();
            }
        }
        if(tid<KNB)
            g_idx[((size_t)bq*NN+n)*KNB + tid] = (int)(~(unsigned int)cand[sz-1-tid]);
    } else {
        if(tid==0){
            if(FUSED3){
                int chosen[KNB];
                for(int j=0;j<KNB;j++){
                    float bvv=-FLT_MAX; int bii=0;
                    for(int i=0;i<NN;i++){
                        bool skip=false;
                        for(int q=0;q<j;q++) if(chosen[q]==i){ skip=true; break; }
                        if(skip) continue;
                        float a0=X3[i*3],a1=X3[i*3+1],a2=X3[i*3+2];
                        float ac=__fmaf_rn(X3[n*3],a0,0.f);
                        ac=__fmaf_rn(X3[n*3+1],a1,ac);
                        ac=__fmaf_rn(X3[n*3+2],a2,ac);
                        float vv=__fsub_rn(__fsub_rn(__fmul_rn(2.0f,ac),xxn),xxr[i]);
                        if(vv>bvv){ bvv=vv; bii=i; }
                    }
                    chosen[j]=bii;
                    g_idx[((size_t)bq*NN+n)*KNB + j]=bii;
                }
            } else {
                float* rw = g_dist + ((size_t)bq*NN + n)*NN;
                for(int j=0;j<KNB;j++){
                    float bvv=-FLT_MAX; int bii=0;
                    for(int i=0;i<NN;i++){ float vv=rw[i]; if(vv>bvv){bvv=vv;bii=i;} }
                    g_idx[((size_t)bq*NN+n)*KNB + j]=bii;
                    rw[bii]=-FLT_MAX;
                }
            }
        }
    }
}

__global__ void __launch_bounds__(256) k_topk(){
    int n = blockIdx.x, bq = blockIdx.y;
    const float* row = g_dist + ((size_t)bq*NN + n)*NN;
    int tid = threadIdx.x, lane = tid&31, w = tid>>5;
    float v[8];
    {
        const float4* r4 = (const float4*)(row + tid*8);
        float4 q0 = r4[0], q1 = r4[1];
        v[0]=q0.x; v[1]=q0.y; v[2]=q0.z; v[3]=q0.w;
        v[4]=q1.x; v[5]=q1.y; v[6]=q1.z; v[7]=q1.w;
    }
    topk_select<0>(v, tid, lane, w, n, bq, nullptr, 0.f, nullptr);
}

__global__ void __launch_bounds__(256) k_topk3(){
    int n = blockIdx.x, bq = blockIdx.y;
    const float* X3 = g_xT + (size_t)bq*NN*3;
    const float* xxr = g_xx + (size_t)bq*NN;
    int tid = threadIdx.x, lane = tid&31, w = tid>>5;
    float c0 = X3[n*3], c1 = X3[n*3+1], c2 = X3[n*3+2];
    float xxn = xxr[n];
    float f[24];
    {
        const float4* p4 = (const float4*)(X3 + tid*24);
        #pragma unroll
        for(int q=0;q<6;q++){
            float4 t = p4[q];
            f[q*4+0]=t.x; f[q*4+1]=t.y; f[q*4+2]=t.z; f[q*4+3]=t.w;
        }
    }
    float v[8];
    #pragma unroll
    for(int q=0;q<8;q++){
        float ac = __fmaf_rn(c0, f[q*3+0], 0.f);
        ac = __fmaf_rn(c1, f[q*3+1], ac);
        ac = __fmaf_rn(c2, f[q*3+2], ac);
        v[q] = __fsub_rn(__fsub_rn(__fmul_rn(2.0f, ac), xxn), xxr[tid*8+q]);
    }
    topk_select<1>(v, tid, lane, w, n, bq, X3, xxn, xxr);
}

__global__ void k_ec_stats(int O){
    int o = blockIdx.x, tid = threadIdx.x;
    double s=0.0, ss=0.0;
    for(int b=0;b<BB;b++){
        size_t base = ((size_t)b*O + o)*NN;
        for(int n=tid;n<NN;n+=256){ s += g_ksum[base+n]; ss += g_ksq[base+n]; }
    }
    __shared__ double rs[256], rq[256];
    rs[tid]=s; rq[tid]=ss; __syncthreads();
    for(int st=128;st;st>>=1){ if(tid<st){ rs[tid]+=rs[tid+st]; rq[tid]+=rq[tid+st]; } __syncthreads(); }
    if(tid==0){
        double cnt = (double)BB*NN*KNB;
        double mean = rs[0]/cnt;
        double var  = rq[0]/cnt - mean*mean;
        g_prm[2*o]   = (float)mean;
        g_prm[2*o+1] = (float)var;
    }
}

__global__ void __launch_bounds__(256) k_ec_apply2(int O, int c0, float* __restrict__ xTout,
                            const float* __restrict__ gw, const float* __restrict__ bw){
    int o0 = blockIdx.x*32;
    int n0base = blockIdx.y*256;
    int b = blockIdx.z;
    __shared__ float pmm[32], psd[32], pg[32], pb[32];
    __shared__ int   puse[32];
    __shared__ float tile[64][33];
    int tid = threadIdx.x;
    if(tid<32){
        int o = o0+tid;
        float m = g_prm[2*o], vv = g_prm[2*o+1];
        pmm[tid]=m; psd[tid]=__fsqrt_rn(__fadd_rn(vv, EPSB));
        pg[tid]=gw[o]; pb[tid]=bw[o];
        puse[tid] = (gw[o]>=0.f) ? 1 : 0;
    }
    __syncthreads();
    for(int s=0;s<4;s++){
        int n0 = n0base + s*64;
        #pragma unroll
        for(int e=tid; e<2048; e+=256){
            int ol=e>>6, nl=e&63;
            const float* src = puse[ol] ? g_kmax : g_kmin;
            float vsrc = src[((size_t)b*O + o0+ol)*NN + n0+nl];
            float y = __fadd_rn(__fmul_rn(__fdiv_rn(__fsub_rn(vsrc, pmm[ol]), psd[ol]), pg[ol]), pb[ol]);
            y = (y>=0.f) ? y : __fmul_rn(NEGS, y);
            g_xcat[((size_t)b*512 + c0 + o0+ol)*NN + n0+nl] = y;
            tile[nl][ol] = y;
        }
        __syncthreads();
        #pragma unroll
        for(int e=tid; e<2048; e+=256){
            int nl=e>>5, ol=e&31;
            xTout[((size_t)b*NN + n0+nl)*O + o0+ol] = tile[nl][ol];
        }
        __syncthreads();
    }
}

__global__ void k_conv_stats(const float* __restrict__ h, int O){
    int o = blockIdx.x, tid = threadIdx.x;
    double s=0.0, ss=0.0;
    for(int b=0;b<BB;b++){
        size_t base = ((size_t)b*O + o)*NN;
        for(int n=tid;n<NN;n+=256){ float v=h[base+n]; s += v; ss += (double)v*v; }
    }
    __shared__ double rs[256], rq[256];
    rs[tid]=s; rq[tid]=ss; __syncthreads();
    for(int st=128;st;st>>=1){ if(tid<st){ rs[tid]+=rs[tid+st]; rq[tid]+=rq[tid+st]; } __syncthreads(); }
    if(tid==0){
        double cnt = (double)BB*NN;
        double mean = rs[0]/cnt;
        double var  = rq[0]/cnt - mean*mean;
        g_prm[2*o]   = (float)mean;
        g_prm[2*o+1] = (float)var;
    }
}

__global__ void k_conv_apply(float* __restrict__ h, int O,
                             const float* __restrict__ gw, const float* __restrict__ bw){
    int o = blockIdx.x, b = blockIdx.y;
    float m = g_prm[2*o], vv = g_prm[2*o+1];
    float gg = gw[o], bb = bw[o];
    float sd = __fsqrt_rn(__fadd_rn(vv, EPSB));
    float* p = h + ((size_t)b*O + o)*NN;
    for(int n=threadIdx.x;n<NN;n+=blockDim.x){
        float y = __fadd_rn(__fmul_rn(__fdiv_rn(__fsub_rn(p[n], m), sd), gg), bb);
        p[n] = (y>=0.f) ? y : __fmul_rn(NEGS, y);
    }
}

__global__ void __launch_bounds__(256) k_h5stats(const float* __restrict__ gw,
                                                 const float* __restrict__ bw){
    int o = blockIdx.x, tid = threadIdx.x, lane = tid&31, w = tid>>5;
    double s=0.0, ss=0.0;
    float bmx[BB], bmn[BB];
    #pragma unroll
    for(int b=0;b<BB;b++){ bmx[b]=-FLT_MAX; bmn[b]=FLT_MAX; }
    for(int b=0;b<BB;b++){
        size_t base = ((size_t)b*1024 + o)*NN;
        for(int n=tid;n<NN;n+=256){
            float v = g_h5[base+n];
            s += v; ss += (double)v*v;
            bmx[b]=fmaxf(bmx[b],v); bmn[b]=fminf(bmn[b],v);
        }
    }
    __shared__ double rs[256], rq[256];
    rs[tid]=s; rq[tid]=ss; __syncthreads();
    for(int st=128;st;st>>=1){ if(tid<st){ rs[tid]+=rs[tid+st]; rq[tid]+=rq[tid+st]; } __syncthreads(); }
    __shared__ float sx[8][BB], sn[8][BB];
    #pragma unroll
    for(int b=0;b<BB;b++){
        float mx=bmx[b], mn=bmn[b];
        #pragma unroll
        for(int off=16;off;off>>=1){
            mx=fmaxf(mx,__shfl_xor_sync(0xffffffffu,mx,off));
            mn=fminf(mn,__shfl_xor_sync(0xffffffffu,mn,off));
        }
        if(lane==0){ sx[w][b]=mx; sn[w][b]=mn; }
    }
    __shared__ float smean, svar;
    __syncthreads();
    if(tid==0){
        double cnt = (double)BB*NN;
        double mean = rs[0]/cnt;
        double var  = rq[0]/cnt - mean*mean;
        smean = (float)mean; svar = (float)var;
    }
    __syncthreads();
    if(tid<BB){
        int b = tid;
        float mx=sx[0][b], mn=sn[0][b];
        #pragma unroll
        for(int q=1;q<8;q++){ mx=fmaxf(mx,sx[q][b]); mn=fminf(mn,sn[q][b]); }
        float gg = gw[o];
        float src = (gg>=0.f) ? mx : mn;
        float sd = __fsqrt_rn(__fadd_rn(svar, EPSB));
        float y = __fadd_rn(__fmul_rn(__fdiv_rn(__fsub_rn(src, smean), sd), gg), bw[o]);
        y = (y>=0.f) ? y : __fmul_rn(NEGS, y);
        g_glob[b*1088 + o] = y;
    }
}

__global__ void k_lf(const float* __restrict__ l, const float* __restrict__ W,
                     const float* __restrict__ gw, const float* __restrict__ bw){
    int tid = threadIdx.x;
    int o = tid & 63, b = tid >> 6;
    __shared__ float hs[8][64];
    __shared__ float pm[64], pv[64];
    float s = 0.f;
    #pragma unroll
    for(int c=0;c<16;c++) s = __fmaf_rn(W[o*16 + c], l[b*16 + c], s);
    hs[b][o] = s;
    __syncthreads();
    if(tid < 64){
        float m = 0.f;
        #pragma unroll
        for(int q=0;q<8;q++) m = __fadd_rn(m, hs[q][tid]);
        m = __fdiv_rn(m, 8.f);
        float v = 0.f;
        #pragma unroll
        for(int q=0;q<8;q++){ float d = __fsub_rn(hs[q][tid], m); v = __fmaf_rn(d, d, v); }
        v = __fdiv_rn(v, 8.f);
        pm[tid] = m; pv[tid] = v;
    }
    __syncthreads();
    float sd = __fsqrt_rn(__fadd_rn(pv[o], EPSB));
    float y = __fadd_rn(__fmul_rn(__fdiv_rn(__fsub_rn(hs[b][o], pm[o]), sd), gw[o]), bw[o]);
    y = (y>=0.f) ? y : __fmul_rn(NEGS, y);
    g_glob[b*1088 + 1024 + o] = y;
}

__global__ void k_bias207(const float* __restrict__ W207){
    int b = blockIdx.x;
    __shared__ float gl[1088];
    for(int i=threadIdx.x;i<1088;i+=256) gl[i] = g_glob[b*1088 + i];
    __syncthreads();
    int o = threadIdx.x;
    float s = 0.f;
    for(int c=0;c<1088;c++) s = __fmaf_rn(W207[(size_t)o*1600 + c], gl[c], s);
    g_b207[b*256 + o] = s;
}

// ------------------------- launcher -------------------------
extern "C" void kernel_launch(void* const* d_in, const int* in_sizes, int n_in,
                              void* d_out, int out_size){
    (void)in_sizes; (void)n_in; (void)out_size;
    const float* x    = (const float*)d_in[0];
    const float* l    = (const float*)d_in[1];
    const float* Wec[4] = {(const float*)d_in[2],(const float*)d_in[5],(const float*)d_in[8],(const float*)d_in[11]};
    const float* gec[4] = {(const float*)d_in[3],(const float*)d_in[6],(const float*)d_in[9],(const float*)d_in[12]};
    const float* bec[4] = {(const float*)d_in[4],(const float*)d_in[7],(const float*)d_in[10],(const float*)d_in[13]};
    const float* W5   = (const float*)d_in[14]; const float* g5v  = (const float*)d_in[15]; const float* b5v  = (const float*)d_in[16];
    const float* W206 = (const float*)d_in[17]; const float* g206 = (const float*)d_in[18]; const float* b206 = (const float*)d_in[19];
    const float* W207 = (const float*)d_in[20]; const float* g207 = (const float*)d_in[21]; const float* b207 = (const float*)d_in[22];
    const float* W208 = (const float*)d_in[23]; const float* g208 = (const float*)d_in[24]; const float* b208 = (const float*)d_in[25];
    const float* W209 = (const float*)d_in[26]; const float* g209 = (const float*)d_in[27]; const float* b209 = (const float*)d_in[28];
    const float* W2010= (const float*)d_in[29];

    float *xT,*xxp,*xcat,*h5,*hb1,*hb2,*hb3,*b207p;
    int *idxp;
    cudaGetSymbolAddress((void**)&xT,   g_xT);
    cudaGetSymbolAddress((void**)&xxp,  g_xx);
    cudaGetSymbolAddress((void**)&idxp, g_idx);
    cudaGetSymbolAddress((void**)&xcat, g_xcat);
    cudaGetSymbolAddress((void**)&h5,   g_h5);
    cudaGetSymbolAddress((void**)&hb1,  g_hb1);
    cudaGetSymbolAddress((void**)&hb2,  g_hb2);
    cudaGetSymbolAddress((void**)&hb3,  g_hb3);
    cudaGetSymbolAddress((void**)&b207p,g_b207);

    const int Cin[4] = {3,64,64,128};
    const int Oo [4] = {64,64,128,256};
    const int c0 [4] = {0,64,128,256};

    k_tin<<<(BB*NN*3 + 255)/256, 256>>>(x);

    for(int li=0; li<4; li++){
        int C = Cin[li], O = Oo[li];
        k_xx<<<(BB*NN + 255)/256, 256>>>(C);
        if(li==0){
            k_topk3<<<dim3(NN, BB), 256>>>();
        } else {
            k_dgemm<<<dim3(NN/128, NN/128, BB), 256>>>(C, xT, xxp);
            k_topk<<<dim3(NN, BB), 256>>>();
        }
        // templated fused edge GEMM + k-reduce
        if(li==0)      k_egemm_t<3,  64,3><<<dim3(NN/8, 1, BB), 256>>>(64,  Wec[0], xT, idxp);
        else if(li==1) k_egemm_t<64, 64,3><<<dim3(NN/8, 1, BB), 256>>>(64,  Wec[1], xT, idxp);
        else if(li==2) k_egemm_t<64,128,2><<<dim3(NN/8, 1, BB), 256>>>(128, Wec[2], xT, idxp);
        else           k_egemm_t<128,128,2><<<dim3(NN/8, 2, BB), 256>>>(256, Wec[3], xT, idxp);
        k_ec_stats<<<O, 256>>>(O);
        k_ec_apply2<<<dim3(O/32, NN/256, BB), 256>>>(O, c0[li], xT, gec[li], bec[li]);
    }

    k_gemm<true,0><<<dim3(NN/128, 1024/128, BB), 256>>>(
        1024, NN, 512, W5, 512, 0, xcat, NN, (size_t)512*NN, h5, (size_t)1024*NN, nullptr);
    k_h5stats<<<1024, 256>>>(g5v, b5v);
    k_lf<<<1, 512>>>(l, W206, g206, b206);
    k_bias207<<<BB, 256>>>(W207);
    k_gemm<true,2><<<dim3(NN/128, 2, BB), 256>>>(
        256, NN, 512, W207 + 1088, 1600, 0, xcat, NN, (size_t)512*NN, hb1, (size_t)256*NN, b207p);
    k_conv_stats<<<256, 256>>>(hb1, 256);
    k_conv_apply<<<dim3(256, BB), 256>>>(hb1, 256, g207, b207);
    k_gemm<true,0><<<dim3(NN/128, 2, BB), 256>>>(
        256, NN, 256, W208, 256, 0, hb1, NN, (size_t)256*NN, hb2, (size_t)256*NN, nullptr);
    k_conv_stats<<<256, 256>>>(hb2, 256);
    k_conv_apply<<<dim3(256, BB), 256>>>(hb2, 256, g208, b208);
    k_gemm<true,0><<<dim3(NN/128, 1, BB), 256>>>(
        128, NN, 256, W209, 256, 0, hb2, NN, (size_t)256*NN, hb3, (size_t)128*NN, nullptr);
    k_conv_stats<<<128, 256>>>(hb3, 128);
    k_conv_apply<<<dim3(128, BB), 256>>>(hb3, 128, g209, b209);
    k_gemm<true,0><<<dim3(NN/128, 1, BB), 256>>>(
        50, NN, 128, W2010, 128, 0, hb3, NN, (size_t)128*NN, (float*)d_out, (size_t)50*NN, nullptr);
}

// round 13
// speedup vs baseline: 1.8769x; 1.2222x over previous
#include <cuda_runtime.h>
#include <cstdlib>
#include <cfloat>

#define BB 8
#define NN 2048
#define KNB 20
#define NEGS 0.2f
#define EPSB 1e-5f

__attribute__((constructor)) static void _eager_load(){ setenv("CUDA_MODULE_LOADING","EAGER",0); }

// ------------------------- scratch (device globals) -------------------------
__device__ float g_xT  [(size_t)BB*NN*256];
__device__ float g_xx  [BB*NN];
__device__ float g_dist[(size_t)BB*NN*NN];
__device__ int   g_idx [(size_t)BB*NN*KNB];
__device__ float g_kmax[(size_t)BB*256*NN];
__device__ float g_kmin[(size_t)BB*256*NN];
__device__ float g_ksum[(size_t)BB*256*NN];
__device__ float g_ksq [(size_t)BB*256*NN];
__device__ float g_base[(size_t)BB*256*NN];   // (W_b - W_a) @ ctr
__device__ float g_Wd  [256*128];             // W[:,C:2C] - W[:,:C]
__device__ float g_xcat[(size_t)BB*512*NN];
__device__ float g_h5  [(size_t)BB*1024*NN];
__device__ float g_hb1 [(size_t)BB*256*NN];
__device__ float g_hb2 [(size_t)BB*256*NN];
__device__ float g_hb3 [(size_t)BB*128*NN];
__device__ float g_glob[BB*1088];
__device__ float g_b207[BB*256];
__device__ float g_prm [2048];

// ------------------------- generic fp32 GEMM (pipelined) ---------------------
template<bool BT, int MODE>
__global__ void __launch_bounds__(256,2) k_gemm(
    int M, int Ncol, int Kd,
    const float* __restrict__ A, int lda, size_t asb,
    const float* __restrict__ Bp, int ldb, size_t bsb,
    float* __restrict__ Cp, size_t csb,
    const float* __restrict__ e0)
{
    const int BM=128, BN=128, BK=16;
    __shared__ float As[2][BK][BM+4];
    __shared__ float Bs[2][BK][BN+4];
    int b  = blockIdx.z;
    int m0 = blockIdx.y*BM, n0 = blockIdx.x*BN;
    A  += (size_t)b*asb;
    Bp += (size_t)b*bsb;
    Cp += (size_t)b*csb;
    int tid = threadIdx.x;
    int tx = tid%16, ty = tid/16;

    float acc[8][8];
    #pragma unroll
    for(int i=0;i<8;i++)
        #pragma unroll
        for(int j=0;j<8;j++) acc[i][j]=0.f;

    float ra[8], rb[8];

    auto fetchA = [&](int k0){
        #pragma unroll
        for(int i=0;i<8;i++){
            int e = tid + 256*i;
            int kk=e%BK, mm=e/BK;
            int gm=m0+mm, gk=k0+kk;
            ra[i] = (gm<M && gk<Kd) ? A[(size_t)gm*lda+gk] : 0.f;
        }
    };
    auto fetchB = [&](int k0){
        if(!BT){
            #pragma unroll
            for(int i=0;i<8;i++){
                int e = tid + 256*i;
                int kk=e%BK, nn=e/BK;
                int gn=n0+nn, gk=k0+kk;
                rb[i] = (gn<Ncol && gk<Kd) ? Bp[(size_t)gn*ldb+gk] : 0.f;
            }
        } else {
            #pragma unroll
            for(int i=0;i<8;i++){
                int e = tid + 256*i;
                int nn=e%BN, kk=e/BN;
                int gn=n0+nn, gk=k0+kk;
                rb[i] = (gn<Ncol && gk<Kd) ? Bp[(size_t)gk*ldb+gn] : 0.f;
            }
        }
    };
    auto store = [&](int buf){
        #pragma unroll
        for(int i=0;i<8;i++){
            int e = tid + 256*i;
            As[buf][e%BK][e/BK] = ra[i];
        }
        if(!BT){
            #pragma unroll
            for(int i=0;i<8;i++){
                int e = tid + 256*i;
                Bs[buf][e%BK][e/BK] = rb[i];
            }
        } else {
            #pragma unroll
            for(int i=0;i<8;i++){
                int e = tid + 256*i;
                Bs[buf][e/BN][e%BN] = rb[i];
            }
        }
    };

    int nk = (Kd + BK - 1)/BK;
    fetchA(0); fetchB(0);
    store(0);
    __syncthreads();

    for(int t=0;t<nk;t++){
        int cur = t&1;
        if(t+1<nk){ fetchA((t+1)*BK); fetchB((t+1)*BK); }
        #pragma unroll
        for(int kk=0;kk<BK;kk++){
            float a8[8], b8[8];
            #pragma unroll
            for(int i=0;i<8;i++) a8[i]=As[cur][kk][ty*8+i];
            #pragma unroll
            for(int j=0;j<8;j++) b8[j]=Bs[cur][kk][tx*8+j];
            #pragma unroll
            for(int i=0;i<8;i++)
                #pragma unroll
                for(int j=0;j<8;j++) acc[i][j] = __fmaf_rn(a8[i], b8[j], acc[i][j]);
        }
        if(t+1<nk){
            __syncthreads();
            store(1-cur);
            __syncthreads();
        }
    }

    #pragma unroll
    for(int i=0;i<8;i++){
        int gm = m0+ty*8+i;
        if(gm>=M) continue;
        #pragma unroll
        for(int j=0;j<8;j++){
            int gn = n0+tx*8+j;
            if(gn>=Ncol) continue;
            float v = acc[i][j];
            if(MODE==2) v = __fadd_rn(v, e0[(size_t)b*M+gm]);
            Cp[(size_t)gm*Ncol + gn] = v;
        }
    }
}

// -------- symmetric dist GEMM (layers 2-4) --------------------------------
__global__ void __launch_bounds__(256,2) k_dgemm(
    int Kd, const float* __restrict__ Xp, const float* __restrict__ e0)
{
    const int BK=16;
    if(blockIdx.x < blockIdx.y) return;
    __shared__ float pool[8448];
    #define ASM(buf,kk,mm) pool[(buf)*2112 + (kk)*132 + (mm)]
    #define BSM(buf,kk,nn) pool[4224 + (buf)*2112 + (kk)*132 + (nn)]
    int b  = blockIdx.z;
    int m0 = blockIdx.y*128, n0 = blockIdx.x*128;
    const float* A = Xp + (size_t)b*NN*Kd;
    float* Cp = g_dist + (size_t)b*NN*NN;
    const float* xxr = e0 + (size_t)b*NN;
    int tid = threadIdx.x;
    int tx = tid%16, ty = tid/16;

    float acc[8][8];
    #pragma unroll
    for(int i=0;i<8;i++)
        #pragma unroll
        for(int j=0;j<8;j++) acc[i][j]=0.f;

    float ra[8], rb[8];
    auto fetchA = [&](int k0){
        #pragma unroll
        for(int i=0;i<8;i++){
            int e = tid + 256*i;
            int kk=e&15, mm=e>>4;
            int gk=k0+kk;
            ra[i] = (gk<Kd) ? A[(size_t)(m0+mm)*Kd+gk] : 0.f;
        }
    };
    auto fetchB = [&](int k0){
        #pragma unroll
        for(int i=0;i<8;i++){
            int e = tid + 256*i;
            int kk=e&15, nn=e>>4;
            int gk=k0+kk;
            rb[i] = (gk<Kd) ? A[(size_t)(n0+nn)*Kd+gk] : 0.f;
        }
    };
    auto store = [&](int buf){
        #pragma unroll
        for(int i=0;i<8;i++){
            int e = tid + 256*i;
            ASM(buf, e&15, e>>4) = ra[i];
        }
        #pragma unroll
        for(int i=0;i<8;i++){
            int e = tid + 256*i;
            BSM(buf, e&15, e>>4) = rb[i];
        }
    };

    int nk = (Kd + BK - 1)/BK;
    fetchA(0); fetchB(0);
    store(0);
    __syncthreads();
    for(int t=0;t<nk;t++){
        int cur = t&1;
        if(t+1<nk){ fetchA((t+1)*BK); fetchB((t+1)*BK); }
        #pragma unroll
        for(int kk=0;kk<BK;kk++){
            float a8[8], b8[8];
            #pragma unroll
            for(int i=0;i<8;i++) a8[i]=ASM(cur,kk,ty*8+i);
            #pragma unroll
            for(int j=0;j<8;j++) b8[j]=BSM(cur,kk,tx*8+j);
            #pragma unroll
            for(int i=0;i<8;i++)
                #pragma unroll
                for(int j=0;j<8;j++) acc[i][j] = __fmaf_rn(a8[i], b8[j], acc[i][j]);
        }
        if(t+1<nk){
            __syncthreads();
            store(1-cur);
            __syncthreads();
        }
    }

    #pragma unroll
    for(int i=0;i<8;i++){
        int gm = m0+ty*8+i;
        float xm = xxr[gm];
        #pragma unroll
        for(int j=0;j<8;j++){
            int gn = n0+tx*8+j;
            float v = __fsub_rn(__fsub_rn(__fmul_rn(2.0f, acc[i][j]), xm), xxr[gn]);
            acc[i][j] = v;
            Cp[(size_t)gm*NN + gn] = v;
        }
    }
    if(blockIdx.x > blockIdx.y){
        for(int c=0;c<4;c++){
            __syncthreads();
            if((tx>>2)==c){
                int tl = tx&3;
                #pragma unroll
                for(int i=0;i<8;i++)
                    #pragma unroll
                    for(int j=0;j<8;j++)
                        pool[(tl*8+j)*132 + ty*8+i] = acc[i][j];
            }
            __syncthreads();
            #pragma unroll
            for(int q=0;q<16;q++){
                int e = tid + 256*q;
                int rr=e>>7, cc=e&127;
                Cp[(size_t)(n0+c*32+rr)*NN + m0+cc] = pool[rr*132+cc];
            }
        }
    }
    #undef ASM
    #undef BSM
}

// ------- L1 exact fused edge-conv GEMM + k-reduce (full 2C path) -----------
template<int C, int BM, int MAXB>
__global__ void __launch_bounds__(256,MAXB) k_egemm_t(
    int M,
    const float* __restrict__ A,
    const float* __restrict__ xTp,
    const int*   __restrict__ idxp)
{
    const int BN=160, BK=16;
    const int Kd = 2*C;
    const int NK = (Kd + BK - 1)/BK;
    const int TM = BM/16;
    const int NA = BM*BK/256;
    __shared__ float As[2][BK][BM+4];
    __shared__ float Bs[2][BK][BN+4];
    __shared__ int   s_moff[BN];
    __shared__ int   s_poff[BN];
    int b  = blockIdx.z;
    int m0 = blockIdx.y*BM;
    int p0 = blockIdx.x*8;
    xTp  += (size_t)b*NN*C;
    idxp += (size_t)b*NN*KNB;
    int tid = threadIdx.x;
    int tx = tid%16, ty = tid/16;

    if(tid < BN){
        int pt = tid/KNB;
        int kq = tid - pt*KNB;
        s_poff[tid] = (p0+pt)*C;
        s_moff[tid] = idxp[(size_t)(p0+pt)*KNB + kq]*C;
    }
    __syncthreads();

    float acc[TM][10];
    #pragma unroll
    for(int i=0;i<TM;i++)
        #pragma unroll
        for(int j=0;j<10;j++) acc[i][j]=0.f;

    float ra[NA], rb[10];
    int kkme = tid & 15;

    auto fetchA = [&](int k0){
        #pragma unroll
        for(int i=0;i<NA;i++){
            int e = tid + 256*i;
            int kk=e&15, mm=e>>4;
            int gk=k0+kk;
            ra[i] = (gk<Kd) ? A[(size_t)(m0+mm)*Kd+gk] : 0.f;
        }
    };
    auto fetchB = [&](int k0){
        int gk = k0 + kkme;
        #pragma unroll
        for(int i=0;i<10;i++){
            int nn = (tid>>4) + 16*i;
            float val = 0.f;
            if(gk < Kd){
                int cc = (gk<C) ? gk : gk-C;
                float ctr = xTp[s_poff[nn] + cc];
                if(gk<C) val = __fsub_rn(xTp[s_moff[nn] + cc], ctr);
                else     val = ctr;
            }
            rb[i] = val;
        }
    };
    auto store = [&](int buf){
        #pragma unroll
        for(int i=0;i<NA;i++){
            int e = tid + 256*i;
            As[buf][e&15][e>>4] = ra[i];
        }
        #pragma unroll
        for(int i=0;i<10;i++){
            int nn = (tid>>4) + 16*i;
            Bs[buf][kkme][nn] = rb[i];
        }
    };

    fetchA(0); fetchB(0);
    store(0);
    __syncthreads();

    #pragma unroll 1
    for(int t=0;t<NK;t++){
        int cur = t&1;
        if(t+1<NK){ fetchA((t+1)*BK); fetchB((t+1)*BK); }
        #pragma unroll
        for(int kk=0;kk<BK;kk++){
            float am[TM], b10[10];
            #pragma unroll
            for(int i=0;i<TM;i++) am[i]=As[cur][kk][ty*TM+i];
            #pragma unroll
            for(int j=0;j<10;j++) b10[j]=Bs[cur][kk][tx*10+j];
            #pragma unroll
            for(int i=0;i<TM;i++)
                #pragma unroll
                for(int j=0;j<10;j++) acc[i][j] = __fmaf_rn(am[i], b10[j], acc[i][j]);
        }
        if(t+1<NK){
            __syncthreads();
            store(1-cur);
            __syncthreads();
        }
    }

    int O = M;
    #pragma unroll
    for(int i=0;i<TM;i++){
        float mx=-FLT_MAX, mn=FLT_MAX, sm=0.f, sq=0.f;
        #pragma unroll
        for(int j=0;j<10;j++){
            float h = acc[i][j];
            mx = fmaxf(mx,h); mn = fminf(mn,h);
            sm = __fadd_rn(sm,h); sq = __fmaf_rn(h,h,sq);
        }
        #pragma unroll
        for(int j=0;j<10;j++){
            float h = __shfl_xor_sync(0xffffffffu, acc[i][j], 1);
            mx = fmaxf(mx,h); mn = fminf(mn,h);
            sm = __fadd_rn(sm,h); sq = __fmaf_rn(h,h,sq);
        }
        int gm = m0 + ty*TM + i;
        if((tx&1)==0){
            int point = p0 + (tx>>1);
            size_t base = ((size_t)b*O + gm)*NN + point;
            g_kmax[base]=mx; g_kmin[base]=mn; g_ksum[base]=sm; g_ksq[base]=sq;
        }
    }
}

// ------- SPLIT edge-conv GEMM (layers 2-4): h = W_a @ nbr + base -----------
// Kd = C (half of the exact path); base added before the ascending-k reduce.
template<int C, int BM, int MAXB>
__global__ void __launch_bounds__(256,MAXB) k_egemm_s(
    int M,
    const float* __restrict__ A,         // W [O, 2C]; uses first C columns
    const float* __restrict__ xTp,
    const int*   __restrict__ idxp)
{
    const int BN=160, BK=16;
    const int NK = C/BK;
    const int TM = BM/16;
    const int NA = BM*BK/256;
    __shared__ float As[2][BK][BM+4];
    __shared__ float Bs[2][BK][BN+4];
    __shared__ int   s_moff[BN];
    int b  = blockIdx.z;
    int m0 = blockIdx.y*BM;
    int p0 = blockIdx.x*8;
    xTp  += (size_t)b*NN*C;
    idxp += (size_t)b*NN*KNB;
    int tid = threadIdx.x;
    int tx = tid%16, ty = tid/16;

    if(tid < BN){
        int pt = tid/KNB;
        int kq = tid - pt*KNB;
        s_moff[tid] = idxp[(size_t)(p0+pt)*KNB + kq]*C;
    }
    __syncthreads();

    float acc[TM][10];
    #pragma unroll
    for(int i=0;i<TM;i++)
        #pragma unroll
        for(int j=0;j<10;j++) acc[i][j]=0.f;

    float ra[NA], rb[10];
    int kkme = tid & 15;

    auto fetchA = [&](int k0){
        #pragma unroll
        for(int i=0;i<NA;i++){
            int e = tid + 256*i;
            int kk=e&15, mm=e>>4;
            ra[i] = A[(size_t)(m0+(e>>4))*(2*C) + k0+kk];
            (void)mm;
        }
    };
    auto fetchB = [&](int k0){
        int cc = k0 + kkme;
        #pragma unroll
        for(int i=0;i<10;i++){
            int nn = (tid>>4) + 16*i;
            rb[i] = xTp[s_moff[nn] + cc];
        }
    };
    auto store = [&](int buf){
        #pragma unroll
        for(int i=0;i<NA;i++){
            int e = tid + 256*i;
            As[buf][e&15][e>>4] = ra[i];
        }
        #pragma unroll
        for(int i=0;i<10;i++){
            int nn = (tid>>4) + 16*i;
            Bs[buf][kkme][nn] = rb[i];
        }
    };

    fetchA(0); fetchB(0);
    store(0);
    __syncthreads();

    #pragma unroll 1
    for(int t=0;t<NK;t++){
        int cur = t&1;
        if(t+1<NK){ fetchA((t+1)*BK); fetchB((t+1)*BK); }
        #pragma unroll
        for(int kk=0;kk<BK;kk++){
            float am[TM], b10[10];
            #pragma unroll
            for(int i=0;i<TM;i++) am[i]=As[cur][kk][ty*TM+i];
            #pragma unroll
            for(int j=0;j<10;j++) b10[j]=Bs[cur][kk][tx*10+j];
            #pragma unroll
            for(int i=0;i<TM;i++)
                #pragma unroll
                for(int j=0;j<10;j++) acc[i][j] = __fmaf_rn(am[i], b10[j], acc[i][j]);
        }
        if(t+1<NK){
            __syncthreads();
            store(1-cur);
            __syncthreads();
        }
    }

    int O = M;
    int point = p0 + (tx>>1);
    #pragma unroll
    for(int i=0;i<TM;i++){
        int gm = m0 + ty*TM + i;
        float bsv = g_base[((size_t)b*O + gm)*NN + point];
        float mx=-FLT_MAX, mn=FLT_MAX, sm=0.f, sq=0.f;
        #pragma unroll
        for(int j=0;j<10;j++){
            float h = __fadd_rn(acc[i][j], bsv);
            mx = fmaxf(mx,h); mn = fminf(mn,h);
            sm = __fadd_rn(sm,h); sq = __fmaf_rn(h,h,sq);
        }
        #pragma unroll
        for(int j=0;j<10;j++){
            float h = __fadd_rn(__shfl_xor_sync(0xffffffffu, acc[i][j], 1), bsv);
            mx = fmaxf(mx,h); mn = fminf(mn,h);
            sm = __fadd_rn(sm,h); sq = __fmaf_rn(h,h,sq);
        }
        if((tx&1)==0){
            size_t base = ((size_t)b*O + gm)*NN + point;
            g_kmax[base]=mx; g_kmin[base]=mn; g_ksum[base]=sm; g_ksq[base]=sq;
        }
    }
}

// ------------------------- small kernels -------------------------

__global__ void k_tin(const float* __restrict__ x){
    int i = blockIdx.x*blockDim.x + threadIdx.x;
    if(i >= BB*NN*3) return;
    int c = i%3; int n = (i/3)%NN; int b = i/(3*NN);
    g_xT[i] = x[((size_t)b*3 + c)*NN + n];
}

__global__ void k_xx(int C){
    int p = blockIdx.x*blockDim.x + threadIdx.x;
    if(p >= BB*NN) return;
    const float* v = g_xT + (size_t)p*C;
    float s = 0.f;
    for(int c=0;c<C;c++) s = __fadd_rn(s, __fmul_rn(v[c], v[c]));
    g_xx[p] = s;
}

__global__ void k_wdiff(const float* __restrict__ W, int O, int C){
    int i = blockIdx.x*blockDim.x + threadIdx.x;
    if(i >= O*C) return;
    int o = i/C, c = i%C;
    g_Wd[i] = __fsub_rn(W[(size_t)o*2*C + C + c], W[(size_t)o*2*C + c]);
}

// shared top-k selection body (given v[8] per thread).
template<int FUSED3>
__device__ __forceinline__ void topk_select(
    float* v, int tid, int lane, int w, int n, int bq,
    const float* __restrict__ X3, float xxn, const float* __restrict__ xxr)
{
    __shared__ float swmx[8], swmn[8];
    __shared__ int hist8[8][256];
    __shared__ int hist[256];
    __shared__ unsigned long long cand[256];
    __shared__ int s_cnt, s_B, s_size;
    __shared__ float s_lo, s_hi;
    int base = tid*8;

    float mx=v[0], mn=v[0];
    #pragma unroll
    for(int t=1;t<8;t++){ mx=fmaxf(mx,v[t]); mn=fminf(mn,v[t]); }
    #pragma unroll
    for(int o=16;o;o>>=1){
        mx=fmaxf(mx,__shfl_xor_sync(0xffffffffu,mx,o));
        mn=fminf(mn,__shfl_xor_sync(0xffffffffu,mn,o));
    }
    if(lane==0){ swmx[w]=mx; swmn[w]=mn; }
    #pragma unroll
    for(int q=0;q<8;q++) hist8[q][tid]=0;
    __syncthreads();
    if(tid==0){
        float hx=swmx[0], hn=swmn[0];
        #pragma unroll
        for(int q=1;q<8;q++){ hx=fmaxf(hx,swmx[q]); hn=fminf(hn,swmn[q]); }
        s_lo=hn; s_hi=hx; s_cnt=0;
    }
    __syncthreads();
    float lo=s_lo, hi=s_hi;
    float scale = (hi>lo) ? 255.0f/(hi-lo) : 0.0f;
    int bk[8];
    #pragma unroll
    for(int t=0;t<8;t++){
        int bb = (int)((v[t]-lo)*scale);
        bb = max(0, min(255, bb));
        bk[t]=bb;
        atomicAdd(&hist8[w][bb],1);
    }
    __syncthreads();
    {
        int hsum = 0;
        #pragma unroll
        for(int q=0;q<8;q++) hsum += hist8[q][tid];
        hist[tid] = hsum;
    }
    __syncthreads();
    if(w==0){
        int cs = 0;
        #pragma unroll
        for(int t=0;t<8;t++) cs += hist[lane*8+t];
        int rs = cs;
        #pragma unroll
        for(int o=1;o<32;o<<=1){
            int t2 = __shfl_down_sync(0xffffffffu, rs, o);
            if(lane+o<32) rs += t2;
        }
        int sufx = rs - cs;
        if(rs >= KNB && sufx < KNB){
            int run = sufx, Bv = lane*8;
            for(int j=7;j>=0;j--){
                run += hist[lane*8+j];
                if(run >= KNB){ Bv = lane*8+j; break; }
            }
            s_B = Bv;
        }
    }
    __syncthreads();
    int B = s_B;
    #pragma unroll
    for(int t=0;t<8;t++){
        if(bk[t] >= B){
            int pos = atomicAdd(&s_cnt,1);
            if(pos<256){
                unsigned int u = __float_as_uint(v[t]);
                u = (u & 0x80000000u) ? ~u : (u | 0x80000000u);
                cand[pos] = ((unsigned long long)u<<32) | (unsigned int)(~(base+t));
            }
        }
    }
    __syncthreads();
    int cnt = s_cnt;
    if(cnt<=256){
        if(tid==0){
            int sz = 32;
            while(sz < cnt) sz <<= 1;
            s_size = sz;
        }
        __syncthreads();
        int sz = s_size;
        if(tid<sz && tid>=cnt) cand[tid]=0ull;
        __syncthreads();
        for(int k=2;k<=sz;k<<=1){
            for(int j=k>>1;j>0;j>>=1){
                int ixj = tid ^ j;
                if(ixj > tid && ixj < sz && tid < sz){
                    bool up = ((tid & k) == 0);
                    unsigned long long a=cand[tid], c=cand[ixj];
                    if( (a > c) == up ){ cand[tid]=c; cand[ixj]=a; }
                }
                __syncthreads();
            }
        }
        if(tid<KNB)
            g_idx[((size_t)bq*NN+n)*KNB + tid] = (int)(~(unsigned int)cand[sz-1-tid]);
    } else {
        if(tid==0){
            if(FUSED3){
                int chosen[KNB];
                for(int j=0;j<KNB;j++){
                    float bvv=-FLT_MAX; int bii=0;
                    for(int i=0;i<NN;i++){
                        bool skip=false;
                        for(int q=0;q<j;q++) if(chosen[q]==i){ skip=true; break; }
                        if(skip) continue;
                        float a0=X3[i*3],a1=X3[i*3+1],a2=X3[i*3+2];
                        float ac=__fmaf_rn(X3[n*3],a0,0.f);
                        ac=__fmaf_rn(X3[n*3+1],a1,ac);
                        ac=__fmaf_rn(X3[n*3+2],a2,ac);
                        float vv=__fsub_rn(__fsub_rn(__fmul_rn(2.0f,ac),xxn),xxr[i]);
                        if(vv>bvv){ bvv=vv; bii=i; }
                    }
                    chosen[j]=bii;
                    g_idx[((size_t)bq*NN+n)*KNB + j]=bii;
                }
            } else {
                float* rw = g_dist + ((size_t)bq*NN + n)*NN;
                for(int j=0;j<KNB;j++){
                    float bvv=-FLT_MAX; int bii=0;
                    for(int i=0;i<NN;i++){ float vv=rw[i]; if(vv>bvv){bvv=vv;bii=i;} }
                    g_idx[((size_t)bq*NN+n)*KNB + j]=bii;
                    rw[bii]=-FLT_MAX;
                }
            }
        }
    }
}

__global__ void __launch_bounds__(256) k_topk(){
    int n = blockIdx.x, bq = blockIdx.y;
    const float* row = g_dist + ((size_t)bq*NN + n)*NN;
    int tid = threadIdx.x, lane = tid&31, w = tid>>5;
    float v[8];
    {
        const float4* r4 = (const float4*)(row + tid*8);
        float4 q0 = r4[0], q1 = r4[1];
        v[0]=q0.x; v[1]=q0.y; v[2]=q0.z; v[3]=q0.w;
        v[4]=q1.x; v[5]=q1.y; v[6]=q1.z; v[7]=q1.w;
    }
    topk_select<0>(v, tid, lane, w, n, bq, nullptr, 0.f, nullptr);
}

__global__ void __launch_bounds__(256) k_topk3(){
    int n = blockIdx.x, bq = blockIdx.y;
    const float* X3 = g_xT + (size_t)bq*NN*3;
    const float* xxr = g_xx + (size_t)bq*NN;
    int tid = threadIdx.x, lane = tid&31, w = tid>>5;
    float c0 = X3[n*3], c1 = X3[n*3+1], c2 = X3[n*3+2];
    float xxn = xxr[n];
    float f[24];
    {
        const float4* p4 = (const float4*)(X3 + tid*24);
        #pragma unroll
        for(int q=0;q<6;q++){
            float4 t = p4[q];
            f[q*4+0]=t.x; f[q*4+1]=t.y; f[q*4+2]=t.z; f[q*4+3]=t.w;
        }
    }
    float v[8];
    #pragma unroll
    for(int q=0;q<8;q++){
        float ac = __fmaf_rn(c0, f[q*3+0], 0.f);
        ac = __fmaf_rn(c1, f[q*3+1], ac);
        ac = __fmaf_rn(c2, f[q*3+2], ac);
        v[q] = __fsub_rn(__fsub_rn(__fmul_rn(2.0f, ac), xxn), xxr[tid*8+q]);
    }
    topk_select<1>(v, tid, lane, w, n, bq, X3, xxn, xxr);
}

__global__ void k_ec_stats(int O){
    int o = blockIdx.x, tid = threadIdx.x;
    double s=0.0, ss=0.0;
    for(int b=0;b<BB;b++){
        size_t base = ((size_t)b*O + o)*NN;
        for(int n=tid;n<NN;n+=256){ s += g_ksum[base+n]; ss += g_ksq[base+n]; }
    }
    __shared__ double rs[256], rq[256];
    rs[tid]=s; rq[tid]=ss; __syncthreads();
    for(int st=128;st;st>>=1){ if(tid<st){ rs[tid]+=rs[tid+st]; rq[tid]+=rq[tid+st]; } __syncthreads(); }
    if(tid==0){
        double cnt = (double)BB*NN*KNB;
        double mean = rs[0]/cnt;
        double var  = rq[0]/cnt - mean*mean;
        g_prm[2*o]   = (float)mean;
        g_prm[2*o+1] = (float)var;
    }
}

__global__ void __launch_bounds__(256) k_ec_apply2(int O, int c0, float* __restrict__ xTout,
                            const float* __restrict__ gw, const float* __restrict__ bw){
    int o0 = blockIdx.x*32;
    int n0base = blockIdx.y*256;
    int b = blockIdx.z;
    __shared__ float pmm[32], psd[32], pg[32], pb[32];
    __shared__ int   puse[32];
    __shared__ float tile[64][33];
    int tid = threadIdx.x;
    if(tid<32){
        int o = o0+tid;
        float m = g_prm[2*o], vv = g_prm[2*o+1];
        pmm[tid]=m; psd[tid]=__fsqrt_rn(__fadd_rn(vv, EPSB));
        pg[tid]=gw[o]; pb[tid]=bw[o];
        puse[tid] = (gw[o]>=0.f) ? 1 : 0;
    }
    __syncthreads();
    for(int s=0;s<4;s++){
        int n0 = n0base + s*64;
        #pragma unroll
        for(int e=tid; e<2048; e+=256){
            int ol=e>>6, nl=e&63;
            const float* src = puse[ol] ? g_kmax : g_kmin;
            float vsrc = src[((size_t)b*O + o0+ol)*NN + n0+nl];
            float y = __fadd_rn(__fmul_rn(__fdiv_rn(__fsub_rn(vsrc, pmm[ol]), psd[ol]), pg[ol]), pb[ol]);
            y = (y>=0.f) ? y : __fmul_rn(NEGS, y);
            g_xcat[((size_t)b*512 + c0 + o0+ol)*NN + n0+nl] = y;
            tile[nl][ol] = y;
        }
        __syncthreads();
        #pragma unroll
        for(int e=tid; e<2048; e+=256){
            int nl=e>>5, ol=e&31;
            xTout[((size_t)b*NN + n0+nl)*O + o0+ol] = tile[nl][ol];
        }
        __syncthreads();
    }
}

__global__ void k_conv_stats(const float* __restrict__ h, int O){
    int o = blockIdx.x, tid = threadIdx.x;
    double s=0.0, ss=0.0;
    for(int b=0;b<BB;b++){
        size_t base = ((size_t)b*O + o)*NN;
        for(int n=tid;n<NN;n+=256){ float v=h[base+n]; s += v; ss += (double)v*v; }
    }
    __shared__ double rs[256], rq[256];
    rs[tid]=s; rq[tid]=ss; __syncthreads();
    for(int st=128;st;st>>=1){ if(tid<st){ rs[tid]+=rs[tid+st]; rq[tid]+=rq[tid+st]; } __syncthreads(); }
    if(tid==0){
        double cnt = (double)BB*NN;
        double mean = rs[0]/cnt;
        double var  = rq[0]/cnt - mean*mean;
        g_prm[2*o]   = (float)mean;
        g_prm[2*o+1] = (float)var;
    }
}

__global__ void k_conv_apply(float* __restrict__ h, int O,
                             const float* __restrict__ gw, const float* __restrict__ bw){
    int o = blockIdx.x, b = blockIdx.y;
    float m = g_prm[2*o], vv = g_prm[2*o+1];
    float gg = gw[o], bb = bw[o];
    float sd = __fsqrt_rn(__fadd_rn(vv, EPSB));
    float* p = h + ((size_t)b*O + o)*NN;
    for(int n=threadIdx.x;n<NN;n+=blockDim.x){
        float y = __fadd_rn(__fmul_rn(__fdiv_rn(__fsub_rn(p[n], m), sd), gg), bb);
        p[n] = (y>=0.f) ? y : __fmul_rn(NEGS, y);
    }
}

__global__ void __launch_bounds__(256) k_h5stats(const float* __restrict__ gw,
                                                 const float* __restrict__ bw){
    int o = blockIdx.x, tid = threadIdx.x, lane = tid&31, w = tid>>5;
    double s=0.0, ss=0.0;
    float bmx[BB], bmn[BB];
    #pragma unroll
    for(int b=0;b<BB;b++){ bmx[b]=-FLT_MAX; bmn[b]=FLT_MAX; }
    for(int b=0;b<BB;b++){
        size_t base = ((size_t)b*1024 + o)*NN;
        for(int n=tid;n<NN;n+=256){
            float v = g_h5[base+n];
            s += v; ss += (double)v*v;
            bmx[b]=fmaxf(bmx[b],v); bmn[b]=fminf(bmn[b],v);
        }
    }
    __shared__ double rs[256], rq[256];
    rs[tid]=s; rq[tid]=ss; __syncthreads();
    for(int st=128;st;st>>=1){ if(tid<st){ rs[tid]+=rs[tid+st]; rq[tid]+=rq[tid+st]; } __syncthreads(); }
    __shared__ float sx[8][BB], sn[8][BB];
    #pragma unroll
    for(int b=0;b<BB;b++){
        float mx=bmx[b], mn=bmn[b];
        #pragma unroll
        for(int off=16;off;off>>=1){
            mx=fmaxf(mx,__shfl_xor_sync(0xffffffffu,mx,off));
            mn=fminf(mn,__shfl_xor_sync(0xffffffffu,mn,off));
        }
        if(lane==0){ sx[w][b]=mx; sn[w][b]=mn; }
    }
    __shared__ float smean, svar;
    __syncthreads();
    if(tid==0){
        double cnt = (double)BB*NN;
        double mean = rs[0]/cnt;
        double var  = rq[0]/cnt - mean*mean;
        smean = (float)mean; svar = (float)var;
    }
    __syncthreads();
    if(tid<BB){
        int b = tid;
        float mx=sx[0][b], mn=sn[0][b];
        #pragma unroll
        for(int q=1;q<8;q++){ mx=fmaxf(mx,sx[q][b]); mn=fminf(mn,sn[q][b]); }
        float gg = gw[o];
        float src = (gg>=0.f) ? mx : mn;
        float sd = __fsqrt_rn(__fadd_rn(svar, EPSB));
        float y = __fadd_rn(__fmul_rn(__fdiv_rn(__fsub_rn(src, smean), sd), gg), bw[o]);
        y = (y>=0.f) ? y : __fmul_rn(NEGS, y);
        g_glob[b*1088 + o] = y;
    }
}

__global__ void k_lf(const float* __restrict__ l, const float* __restrict__ W,
                     const float* __restrict__ gw, const float* __restrict__ bw){
    int tid = threadIdx.x;
    int o = tid & 63, b = tid >> 6;
    __shared__ float hs[8][64];
    __shared__ float pm[64], pv[64];
    float s = 0.f;
    #pragma unroll
    for(int c=0;c<16;c++) s = __fmaf_rn(W[o*16 + c], l[b*16 + c], s);
    hs[b][o] = s;
    __syncthreads();
    if(tid < 64){
        float m = 0.f;
        #pragma unroll
        for(int q=0;q<8;q++) m = __fadd_rn(m, hs[q][tid]);
        m = __fdiv_rn(m, 8.f);
        float v = 0.f;
        #pragma unroll
        for(int q=0;q<8;q++){ float d = __fsub_rn(hs[q][tid], m); v = __fmaf_rn(d, d, v); }
        v = __fdiv_rn(v, 8.f);
        pm[tid] = m; pv[tid] = v;
    }
    __syncthreads();
    float sd = __fsqrt_rn(__fadd_rn(pv[o], EPSB));
    float y = __fadd_rn(__fmul_rn(__fdiv_rn(__fsub_rn(hs[b][o], pm[o]), sd), gw[o]), bw[o]);
    y = (y>=0.f) ? y : __fmul_rn(NEGS, y);
    g_glob[b*1088 + 1024 + o] = y;
}

__global__ void k_bias207(const float* __restrict__ W207){
    int b = blockIdx.x;
    __shared__ float gl[1088];
    for(int i=threadIdx.x;i<1088;i+=256) gl[i] = g_glob[b*1088 + i];
    __syncthreads();
    int o = threadIdx.x;
    float s = 0.f;
    for(int c=0;c<1088;c++) s = __fmaf_rn(W207[(size_t)o*1600 + c], gl[c], s);
    g_b207[b*256 + o] = s;
}

// ------------------------- launcher -------------------------
extern "C" void kernel_launch(void* const* d_in, const int* in_sizes, int n_in,
                              void* d_out, int out_size){
    (void)in_sizes; (void)n_in; (void)out_size;
    const float* x    = (const float*)d_in[0];
    const float* l    = (const float*)d_in[1];
    const float* Wec[4] = {(const float*)d_in[2],(const float*)d_in[5],(const float*)d_in[8],(const float*)d_in[11]};
    const float* gec[4] = {(const float*)d_in[3],(const float*)d_in[6],(const float*)d_in[9],(const float*)d_in[12]};
    const float* bec[4] = {(const float*)d_in[4],(const float*)d_in[7],(const float*)d_in[10],(const float*)d_in[13]};
    const float* W5   = (const float*)d_in[14]; const float* g5v  = (const float*)d_in[15]; const float* b5v  = (const float*)d_in[16];
    const float* W206 = (const float*)d_in[17]; const float* g206 = (const float*)d_in[18]; const float* b206 = (const float*)d_in[19];
    const float* W207 = (const float*)d_in[20]; const float* g207 = (const float*)d_in[21]; const float* b207 = (const float*)d_in[22];
    const float* W208 = (const float*)d_in[23]; const float* g208 = (const float*)d_in[24]; const float* b208 = (const float*)d_in[25];
    const float* W209 = (const float*)d_in[26]; const float* g209 = (const float*)d_in[27]; const float* b209 = (const float*)d_in[28];
    const float* W2010= (const float*)d_in[29];

    float *xT,*xxp,*xcat,*h5,*hb1,*hb2,*hb3,*b207p,*basep,*Wdp;
    int *idxp;
    cudaGetSymbolAddress((void**)&xT,   g_xT);
    cudaGetSymbolAddress((void**)&xxp,  g_xx);
    cudaGetSymbolAddress((void**)&idxp, g_idx);
    cudaGetSymbolAddress((void**)&xcat, g_xcat);
    cudaGetSymbolAddress((void**)&h5,   g_h5);
    cudaGetSymbolAddress((void**)&hb1,  g_hb1);
    cudaGetSymbolAddress((void**)&hb2,  g_hb2);
    cudaGetSymbolAddress((void**)&hb3,  g_hb3);
    cudaGetSymbolAddress((void**)&b207p,g_b207);
    cudaGetSymbolAddress((void**)&basep,g_base);
    cudaGetSymbolAddress((void**)&Wdp,  g_Wd);

    const int Cin[4] = {3,64,64,128};
    const int Oo [4] = {64,64,128,256};
    const int c0 [4] = {0,64,128,256};

    k_tin<<<(BB*NN*3 + 255)/256, 256>>>(x);

    for(int li=0; li<4; li++){
        int C = Cin[li], O = Oo[li];
        k_xx<<<(BB*NN + 255)/256, 256>>>(C);
        if(li==0){
            k_topk3<<<dim3(NN, BB), 256>>>();
        } else {
            k_dgemm<<<dim3(NN/128, NN/128, BB), 256>>>(C, xT, xxp);
            k_topk<<<dim3(NN, BB), 256>>>();
        }
        if(li==0){
            k_egemm_t<3,64,3><<<dim3(NN/8, 1, BB), 256>>>(64, Wec[0], xT, idxp);
        } else {
            // split: base = (W_b - W_a) @ ctr, then h = W_a @ nbr + base
            k_wdiff<<<(O*C + 255)/256, 256>>>(Wec[li], O, C);
            k_gemm<false,0><<<dim3(NN/128, (O+127)/128, BB), 256>>>(
                O, NN, C, Wdp, C, 0, xT, C, (size_t)NN*C, basep, (size_t)O*NN, nullptr);
            if(li==1)      k_egemm_s<64, 64,3><<<dim3(NN/8, 1, BB), 256>>>(64,  Wec[1], xT, idxp);
            else if(li==2) k_egemm_s<64,128,2><<<dim3(NN/8, 1, BB), 256>>>(128, Wec[2], xT, idxp);
            else           k_egemm_s<128,128,2><<<dim3(NN/8, 2, BB), 256>>>(256, Wec[3], xT, idxp);
        }
        k_ec_stats<<<O, 256>>>(O);
        k_ec_apply2<<<dim3(O/32, NN/256, BB), 256>>>(O, c0[li], xT, gec[li], bec[li]);
    }

    k_gemm<true,0><<<dim3(NN/128, 1024/128, BB), 256>>>(
        1024, NN, 512, W5, 512, 0, xcat, NN, (size_t)512*NN, h5, (size_t)1024*NN, nullptr);
    k_h5stats<<<1024, 256>>>(g5v, b5v);
    k_lf<<<1, 512>>>(l, W206, g206, b206);
    k_bias207<<<BB, 256>>>(W207);
    k_gemm<true,2><<<dim3(NN/128, 2, BB), 256>>>(
        256, NN, 512, W207 + 1088, 1600, 0, xcat, NN, (size_t)512*NN, hb1, (size_t)256*NN, b207p);
    k_conv_stats<<<256, 256>>>(hb1, 256);
    k_conv_apply<<<dim3(256, BB), 256>>>(hb1, 256, g207, b207);
    k_gemm<true,0><<<dim3(NN/128, 2, BB), 256>>>(
        256, NN, 256, W208, 256, 0, hb1, NN, (size_t)256*NN, hb2, (size_t)256*NN, nullptr);
    k_conv_stats<<<256, 256>>>(hb2, 256);
    k_conv_apply<<<dim3(256, BB), 256>>>(hb2, 256, g208, b208);
    k_gemm<true,0><<<dim3(NN/128, 1, BB), 256>>>(
        128, NN, 256, W209, 256, 0, hb2, NN, (size_t)256*NN, hb3, (size_t)128*NN, nullptr);
    k_conv_stats<<<128, 256>>>(hb3, 128);
    k_conv_apply<<<dim3(128, BB), 256>>>(hb3, 128, g209, b209);
    k_gemm<true,0><<<dim3(NN/128, 1, BB), 256>>>(
        50, NN, 128, W2010, 128, 0, hb3, NN, (size_t)128*NN, (float*)d_out, (size_t)50*NN, nullptr);
}

// round 15
// speedup vs baseline: 1.9472x; 1.0374x over previous
#include <cuda_runtime.h>
#include <cstdlib>
#include <cstdint>
#include <cfloat>

#define BB 8
#define NN 2048
#define KNB 20
#define NEGS 0.2f
#define EPSB 1e-5f

__attribute__((constructor)) static void _eager_load(){ setenv("CUDA_MODULE_LOADING","EAGER",0); }

// ------------------------- scratch (device globals) -------------------------
__device__ float g_xT  [(size_t)BB*NN*256];
__device__ float g_xx  [BB*NN];
__device__ float g_dist[(size_t)BB*NN*NN];
__device__ int   g_idx [(size_t)BB*NN*KNB];
__device__ float g_kmax[(size_t)BB*256*NN];
__device__ float g_kmin[(size_t)BB*256*NN];
__device__ float g_ksum[(size_t)BB*256*NN];
__device__ float g_ksq [(size_t)BB*256*NN];
__device__ float g_base[(size_t)BB*256*NN];   // (W_b - W_a) @ ctr
__device__ float g_Wd  [256*128];             // W[:,C:2C] - W[:,:C]
__device__ float g_xcat[(size_t)BB*512*NN];
__device__ float g_h5  [(size_t)BB*1024*NN];
__device__ float g_hb1 [(size_t)BB*256*NN];
__device__ float g_hb2 [(size_t)BB*256*NN];
__device__ float g_hb3 [(size_t)BB*128*NN];
__device__ float g_glob[BB*1088];
__device__ float g_b207[BB*256];
__device__ float g_prm [2048];

// ------------------------- generic fp32 GEMM (pipelined) ---------------------
// (used only for the small "base" GEMMs in the split edge path)
template<bool BT, int MODE>
__global__ void __launch_bounds__(256,2) k_gemm(
    int M, int Ncol, int Kd,
    const float* __restrict__ A, int lda, size_t asb,
    const float* __restrict__ Bp, int ldb, size_t bsb,
    float* __restrict__ Cp, size_t csb,
    const float* __restrict__ e0)
{
    const int BM=128, BN=128, BK=16;
    __shared__ float As[2][BK][BM+4];
    __shared__ float Bs[2][BK][BN+4];
    int b  = blockIdx.z;
    int m0 = blockIdx.y*BM, n0 = blockIdx.x*BN;
    A  += (size_t)b*asb;
    Bp += (size_t)b*bsb;
    Cp += (size_t)b*csb;
    int tid = threadIdx.x;
    int tx = tid%16, ty = tid/16;

    float acc[8][8];
    #pragma unroll
    for(int i=0;i<8;i++)
        #pragma unroll
        for(int j=0;j<8;j++) acc[i][j]=0.f;

    float ra[8], rb[8];

    auto fetchA = [&](int k0){
        #pragma unroll
        for(int i=0;i<8;i++){
            int e = tid + 256*i;
            int kk=e%BK, mm=e/BK;
            int gm=m0+mm, gk=k0+kk;
            ra[i] = (gm<M && gk<Kd) ? A[(size_t)gm*lda+gk] : 0.f;
        }
    };
    auto fetchB = [&](int k0){
        if(!BT){
            #pragma unroll
            for(int i=0;i<8;i++){
                int e = tid + 256*i;
                int kk=e%BK, nn=e/BK;
                int gn=n0+nn, gk=k0+kk;
                rb[i] = (gn<Ncol && gk<Kd) ? Bp[(size_t)gn*ldb+gk] : 0.f;
            }
        } else {
            #pragma unroll
            for(int i=0;i<8;i++){
                int e = tid + 256*i;
                int nn=e%BN, kk=e/BN;
                int gn=n0+nn, gk=k0+kk;
                rb[i] = (gn<Ncol && gk<Kd) ? Bp[(size_t)gk*ldb+gn] : 0.f;
            }
        }
    };
    auto store = [&](int buf){
        #pragma unroll
        for(int i=0;i<8;i++){
            int e = tid + 256*i;
            As[buf][e%BK][e/BK] = ra[i];
        }
        if(!BT){
            #pragma unroll
            for(int i=0;i<8;i++){
                int e = tid + 256*i;
                Bs[buf][e%BK][e/BK] = rb[i];
            }
        } else {
            #pragma unroll
            for(int i=0;i<8;i++){
                int e = tid + 256*i;
                Bs[buf][e/BN][e%BN] = rb[i];
            }
        }
    };

    int nk = (Kd + BK - 1)/BK;
    fetchA(0); fetchB(0);
    store(0);
    __syncthreads();

    for(int t=0;t<nk;t++){
        int cur = t&1;
        if(t+1<nk){ fetchA((t+1)*BK); fetchB((t+1)*BK); }
        #pragma unroll
        for(int kk=0;kk<BK;kk++){
            float a8[8], b8[8];
            #pragma unroll
            for(int i=0;i<8;i++) a8[i]=As[cur][kk][ty*8+i];
            #pragma unroll
            for(int j=0;j<8;j++) b8[j]=Bs[cur][kk][tx*8+j];
            #pragma unroll
            for(int i=0;i<8;i++)
                #pragma unroll
                for(int j=0;j<8;j++) acc[i][j] = __fmaf_rn(a8[i], b8[j], acc[i][j]);
        }
        if(t+1<nk){
            __syncthreads();
            store(1-cur);
            __syncthreads();
        }
    }

    #pragma unroll
    for(int i=0;i<8;i++){
        int gm = m0+ty*8+i;
        if(gm>=M) continue;
        #pragma unroll
        for(int j=0;j<8;j++){
            int gn = n0+tx*8+j;
            if(gn>=Ncol) continue;
            float v = acc[i][j];
            if(MODE==2) v = __fadd_rn(v, e0[(size_t)b*M+gm]);
            Cp[(size_t)gm*Ncol + gn] = v;
        }
    }
}

// ------------------- 3xTF32 tensor-core tail GEMM ---------------------------
// out[b][m][n] = sum_k A[m][k]*B[b][k][n]  (+ row bias for MODE 2)
// Operands split x = hi + lo (hi = tf32(x), lo = tf32(x-hi)); per fragment
// pair: hi*hi + hi*lo + lo*hi  -> ~fp32 accuracy at tensor-core speed.
// Tiles 128x64, BK=16, 8 warps (4m x 2n), warp tile 32x32.
__device__ __forceinline__ uint32_t f2tf32(float x){
    uint32_t u; asm("cvt.rna.tf32.f32 %0, %1;" : "=r"(u) : "f"(x)); return u;
}
__device__ __forceinline__ void mma_tf32(float* d, const uint32_t* a, const uint32_t* b){
    asm volatile("mma.sync.aligned.m16n8k8.row.col.f32.tf32.tf32.f32 "
        "{%0,%1,%2,%3}, {%4,%5,%6,%7}, {%8,%9}, {%0,%1,%2,%3};"
        : "+f"(d[0]),"+f"(d[1]),"+f"(d[2]),"+f"(d[3])
        : "r"(a[0]),"r"(a[1]),"r"(a[2]),"r"(a[3]), "r"(b[0]),"r"(b[1]));
}
template<int MODE>
__global__ void __launch_bounds__(256,3) k_tgemm(
    int M, int Kd,
    const float* __restrict__ A, int lda,
    const float* __restrict__ Bp, size_t bsb, int ldb,
    float* __restrict__ Cp, size_t csb,
    const float* __restrict__ e0)
{
    const int BM=128, BN=64, BK=16;
    __shared__ float Ah[BM][20], Al[BM][20];   // [m][k] stride 20
    __shared__ float Bh[BK][72], Bl[BK][72];   // [k][n] stride 72
    int b  = blockIdx.z;
    int m0 = blockIdx.y*BM, n0 = blockIdx.x*BN;
    Bp += (size_t)b*bsb;
    Cp += (size_t)b*csb;
    int tid = threadIdx.x;
    int lane = tid&31, warp = tid>>5;
    int wm = warp>>1, wn = warp&1;
    int gID = lane>>2, tig = lane&3;

    float acc[2][4][4];
    #pragma unroll
    for(int i=0;i<2;i++)
        #pragma unroll
        for(int j=0;j<4;j++)
            #pragma unroll
            for(int q=0;q<4;q++) acc[i][j][q]=0.f;

    int nk = Kd/BK;   // all tail K are multiples of 16
    for(int t=0;t<nk;t++){
        int k0 = t*BK;
        // fetch + split + store (single buffer)
        #pragma unroll
        for(int i=0;i<8;i++){
            int e = tid + 256*i;
            int k = e&15, m = e>>4;
            int gm = m0+m;
            float x = (gm<M) ? A[(size_t)gm*lda + k0+k] : 0.f;
            float hi = __uint_as_float(f2tf32(x));
            float lo = __uint_as_float(f2tf32(__fsub_rn(x, hi)));
            Ah[m][k] = hi; Al[m][k] = lo;
        }
        #pragma unroll
        for(int i=0;i<4;i++){
            int e = tid + 256*i;
            int n = e&63, k = e>>6;
            float x = Bp[(size_t)(k0+k)*ldb + n0+n];
            float hi = __uint_as_float(f2tf32(x));
            float lo = __uint_as_float(f2tf32(__fsub_rn(x, hi)));
            Bh[k][n] = hi; Bl[k][n] = lo;
        }
        __syncthreads();
        #pragma unroll
        for(int kk=0;kk<BK;kk+=8){
            uint32_t afh[2][4], afl[2][4], bfh[4][2], bfl[4][2];
            #pragma unroll
            for(int mt=0;mt<2;mt++){
                int row = wm*32 + mt*16;
                afh[mt][0] = __float_as_uint(Ah[row+gID  ][kk+tig  ]);
                afh[mt][1] = __float_as_uint(Ah[row+gID+8][kk+tig  ]);
                afh[mt][2] = __float_as_uint(Ah[row+gID  ][kk+tig+4]);
                afh[mt][3] = __float_as_uint(Ah[row+gID+8][kk+tig+4]);
                afl[mt][0] = __float_as_uint(Al[row+gID  ][kk+tig  ]);
                afl[mt][1] = __float_as_uint(Al[row+gID+8][kk+tig  ]);
                afl[mt][2] = __float_as_uint(Al[row+gID  ][kk+tig+4]);
                afl[mt][3] = __float_as_uint(Al[row+gID+8][kk+tig+4]);
            }
            #pragma unroll
            for(int nt=0;nt<4;nt++){
                int col = wn*32 + nt*8 + gID;
                bfh[nt][0] = __float_as_uint(Bh[kk+tig  ][col]);
                bfh[nt][1] = __float_as_uint(Bh[kk+tig+4][col]);
                bfl[nt][0] = __float_as_uint(Bl[kk+tig  ][col]);
                bfl[nt][1] = __float_as_uint(Bl[kk+tig+4][col]);
            }
            #pragma unroll
            for(int mt=0;mt<2;mt++)
                #pragma unroll
                for(int nt=0;nt<4;nt++){
                    mma_tf32(acc[mt][nt], afl[mt], bfh[nt]);   // lo*hi
                    mma_tf32(acc[mt][nt], afh[mt], bfl[nt]);   // hi*lo
                    mma_tf32(acc[mt][nt], afh[mt], bfh[nt]);   // hi*hi
                }
        }
        __syncthreads();
    }

    #pragma unroll
    for(int mt=0;mt<2;mt++){
        int r0 = m0 + wm*32 + mt*16 + gID;
        int r1 = r0 + 8;
        #pragma unroll
        for(int nt=0;nt<4;nt++){
            int c0 = n0 + wn*32 + nt*8 + tig*2;
            float v0=acc[mt][nt][0], v1=acc[mt][nt][1], v2=acc[mt][nt][2], v3=acc[mt][nt][3];
            if(MODE==2){
                if(r0<M){ float e=e0[(size_t)b*M+r0]; v0=__fadd_rn(v0,e); v1=__fadd_rn(v1,e); }
                if(r1<M){ float e=e0[(size_t)b*M+r1]; v2=__fadd_rn(v2,e); v3=__fadd_rn(v3,e); }
            }
            if(r0<M){ Cp[(size_t)r0*NN + c0] = v0; Cp[(size_t)r0*NN + c0+1] = v1; }
            if(r1<M){ Cp[(size_t)r1*NN + c0] = v2; Cp[(size_t)r1*NN + c0+1] = v3; }
        }
    }
}

// -------- symmetric dist GEMM (layers 2-4) --------------------------------
__global__ void __launch_bounds__(256,2) k_dgemm(
    int Kd, const float* __restrict__ Xp, const float* __restrict__ e0)
{
    const int BK=16;
    if(blockIdx.x < blockIdx.y) return;
    __shared__ float pool[8448];
    #define ASM(buf,kk,mm) pool[(buf)*2112 + (kk)*132 + (mm)]
    #define BSM(buf,kk,nn) pool[4224 + (buf)*2112 + (kk)*132 + (nn)]
    int b  = blockIdx.z;
    int m0 = blockIdx.y*128, n0 = blockIdx.x*128;
    const float* A = Xp + (size_t)b*NN*Kd;
    float* Cp = g_dist + (size_t)b*NN*NN;
    const float* xxr = e0 + (size_t)b*NN;
    int tid = threadIdx.x;
    int tx = tid%16, ty = tid/16;

    float acc[8][8];
    #pragma unroll
    for(int i=0;i<8;i++)
        #pragma unroll
        for(int j=0;j<8;j++) acc[i][j]=0.f;

    float ra[8], rb[8];
    auto fetchA = [&](int k0){
        #pragma unroll
        for(int i=0;i<8;i++){
            int e = tid + 256*i;
            int kk=e&15, mm=e>>4;
            int gk=k0+kk;
            ra[i] = (gk<Kd) ? A[(size_t)(m0+mm)*Kd+gk] : 0.f;
        }
    };
    auto fetchB = [&](int k0){
        #pragma unroll
        for(int i=0;i<8;i++){
            int e = tid + 256*i;
            int kk=e&15, nn=e>>4;
            int gk=k0+kk;
            rb[i] = (gk<Kd) ? A[(size_t)(n0+nn)*Kd+gk] : 0.f;
        }
    };
    auto store = [&](int buf){
        #pragma unroll
        for(int i=0;i<8;i++){
            int e = tid + 256*i;
            ASM(buf, e&15, e>>4) = ra[i];
        }
        #pragma unroll
        for(int i=0;i<8;i++){
            int e = tid + 256*i;
            BSM(buf, e&15, e>>4) = rb[i];
        }
    };

    int nk = (Kd + BK - 1)/BK;
    fetchA(0); fetchB(0);
    store(0);
    __syncthreads();
    for(int t=0;t<nk;t++){
        int cur = t&1;
        if(t+1<nk){ fetchA((t+1)*BK); fetchB((t+1)*BK); }
        #pragma unroll
        for(int kk=0;kk<BK;kk++){
            float a8[8], b8[8];
            #pragma unroll
            for(int i=0;i<8;i++) a8[i]=ASM(cur,kk,ty*8+i);
            #pragma unroll
            for(int j=0;j<8;j++) b8[j]=BSM(cur,kk,tx*8+j);
            #pragma unroll
            for(int i=0;i<8;i++)
                #pragma unroll
                for(int j=0;j<8;j++) acc[i][j] = __fmaf_rn(a8[i], b8[j], acc[i][j]);
        }
        if(t+1<nk){
            __syncthreads();
            store(1-cur);
            __syncthreads();
        }
    }

    #pragma unroll
    for(int i=0;i<8;i++){
        int gm = m0+ty*8+i;
        float xm = xxr[gm];
        #pragma unroll
        for(int j=0;j<8;j++){
            int gn = n0+tx*8+j;
            float v = __fsub_rn(__fsub_rn(__fmul_rn(2.0f, acc[i][j]), xm), xxr[gn]);
            acc[i][j] = v;
            Cp[(size_t)gm*NN + gn] = v;
        }
    }
    if(blockIdx.x > blockIdx.y){
        for(int c=0;c<4;c++){
            __syncthreads();
            if((tx>>2)==c){
                int tl = tx&3;
                #pragma unroll
                for(int i=0;i<8;i++)
                    #pragma unroll
                    for(int j=0;j<8;j++)
                        pool[(tl*8+j)*132 + ty*8+i] = acc[i][j];
            }
            __syncthreads();
            #pragma unroll
            for(int q=0;q<16;q++){
                int e = tid + 256*q;
                int rr=e>>7, cc=e&127;
                Cp[(size_t)(n0+c*32+rr)*NN + m0+cc] = pool[rr*132+cc];
            }
        }
    }
    #undef ASM
    #undef BSM
}

// ------- L1 exact fused edge-conv GEMM + k-reduce (full 2C path) -----------
template<int C, int BM, int MAXB>
__global__ void __launch_bounds__(256,MAXB) k_egemm_t(
    int M,
    const float* __restrict__ A,
    const float* __restrict__ xTp,
    const int*   __restrict__ idxp)
{
    const int BN=160, BK=16;
    const int Kd = 2*C;
    const int NK = (Kd + BK - 1)/BK;
    const int TM = BM/16;
    const int NA = BM*BK/256;
    __shared__ float As[2][BK][BM+4];
    __shared__ float Bs[2][BK][BN+4];
    __shared__ int   s_moff[BN];
    __shared__ int   s_poff[BN];
    int b  = blockIdx.z;
    int m0 = blockIdx.y*BM;
    int p0 = blockIdx.x*8;
    xTp  += (size_t)b*NN*C;
    idxp += (size_t)b*NN*KNB;
    int tid = threadIdx.x;
    int tx = tid%16, ty = tid/16;

    if(tid < BN){
        int pt = tid/KNB;
        int kq = tid - pt*KNB;
        s_poff[tid] = (p0+pt)*C;
        s_moff[tid] = idxp[(size_t)(p0+pt)*KNB + kq]*C;
    }
    __syncthreads();

    float acc[TM][10];
    #pragma unroll
    for(int i=0;i<TM;i++)
        #pragma unroll
        for(int j=0;j<10;j++) acc[i][j]=0.f;

    float ra[NA], rb[10];
    int kkme = tid & 15;

    auto fetchA = [&](int k0){
        #pragma unroll
        for(int i=0;i<NA;i++){
            int e = tid + 256*i;
            int kk=e&15, mm=e>>4;
            int gk=k0+kk;
            ra[i] = (gk<Kd) ? A[(size_t)(m0+mm)*Kd+gk] : 0.f;
        }
    };
    auto fetchB = [&](int k0){
        int gk = k0 + kkme;
        #pragma unroll
        for(int i=0;i<10;i++){
            int nn = (tid>>4) + 16*i;
            float val = 0.f;
            if(gk < Kd){
                int cc = (gk<C) ? gk : gk-C;
                float ctr = xTp[s_poff[nn] + cc];
                if(gk<C) val = __fsub_rn(xTp[s_moff[nn] + cc], ctr);
                else     val = ctr;
            }
            rb[i] = val;
        }
    };
    auto store = [&](int buf){
        #pragma unroll
        for(int i=0;i<NA;i++){
            int e = tid + 256*i;
            As[buf][e&15][e>>4] = ra[i];
        }
        #pragma unroll
        for(int i=0;i<10;i++){
            int nn = (tid>>4) + 16*i;
            Bs[buf][kkme][nn] = rb[i];
        }
    };

    fetchA(0); fetchB(0);
    store(0);
    __syncthreads();

    #pragma unroll 1
    for(int t=0;t<NK;t++){
        int cur = t&1;
        if(t+1<NK){ fetchA((t+1)*BK); fetchB((t+1)*BK); }
        #pragma unroll
        for(int kk=0;kk<BK;kk++){
            float am[TM], b10[10];
            #pragma unroll
            for(int i=0;i<TM;i++) am[i]=As[cur][kk][ty*TM+i];
            #pragma unroll
            for(int j=0;j<10;j++) b10[j]=Bs[cur][kk][tx*10+j];
            #pragma unroll
            for(int i=0;i<TM;i++)
                #pragma unroll
                for(int j=0;j<10;j++) acc[i][j] = __fmaf_rn(am[i], b10[j], acc[i][j]);
        }
        if(t+1<NK){
            __syncthreads();
            store(1-cur);
            __syncthreads();
        }
    }

    int O = M;
    #pragma unroll
    for(int i=0;i<TM;i++){
        float mx=-FLT_MAX, mn=FLT_MAX, sm=0.f, sq=0.f;
        #pragma unroll
        for(int j=0;j<10;j++){
            float h = acc[i][j];
            mx = fmaxf(mx,h); mn = fminf(mn,h);
            sm = __fadd_rn(sm,h); sq = __fmaf_rn(h,h,sq);
        }
        #pragma unroll
        for(int j=0;j<10;j++){
            float h = __shfl_xor_sync(0xffffffffu, acc[i][j], 1);
            mx = fmaxf(mx,h); mn = fminf(mn,h);
            sm = __fadd_rn(sm,h); sq = __fmaf_rn(h,h,sq);
        }
        int gm = m0 + ty*TM + i;
        if((tx&1)==0){
            int point = p0 + (tx>>1);
            size_t base = ((size_t)b*O + gm)*NN + point;
            g_kmax[base]=mx; g_kmin[base]=mn; g_ksum[base]=sm; g_ksq[base]=sq;
        }
    }
}

// ------- SPLIT edge-conv GEMM (layers 2-4): h = W_a @ nbr + base -----------
template<int C, int BM, int MAXB>
__global__ void __launch_bounds__(256,MAXB) k_egemm_s(
    int M,
    const float* __restrict__ A,
    const float* __restrict__ xTp,
    const int*   __restrict__ idxp)
{
    const int BN=160, BK=16;
    const int NK = C/BK;
    const int TM = BM/16;
    const int NA = BM*BK/256;
    __shared__ float As[2][BK][BM+4];
    __shared__ float Bs[2][BK][BN+4];
    __shared__ int   s_moff[BN];
    int b  = blockIdx.z;
    int m0 = blockIdx.y*BM;
    int p0 = blockIdx.x*8;
    xTp  += (size_t)b*NN*C;
    idxp += (size_t)b*NN*KNB;
    int tid = threadIdx.x;
    int tx = tid%16, ty = tid/16;

    if(tid < BN){
        int pt = tid/KNB;
        int kq = tid - pt*KNB;
        s_moff[tid] = idxp[(size_t)(p0+pt)*KNB + kq]*C;
    }
    __syncthreads();

    float acc[TM][10];
    #pragma unroll
    for(int i=0;i<TM;i++)
        #pragma unroll
        for(int j=0;j<10;j++) acc[i][j]=0.f;

    float ra[NA], rb[10];
    int kkme = tid & 15;

    auto fetchA = [&](int k0){
        #pragma unroll
        for(int i=0;i<NA;i++){
            int e = tid + 256*i;
            int kk=e&15;
            ra[i] = A[(size_t)(m0+(e>>4))*(2*C) + k0+kk];
        }
    };
    auto fetchB = [&](int k0){
        int cc = k0 + kkme;
        #pragma unroll
        for(int i=0;i<10;i++){
            int nn = (tid>>4) + 16*i;
            rb[i] = xTp[s_moff[nn] + cc];
        }
    };
    auto store = [&](int buf){
        #pragma unroll
        for(int i=0;i<NA;i++){
            int e = tid + 256*i;
            As[buf][e&15][e>>4] = ra[i];
        }
        #pragma unroll
        for(int i=0;i<10;i++){
            int nn = (tid>>4) + 16*i;
            Bs[buf][kkme][nn] = rb[i];
        }
    };

    fetchA(0); fetchB(0);
    store(0);
    __syncthreads();

    #pragma unroll 1
    for(int t=0;t<NK;t++){
        int cur = t&1;
        if(t+1<NK){ fetchA((t+1)*BK); fetchB((t+1)*BK); }
        #pragma unroll
        for(int kk=0;kk<BK;kk++){
            float am[TM], b10[10];
            #pragma unroll
            for(int i=0;i<TM;i++) am[i]=As[cur][kk][ty*TM+i];
            #pragma unroll
            for(int j=0;j<10;j++) b10[j]=Bs[cur][kk][tx*10+j];
            #pragma unroll
            for(int i=0;i<TM;i++)
                #pragma unroll
                for(int j=0;j<10;j++) acc[i][j] = __fmaf_rn(am[i], b10[j], acc[i][j]);
        }
        if(t+1<NK){
            __syncthreads();
            store(1-cur);
            __syncthreads();
        }
    }

    int O = M;
    int point = p0 + (tx>>1);
    #pragma unroll
    for(int i=0;i<TM;i++){
        int gm = m0 + ty*TM + i;
        float bsv = g_base[((size_t)b*O + gm)*NN + point];
        float mx=-FLT_MAX, mn=FLT_MAX, sm=0.f, sq=0.f;
        #pragma unroll
        for(int j=0;j<10;j++){
            float h = __fadd_rn(acc[i][j], bsv);
            mx = fmaxf(mx,h); mn = fminf(mn,h);
            sm = __fadd_rn(sm,h); sq = __fmaf_rn(h,h,sq);
        }
        #pragma unroll
        for(int j=0;j<10;j++){
            float h = __fadd_rn(__shfl_xor_sync(0xffffffffu, acc[i][j], 1), bsv);
            mx = fmaxf(mx,h); mn = fminf(mn,h);
            sm = __fadd_rn(sm,h); sq = __fmaf_rn(h,h,sq);
        }
        if((tx&1)==0){
            size_t base = ((size_t)b*O + gm)*NN + point;
            g_kmax[base]=mx; g_kmin[base]=mn; g_ksum[base]=sm; g_ksq[base]=sq;
        }
    }
}

// ------------------------- small kernels -------------------------

__global__ void k_tin(const float* __restrict__ x){
    int i = blockIdx.x*blockDim.x + threadIdx.x;
    if(i >= BB*NN*3) return;
    int c = i%3; int n = (i/3)%NN; int b = i/(3*NN);
    g_xT[i] = x[((size_t)b*3 + c)*NN + n];
}

__global__ void k_xx(int C){
    int p = blockIdx.x*blockDim.x + threadIdx.x;
    if(p >= BB*NN) return;
    const float* v = g_xT + (size_t)p*C;
    float s = 0.f;
    for(int c=0;c<C;c++) s = __fadd_rn(s, __fmul_rn(v[c], v[c]));
    g_xx[p] = s;
}

__global__ void k_wdiff(const float* __restrict__ W, int O, int C){
    int i = blockIdx.x*blockDim.x + threadIdx.x;
    if(i >= O*C) return;
    int o = i/C, c = i%C;
    g_Wd[i] = __fsub_rn(W[(size_t)o*2*C + C + c], W[(size_t)o*2*C + c]);
}

// shared top-k selection body (given v[8] per thread).
template<int FUSED3>
__device__ __forceinline__ void topk_select(
    float* v, int tid, int lane, int w, int n, int bq,
    const float* __restrict__ X3, float xxn, const float* __restrict__ xxr)
{
    __shared__ float swmx[8], swmn[8];
    __shared__ int hist8[8][256];
    __shared__ int hist[256];
    __shared__ unsigned long long cand[256];
    __shared__ int s_cnt, s_B, s_size;
    __shared__ float s_lo, s_hi;
    int base = tid*8;

    float mx=v[0], mn=v[0];
    #pragma unroll
    for(int t=1;t<8;t++){ mx=fmaxf(mx,v[t]); mn=fminf(mn,v[t]); }
    #pragma unroll
    for(int o=16;o;o>>=1){
        mx=fmaxf(mx,__shfl_xor_sync(0xffffffffu,mx,o));
        mn=fminf(mn,__shfl_xor_sync(0xffffffffu,mn,o));
    }
    if(lane==0){ swmx[w]=mx; swmn[w]=mn; }
    #pragma unroll
    for(int q=0;q<8;q++) hist8[q][tid]=0;
    __syncthreads();
    if(tid==0){
        float hx=swmx[0], hn=swmn[0];
        #pragma unroll
        for(int q=1;q<8;q++){ hx=fmaxf(hx,swmx[q]); hn=fminf(hn,swmn[q]); }
        s_lo=hn; s_hi=hx; s_cnt=0;
    }
    __syncthreads();
    float lo=s_lo, hi=s_hi;
    float scale = (hi>lo) ? 255.0f/(hi-lo) : 0.0f;
    int bk[8];
    #pragma unroll
    for(int t=0;t<8;t++){
        int bb = (int)((v[t]-lo)*scale);
        bb = max(0, min(255, bb));
        bk[t]=bb;
        atomicAdd(&hist8[w][bb],1);
    }
    __syncthreads();
    {
        int hsum = 0;
        #pragma unroll
        for(int q=0;q<8;q++) hsum += hist8[q][tid];
        hist[tid] = hsum;
    }
    __syncthreads();
    if(w==0){
        int cs = 0;
        #pragma unroll
        for(int t=0;t<8;t++) cs += hist[lane*8+t];
        int rs = cs;
        #pragma unroll
        for(int o=1;o<32;o<<=1){
            int t2 = __shfl_down_sync(0xffffffffu, rs, o);
            if(lane+o<32) rs += t2;
        }
        int sufx = rs - cs;
        if(rs >= KNB && sufx < KNB){
            int run = sufx, Bv = lane*8;
            for(int j=7;j>=0;j--){
                run += hist[lane*8+j];
                if(run >= KNB){ Bv = lane*8+j; break; }
            }
            s_B = Bv;
        }
    }
    __syncthreads();
    int B = s_B;
    #pragma unroll
    for(int t=0;t<8;t++){
        if(bk[t] >= B){
            int pos = atomicAdd(&s_cnt,1);
            if(pos<256){
                unsigned int u = __float_as_uint(v[t]);
                u = (u & 0x80000000u) ? ~u : (u | 0x80000000u);
                cand[pos] = ((unsigned long long)u<<32) | (unsigned int)(~(base+t));
            }
        }
    }
    __syncthreads();
    int cnt = s_cnt;
    if(cnt<=256){
        if(tid==0){
            int sz = 32;
            while(sz < cnt) sz <<= 1;
            s_size = sz;
        }
        __syncthreads();
        int sz = s_size;
        if(tid<sz && tid>=cnt) cand[tid]=0ull;
        __syncthreads();
        for(int k=2;k<=sz;k<<=1){
            for(int j=k>>1;j>0;j>>=1){
                int ixj = tid ^ j;
                if(ixj > tid && ixj < sz && tid < sz){
                    bool up = ((tid & k) == 0);
                    unsigned long long a=cand[tid], c=cand[ixj];
                    if( (a > c) == up ){ cand[tid]=c; cand[ixj]=a; }
                }
                __syncthreads();
            }
        }
        if(tid<KNB)
            g_idx[((size_t)bq*NN+n)*KNB + tid] = (int)(~(unsigned int)cand[sz-1-tid]);
    } else {
        if(tid==0){
            if(FUSED3){
                int chosen[KNB];
                for(int j=0;j<KNB;j++){
                    float bvv=-FLT_MAX; int bii=0;
                    for(int i=0;i<NN;i++){
                        bool skip=false;
                        for(int q=0;q<j;q++) if(chosen[q]==i){ skip=true; break; }
                        if(skip) continue;
                        float a0=X3[i*3],a1=X3[i*3+1],a2=X3[i*3+2];
                        float ac=__fmaf_rn(X3[n*3],a0,0.f);
                        ac=__fmaf_rn(X3[n*3+1],a1,ac);
                        ac=__fmaf_rn(X3[n*3+2],a2,ac);
                        float vv=__fsub_rn(__fsub_rn(__fmul_rn(2.0f,ac),xxn),xxr[i]);
                        if(vv>bvv){ bvv=vv; bii=i; }
                    }
                    chosen[j]=bii;
                    g_idx[((size_t)bq*NN+n)*KNB + j]=bii;
                }
            } else {
                float* rw = g_dist + ((size_t)bq*NN + n)*NN;
                for(int j=0;j<KNB;j++){
                    float bvv=-FLT_MAX; int bii=0;
                    for(int i=0;i<NN;i++){ float vv=rw[i]; if(vv>bvv){bvv=vv;bii=i;} }
                    g_idx[((size_t)bq*NN+n)*KNB + j]=bii;
                    rw[bii]=-FLT_MAX;
                }
            }
        }
    }
}

__global__ void __launch_bounds__(256) k_topk(){
    int n = blockIdx.x, bq = blockIdx.y;
    const float* row = g_dist + ((size_t)bq*NN + n)*NN;
    int tid = threadIdx.x, lane = tid&31, w = tid>>5;
    float v[8];
    {
        const float4* r4 = (const float4*)(row + tid*8);
        float4 q0 = r4[0], q1 = r4[1];
        v[0]=q0.x; v[1]=q0.y; v[2]=q0.z; v[3]=q0.w;
        v[4]=q1.x; v[5]=q1.y; v[6]=q1.z; v[7]=q1.w;
    }
    topk_select<0>(v, tid, lane, w, n, bq, nullptr, 0.f, nullptr);
}

__global__ void __launch_bounds__(256) k_topk3(){
    int n = blockIdx.x, bq = blockIdx.y;
    const float* X3 = g_xT + (size_t)bq*NN*3;
    const float* xxr = g_xx + (size_t)bq*NN;
    int tid = threadIdx.x, lane = tid&31, w = tid>>5;
    float c0 = X3[n*3], c1 = X3[n*3+1], c2 = X3[n*3+2];
    float xxn = xxr[n];
    float f[24];
    {
        const float4* p4 = (const float4*)(X3 + tid*24);
        #pragma unroll
        for(int q=0;q<6;q++){
            float4 t = p4[q];
            f[q*4+0]=t.x; f[q*4+1]=t.y; f[q*4+2]=t.z; f[q*4+3]=t.w;
        }
    }
    float v[8];
    #pragma unroll
    for(int q=0;q<8;q++){
        float ac = __fmaf_rn(c0, f[q*3+0], 0.f);
        ac = __fmaf_rn(c1, f[q*3+1], ac);
        ac = __fmaf_rn(c2, f[q*3+2], ac);
        v[q] = __fsub_rn(__fsub_rn(__fmul_rn(2.0f, ac), xxn), xxr[tid*8+q]);
    }
    topk_select<1>(v, tid, lane, w, n, bq, X3, xxn, xxr);
}

__global__ void k_ec_stats(int O){
    int o = blockIdx.x, tid = threadIdx.x;
    double s=0.0, ss=0.0;
    for(int b=0;b<BB;b++){
        size_t base = ((size_t)b*O + o)*NN;
        for(int n=tid;n<NN;n+=256){ s += g_ksum[base+n]; ss += g_ksq[base+n]; }
    }
    __shared__ double rs[256], rq[256];
    rs[tid]=s; rq[tid]=ss; __syncthreads();
    for(int st=128;st;st>>=1){ if(tid<st){ rs[tid]+=rs[tid+st]; rq[tid]+=rq[tid+st]; } __syncthreads(); }
    if(tid==0){
        double cnt = (double)BB*NN*KNB;
        double mean = rs[0]/cnt;
        double var  = rq[0]/cnt - mean*mean;
        g_prm[2*o]   = (float)mean;
        g_prm[2*o+1] = (float)var;
    }
}

__global__ void __launch_bounds__(256) k_ec_apply2(int O, int c0, float* __restrict__ xTout,
                            const float* __restrict__ gw, const float* __restrict__ bw){
    int o0 = blockIdx.x*32;
    int n0base = blockIdx.y*256;
    int b = blockIdx.z;
    __shared__ float pmm[32], psd[32], pg[32], pb[32];
    __shared__ int   puse[32];
    __shared__ float tile[64][33];
    int tid = threadIdx.x;
    if(tid<32){
        int o = o0+tid;
        float m = g_prm[2*o], vv = g_prm[2*o+1];
        pmm[tid]=m; psd[tid]=__fsqrt_rn(__fadd_rn(vv, EPSB));
        pg[tid]=gw[o]; pb[tid]=bw[o];
        puse[tid] = (gw[o]>=0.f) ? 1 : 0;
    }
    __syncthreads();
    for(int s=0;s<4;s++){
        int n0 = n0base + s*64;
        #pragma unroll
        for(int e=tid; e<2048; e+=256){
            int ol=e>>6, nl=e&63;
            const float* src = puse[ol] ? g_kmax : g_kmin;
            float vsrc = src[((size_t)b*O + o0+ol)*NN + n0+nl];
            float y = __fadd_rn(__fmul_rn(__fdiv_rn(__fsub_rn(vsrc, pmm[ol]), psd[ol]), pg[ol]), pb[ol]);
            y = (y>=0.f) ? y : __fmul_rn(NEGS, y);
            g_xcat[((size_t)b*512 + c0 + o0+ol)*NN + n0+nl] = y;
            tile[nl][ol] = y;
        }
        __syncthreads();
        #pragma unroll
        for(int e=tid; e<2048; e+=256){
            int nl=e>>5, ol=e&31;
            xTout[((size_t)b*NN + n0+nl)*O + o0+ol] = tile[nl][ol];
        }
        __syncthreads();
    }
}

__global__ void k_conv_stats(const float* __restrict__ h, int O){
    int o = blockIdx.x, tid = threadIdx.x;
    double s=0.0, ss=0.0;
    for(int b=0;b<BB;b++){
        size_t base = ((size_t)b*O + o)*NN;
        for(int n=tid;n<NN;n+=256){ float v=h[base+n]; s += v; ss += (double)v*v; }
    }
    __shared__ double rs[256], rq[256];
    rs[tid]=s; rq[tid]=ss; __syncthreads();
    for(int st=128;st;st>>=1){ if(tid<st){ rs[tid]+=rs[tid+st]; rq[tid]+=rq[tid+st]; } __syncthreads(); }
    if(tid==0){
        double cnt = (double)BB*NN;
        double mean = rs[0]/cnt;
        double var  = rq[0]/cnt - mean*mean;
        g_prm[2*o]   = (float)mean;
        g_prm[2*o+1] = (float)var;
    }
}

__global__ void k_conv_apply(float* __restrict__ h, int O,
                             const float* __restrict__ gw, const float* __restrict__ bw){
    int o = blockIdx.x, b = blockIdx.y;
    float m = g_prm[2*o], vv = g_prm[2*o+1];
    float gg = gw[o], bb = bw[o];
    float sd = __fsqrt_rn(__fadd_rn(vv, EPSB));
    float* p = h + ((size_t)b*O + o)*NN;
    for(int n=threadIdx.x;n<NN;n+=blockDim.x){
        float y = __fadd_rn(__fmul_rn(__fdiv_rn(__fsub_rn(p[n], m), sd), gg), bb);
        p[n] = (y>=0.f) ? y : __fmul_rn(NEGS, y);
    }
}

__global__ void __launch_bounds__(256) k_h5stats(const float* __restrict__ gw,
                                                 const float* __restrict__ bw){
    int o = blockIdx.x, tid = threadIdx.x, lane = tid&31, w = tid>>5;
    double s=0.0, ss=0.0;
    float bmx[BB], bmn[BB];
    #pragma unroll
    for(int b=0;b<BB;b++){ bmx[b]=-FLT_MAX; bmn[b]=FLT_MAX; }
    for(int b=0;b<BB;b++){
        size_t base = ((size_t)b*1024 + o)*NN;
        for(int n=tid;n<NN;n+=256){
            float v = g_h5[base+n];
            s += v; ss += (double)v*v;
            bmx[b]=fmaxf(bmx[b],v); bmn[b]=fminf(bmn[b],v);
        }
    }
    __shared__ double rs[256], rq[256];
    rs[tid]=s; rq[tid]=ss; __syncthreads();
    for(int st=128;st;st>>=1){ if(tid<st){ rs[tid]+=rs[tid+st]; rq[tid]+=rq[tid+st]; } __syncthreads(); }
    __shared__ float sx[8][BB], sn[8][BB];
    #pragma unroll
    for(int b=0;b<BB;b++){
        float mx=bmx[b], mn=bmn[b];
        #pragma unroll
        for(int off=16;off;off>>=1){
            mx=fmaxf(mx,__shfl_xor_sync(0xffffffffu,mx,off));
            mn=fminf(mn,__shfl_xor_sync(0xffffffffu,mn,off));
        }
        if(lane==0){ sx[w][b]=mx; sn[w][b]=mn; }
    }
    __shared__ float smean, svar;
    __syncthreads();
    if(tid==0){
        double cnt = (double)BB*NN;
        double mean = rs[0]/cnt;
        double var  = rq[0]/cnt - mean*mean;
        smean = (float)mean; svar = (float)var;
    }
    __syncthreads();
    if(tid<BB){
        int b = tid;
        float mx=sx[0][b], mn=sn[0][b];
        #pragma unroll
        for(int q=1;q<8;q++){ mx=fmaxf(mx,sx[q][b]); mn=fminf(mn,sn[q][b]); }
        float gg = gw[o];
        float src = (gg>=0.f) ? mx : mn;
        float sd = __fsqrt_rn(__fadd_rn(svar, EPSB));
        float y = __fadd_rn(__fmul_rn(__fdiv_rn(__fsub_rn(src, smean), sd), gg), bw[o]);
        y = (y>=0.f) ? y : __fmul_rn(NEGS, y);
        g_glob[b*1088 + o] = y;
    }
}

__global__ void k_lf(const float* __restrict__ l, const float* __restrict__ W,
                     const float* __restrict__ gw, const float* __restrict__ bw){
    int tid = threadIdx.x;
    int o = tid & 63, b = tid >> 6;
    __shared__ float hs[8][64];
    __shared__ float pm[64], pv[64];
    float s = 0.f;
    #pragma unroll
    for(int c=0;c<16;c++) s = __fmaf_rn(W[o*16 + c], l[b*16 + c], s);
    hs[b][o] = s;
    __syncthreads();
    if(tid < 64){
        float m = 0.f;
        #pragma unroll
        for(int q=0;q<8;q++) m = __fadd_rn(m, hs[q][tid]);
        m = __fdiv_rn(m, 8.f);
        float v = 0.f;
        #pragma unroll
        for(int q=0;q<8;q++){ float d = __fsub_rn(hs[q][tid], m); v = __fmaf_rn(d, d, v); }
        v = __fdiv_rn(v, 8.f);
        pm[tid] = m; pv[tid] = v;
    }
    __syncthreads();
    float sd = __fsqrt_rn(__fadd_rn(pv[o], EPSB));
    float y = __fadd_rn(__fmul_rn(__fdiv_rn(__fsub_rn(hs[b][o], pm[o]), sd), gw[o]), bw[o]);
    y = (y>=0.f) ? y : __fmul_rn(NEGS, y);
    g_glob[b*1088 + 1024 + o] = y;
}

__global__ void k_bias207(const float* __restrict__ W207){
    int b = blockIdx.x;
    __shared__ float gl[1088];
    for(int i=threadIdx.x;i<1088;i+=256) gl[i] = g_glob[b*1088 + i];
    __syncthreads();
    int o = threadIdx.x;
    float s = 0.f;
    for(int c=0;c<1088;c++) s = __fmaf_rn(W207[(size_t)o*1600 + c], gl[c], s);
    g_b207[b*256 + o] = s;
}

// ------------------------- launcher -------------------------
extern "C" void kernel_launch(void* const* d_in, const int* in_sizes, int n_in,
                              void* d_out, int out_size){
    (void)in_sizes; (void)n_in; (void)out_size;
    const float* x    = (const float*)d_in[0];
    const float* l    = (const float*)d_in[1];
    const float* Wec[4] = {(const float*)d_in[2],(const float*)d_in[5],(const float*)d_in[8],(const float*)d_in[11]};
    const float* gec[4] = {(const float*)d_in[3],(const float*)d_in[6],(const float*)d_in[9],(const float*)d_in[12]};
    const float* bec[4] = {(const float*)d_in[4],(const float*)d_in[7],(const float*)d_in[10],(const float*)d_in[13]};
    const float* W5   = (const float*)d_in[14]; const float* g5v  = (const float*)d_in[15]; const float* b5v  = (const float*)d_in[16];
    const float* W206 = (const float*)d_in[17]; const float* g206 = (const float*)d_in[18]; const float* b206 = (const float*)d_in[19];
    const float* W207 = (const float*)d_in[20]; const float* g207 = (const float*)d_in[21]; const float* b207 = (const float*)d_in[22];
    const float* W208 = (const float*)d_in[23]; const float* g208 = (const float*)d_in[24]; const float* b208 = (const float*)d_in[25];
    const float* W209 = (const float*)d_in[26]; const float* g209 = (const float*)d_in[27]; const float* b209 = (const float*)d_in[28];
    const float* W2010= (const float*)d_in[29];

    float *xT,*xxp,*xcat,*h5,*hb1,*hb2,*hb3,*b207p,*basep,*Wdp;
    int *idxp;
    cudaGetSymbolAddress((void**)&xT,   g_xT);
    cudaGetSymbolAddress((void**)&xxp,  g_xx);
    cudaGetSymbolAddress((void**)&idxp, g_idx);
    cudaGetSymbolAddress((void**)&xcat, g_xcat);
    cudaGetSymbolAddress((void**)&h5,   g_h5);
    cudaGetSymbolAddress((void**)&hb1,  g_hb1);
    cudaGetSymbolAddress((void**)&hb2,  g_hb2);
    cudaGetSymbolAddress((void**)&hb3,  g_hb3);
    cudaGetSymbolAddress((void**)&b207p,g_b207);
    cudaGetSymbolAddress((void**)&basep,g_base);
    cudaGetSymbolAddress((void**)&Wdp,  g_Wd);

    const int Cin[4] = {3,64,64,128};
    const int Oo [4] = {64,64,128,256};
    const int c0 [4] = {0,64,128,256};

    k_tin<<<(BB*NN*3 + 255)/256, 256>>>(x);

    for(int li=0; li<4; li++){
        int C = Cin[li], O = Oo[li];
        k_xx<<<(BB*NN + 255)/256, 256>>>(C);
        if(li==0){
            k_topk3<<<dim3(NN, BB), 256>>>();
        } else {
            k_dgemm<<<dim3(NN/128, NN/128, BB), 256>>>(C, xT, xxp);
            k_topk<<<dim3(NN, BB), 256>>>();
        }
        if(li==0){
            k_egemm_t<3,64,3><<<dim3(NN/8, 1, BB), 256>>>(64, Wec[0], xT, idxp);
        } else {
            k_wdiff<<<(O*C + 255)/256, 256>>>(Wec[li], O, C);
            k_gemm<false,0><<<dim3(NN/128, (O+127)/128, BB), 256>>>(
                O, NN, C, Wdp, C, 0, xT, C, (size_t)NN*C, basep, (size_t)O*NN, nullptr);
            if(li==1)      k_egemm_s<64, 64,3><<<dim3(NN/8, 1, BB), 256>>>(64,  Wec[1], xT, idxp);
            else if(li==2) k_egemm_s<64,128,2><<<dim3(NN/8, 1, BB), 256>>>(128, Wec[2], xT, idxp);
            else           k_egemm_s<128,128,2><<<dim3(NN/8, 2, BB), 256>>>(256, Wec[3], xT, idxp);
        }
        k_ec_stats<<<O, 256>>>(O);
        k_ec_apply2<<<dim3(O/32, NN/256, BB), 256>>>(O, c0[li], xT, gec[li], bec[li]);
    }

    // ---- continuous tail: 3xTF32 tensor cores (fp32-accurate) ----
    k_tgemm<0><<<dim3(NN/64, 1024/128, BB), 256>>>(
        1024, 512, W5, 512, xcat, (size_t)512*NN, NN, h5, (size_t)1024*NN, nullptr);
    k_h5stats<<<1024, 256>>>(g5v, b5v);
    k_lf<<<1, 512>>>(l, W206, g206, b206);
    k_bias207<<<BB, 256>>>(W207);
    k_tgemm<2><<<dim3(NN/64, 2, BB), 256>>>(
        256, 512, W207 + 1088, 1600, xcat, (size_t)512*NN, NN, hb1, (size_t)256*NN, b207p);
    k_conv_stats<<<256, 256>>>(hb1, 256);
    k_conv_apply<<<dim3(256, BB), 256>>>(hb1, 256, g207, b207);
    k_tgemm<0><<<dim3(NN/64, 2, BB), 256>>>(
        256, 256, W208, 256, hb1, (size_t)256*NN, NN, hb2, (size_t)256*NN, nullptr);
    k_conv_stats<<<256, 256>>>(hb2, 256);
    k_conv_apply<<<dim3(256, BB), 256>>>(hb2, 256, g208, b208);
    k_tgemm<0><<<dim3(NN/64, 1, BB), 256>>>(
        128, 256, W209, 256, hb2, (size_t)256*NN, NN, hb3, (size_t)128*NN, nullptr);
    k_conv_stats<<<128, 256>>>(hb3, 128);
    k_conv_apply<<<dim3(128, BB), 256>>>(hb3, 128, g209, b209);
    k_tgemm<0><<<dim3(NN/64, 1, BB), 256>>>(
        50, 128, W2010, 128, hb3, (size_t)128*NN, NN, (float*)d_out, (size_t)50*NN, nullptr);
}